// round 5
// baseline (speedup 1.0000x reference)
#include <cuda_runtime.h>
#include <cuda_bf16.h>
#include <math.h>
#include <stdint.h>

// ---------------------------------------------------------------------------
// Problem constants
// ---------------------------------------------------------------------------
#define BQ    8
#define MTOT  32768
#define CDIM  512
#define TDIM  768
#define KTXT  128
#define HID   2048
#define TOPM  5
#define TEMP_INV (1.0f/0.07f)
#define LN_EPS 1e-5f

// ---------------------------------------------------------------------------
// Scratch (device globals; no cudaMalloc allowed)
// ---------------------------------------------------------------------------
static __device__ float g_visln[MTOT * CDIM];          //  64 MB
static __device__ float g_keyt [BQ * KTXT * TDIM];     //   3 MB (l2-normalized)
static __device__ float g_value[BQ * KTXT * CDIM];     //   2 MB
static __device__ float g_X    [MTOT * CDIM];          //  64 MB (LN2 output)
static __device__ float g_hid  [MTOT * HID];           // 256 MB (gelu hidden)
static __device__ float g_P    [BQ * CDIM * KTXT];     //   2 MB  P[c][k] per batch
static __device__ float g_G    [CDIM * CDIM];          //   1 MB  Wq @ Wq^T
static __device__ float g_pb   [BQ * KTXT];            //  bq . keyt
static __device__ float g_wb2  [CDIM];                 //  2 * Wq @ bq
static __device__ float g_nb2  [1];                    //  ||bq||^2
static __device__ float g_qn2  [MTOT];                 //  v^T(Gv + 2Wq bq)

// ---------------------------------------------------------------------------
// bf16 split helpers
// ---------------------------------------------------------------------------
__device__ __forceinline__ void split2(float x, float y,
                                       uint32_t& hi, uint32_t& lo) {
    __nv_bfloat16 hx = __float2bfloat16_rn(x);
    __nv_bfloat16 hy = __float2bfloat16_rn(y);
    float rx = x - __bfloat162float(hx);
    float ry = y - __bfloat162float(hy);
    __nv_bfloat162 h2 = __halves2bfloat162(hx, hy);   // low half = even-k elem
    __nv_bfloat162 l2 = __floats2bfloat162_rn(rx, ry);
    hi = *reinterpret_cast<uint32_t*>(&h2);
    lo = *reinterpret_cast<uint32_t*>(&l2);
}

__device__ __forceinline__ void mma_bf16(float* c, const uint32_t* a, const uint32_t* b) {
    asm volatile(
        "mma.sync.aligned.m16n8k16.row.col.f32.bf16.bf16.f32 "
        "{%0,%1,%2,%3}, {%4,%5,%6,%7}, {%8,%9}, {%0,%1,%2,%3};\n"
        : "+f"(c[0]), "+f"(c[1]), "+f"(c[2]), "+f"(c[3])
        : "r"(a[0]), "r"(a[1]), "r"(a[2]), "r"(a[3]), "r"(b[0]), "r"(b[1]));
}

// ---------------------------------------------------------------------------
// Kernel 1: text prep — keyt = l2norm(text), value = text @ Wv + bv
// ---------------------------------------------------------------------------
__global__ __launch_bounds__(256) void prep_text_kernel(
    const float* __restrict__ text, const float* __restrict__ Wv,
    const float* __restrict__ bv)
{
    __shared__ float ts[8][TDIM];   // 24 KB
    int tid = threadIdx.x, lane = tid & 31, warp = tid >> 5;
    int b  = blockIdx.x >> 4;
    int kb = (blockIdx.x & 15) * 8;
    const float* tb = text + ((size_t)b * KTXT + kb) * TDIM;

    #pragma unroll
    for (int i = 0; i < 24; i++) {
        int lin = tid + 256 * i;
        int r = lin / TDIM, c = lin % TDIM;
        ts[r][c] = tb[(size_t)r * TDIM + c];
    }
    __syncthreads();

    {
        int r = warp;
        float s = 0.f;
        for (int i = lane; i < TDIM; i += 32) { float v = ts[r][i]; s += v * v; }
        #pragma unroll
        for (int o = 16; o; o >>= 1) s += __shfl_xor_sync(0xffffffffu, s, o);
        float inv = 1.0f / fmaxf(sqrtf(s), 1e-12f);
        float* kr = g_keyt + ((size_t)b * KTXT + kb + r) * TDIM;
        for (int i = lane; i < TDIM; i += 32) kr[i] = ts[r][i] * inv;
    }

    float acc[8][2];
    #pragma unroll
    for (int r = 0; r < 8; r++) { acc[r][0] = 0.f; acc[r][1] = 0.f; }
    int c0 = tid, c1 = tid + 256;
    for (int t = 0; t < TDIM; t++) {
        float w0 = Wv[(size_t)t * CDIM + c0];
        float w1 = Wv[(size_t)t * CDIM + c1];
        #pragma unroll
        for (int r = 0; r < 8; r++) {
            float tv = ts[r][t];
            acc[r][0] += tv * w0;
            acc[r][1] += tv * w1;
        }
    }
    float bb0 = bv[c0], bb1 = bv[c1];
    #pragma unroll
    for (int r = 0; r < 8; r++) {
        float* vr = g_value + ((size_t)b * KTXT + kb + r) * CDIM;
        vr[c0] = acc[r][0] + bb0;
        vr[c1] = acc[r][1] + bb1;
    }
}

// ---------------------------------------------------------------------------
// Kernel: small fp32 SGEMM  C[M,N] = A[M,K] @ B2[N,K]^T  (both k-contiguous)
// 128x128 tile, BK=8, 256 threads, 8x8 micro. Used for P (per batch) and G.
// ---------------------------------------------------------------------------
__global__ __launch_bounds__(256) void sgemm_tn_kernel(
    const float* __restrict__ A, const float* __restrict__ B2,
    float* __restrict__ C, int Kd, int N,
    size_t aStride, size_t bStride, size_t cStride)
{
    __shared__ float As[8][128];
    __shared__ float Bs[8][128];
    int tid = threadIdx.x;
    int tx = tid & 15, ty = tid >> 4;
    int bn = blockIdx.x, bm = blockIdx.y, bz = blockIdx.z;
    const float* Ab = A  + (size_t)bz * aStride + (size_t)bm * 128 * Kd;
    const float* Bb = B2 + (size_t)bz * bStride + (size_t)bn * 128 * Kd;
    int l_r = tid >> 1, l_k = (tid & 1) * 4;

    float acc[8][8];
    #pragma unroll
    for (int i = 0; i < 8; i++)
        #pragma unroll
        for (int j = 0; j < 8; j++) acc[i][j] = 0.f;

    for (int k0 = 0; k0 < Kd; k0 += 8) {
        float4 av = *(const float4*)(Ab + (size_t)l_r * Kd + k0 + l_k);
        As[l_k + 0][l_r] = av.x;
        As[l_k + 1][l_r] = av.y;
        As[l_k + 2][l_r] = av.z;
        As[l_k + 3][l_r] = av.w;
        float4 bv = *(const float4*)(Bb + (size_t)l_r * Kd + k0 + l_k);
        Bs[l_k + 0][l_r] = bv.x;
        Bs[l_k + 1][l_r] = bv.y;
        Bs[l_k + 2][l_r] = bv.z;
        Bs[l_k + 3][l_r] = bv.w;
        __syncthreads();
        #pragma unroll
        for (int k = 0; k < 8; k++) {
            float ar[8], br[8];
            #pragma unroll
            for (int i = 0; i < 4; i++) {
                ar[i]     = As[k][ty * 4 + i];
                ar[4 + i] = As[k][64 + ty * 4 + i];
                br[i]     = Bs[k][tx * 4 + i];
                br[4 + i] = Bs[k][64 + tx * 4 + i];
            }
            #pragma unroll
            for (int i = 0; i < 8; i++)
                #pragma unroll
                for (int j = 0; j < 8; j++) acc[i][j] += ar[i] * br[j];
        }
        __syncthreads();
    }

    float* Cb = C + (size_t)bz * cStride;
    #pragma unroll
    for (int gi = 0; gi < 2; gi++)
        #pragma unroll
        for (int ii = 0; ii < 4; ii++) {
            int r = bm * 128 + gi * 64 + ty * 4 + ii;
            #pragma unroll
            for (int gj = 0; gj < 2; gj++) {
                int cb = bn * 128 + gj * 64 + tx * 4;
                float4 o;
                o.x = acc[gi * 4 + ii][gj * 4 + 0];
                o.y = acc[gi * 4 + ii][gj * 4 + 1];
                o.z = acc[gi * 4 + ii][gj * 4 + 2];
                o.w = acc[gi * 4 + ii][gj * 4 + 3];
                *(float4*)(Cb + (size_t)r * N + cb) = o;
            }
        }
}

// ---------------------------------------------------------------------------
// Kernel: tiny prep — pb[b][k] = bq.keyt, wb2 = 2*Wq@bq, nb2 = ||bq||^2
// grid 12 blocks x 128 threads (blocks 0..7: pb; 8..11: wb2)
// ---------------------------------------------------------------------------
__global__ __launch_bounds__(128) void prep_small_kernel(
    const float* __restrict__ Wq, const float* __restrict__ bq)
{
    int bx = blockIdx.x, tid = threadIdx.x;
    if (bx < BQ) {
        const float* kr = g_keyt + ((size_t)bx * KTXT + tid) * TDIM;
        float s = 0.f;
        for (int t = 0; t < TDIM; t++) s += bq[t] * kr[t];
        g_pb[bx * KTXT + tid] = s;
    } else {
        int c = (bx - BQ) * 128 + tid;
        const float* wr = Wq + (size_t)c * TDIM;
        float s = 0.f;
        for (int t = 0; t < TDIM; t++) s += wr[t] * bq[t];
        g_wb2[c] = 2.0f * s;
        if (bx == BQ && tid == 0) {
            float s2 = 0.f;
            for (int t = 0; t < TDIM; t++) s2 += bq[t] * bq[t];
            g_nb2[0] = s2;
        }
    }
}

// ---------------------------------------------------------------------------
// Kernel: LayerNorm (warp-per-row, float4 I/O)
// ---------------------------------------------------------------------------
__global__ __launch_bounds__(256) void ln_kernel(
    const float* __restrict__ in, const float* __restrict__ g,
    const float* __restrict__ be, float* __restrict__ out)
{
    int warp = threadIdx.x >> 5, lane = threadIdx.x & 31;
    size_t row = (size_t)blockIdx.x * 8 + warp;
    const float4* p = (const float4*)(in + row * CDIM);
    float4 x[4];
    float s = 0.f, s2 = 0.f;
    #pragma unroll
    for (int i = 0; i < 4; i++) {
        x[i] = p[lane + 32 * i];
        s  += x[i].x + x[i].y + x[i].z + x[i].w;
        s2 += x[i].x * x[i].x + x[i].y * x[i].y + x[i].z * x[i].z + x[i].w * x[i].w;
    }
    #pragma unroll
    for (int o = 16; o; o >>= 1) {
        s  += __shfl_xor_sync(0xffffffffu, s, o);
        s2 += __shfl_xor_sync(0xffffffffu, s2, o);
    }
    float mu  = s * (1.0f / CDIM);
    float var = s2 * (1.0f / CDIM) - mu * mu;
    float rs  = rsqrtf(var + LN_EPS);
    float4* o4 = (float4*)(out + row * CDIM);
    const float4* gp = (const float4*)g;
    const float4* bp = (const float4*)be;
    #pragma unroll
    for (int i = 0; i < 4; i++) {
        int c4 = lane + 32 * i;
        float4 gv = gp[c4], bv = bp[c4], r;
        r.x = (x[i].x - mu) * rs * gv.x + bv.x;
        r.y = (x[i].y - mu) * rs * gv.y + bv.y;
        r.z = (x[i].z - mu) * rs * gv.z + bv.z;
        r.w = (x[i].w - mu) * rs * gv.w + bv.w;
        o4[c4] = r;
    }
}

// ---------------------------------------------------------------------------
// bf16x3 split-precision tensor-core GEMM: C = A[M,K] @ B[K,N]
// MODE 1: gelu_exact(acc+bias) -> Out
// MODE 2: acc+bias+Res -> Out
// MODE 3: qn2[r] += sum_c (acc+bias[c]) * Res[r][c]   (fused dot; no Out)
// ---------------------------------------------------------------------------
template <int MODE>
__global__ __launch_bounds__(256) void tgemm_kernel(
    const float* __restrict__ A, const float* __restrict__ B,
    const float* __restrict__ bias, const float* __restrict__ Res,
    float* __restrict__ Out, int M, int N, int Kd)
{
    __shared__ uint32_t AsH[128][20];   // [m][k-pair]
    __shared__ uint32_t AsL[128][20];
    __shared__ uint32_t BsH[128][20];   // [n][k-pair]
    __shared__ uint32_t BsL[128][20];

    int tid = threadIdx.x, lane = tid & 31, warp = tid >> 5;
    int g  = lane >> 2, tg = lane & 3;
    int wm = warp >> 2, wn = warp & 3;
    int m0 = wm * 64,  n0 = wn * 32;
    int bn = blockIdx.x, bm = blockIdx.y;

    const float* Ab = A + (size_t)bm * 128 * Kd;
    const float* Bb = B + (size_t)bn * 128;

    int a_r  = tid >> 1;
    int a_kb = (tid & 1) * 16;
    int b_n  = 32 * (warp & 3) + lane;
    int b_kb = 8 * (warp >> 2);

    float acc[4][4][4];
    #pragma unroll
    for (int mi = 0; mi < 4; mi++)
        #pragma unroll
        for (int ni = 0; ni < 4; ni++)
            #pragma unroll
            for (int r = 0; r < 4; r++) acc[mi][ni][r] = 0.f;

    for (int k0 = 0; k0 < Kd; k0 += 32) {
        #pragma unroll
        for (int i = 0; i < 4; i++) {
            float4 v = *(const float4*)(Ab + (size_t)a_r * Kd + k0 + a_kb + 4 * i);
            int kp = (a_kb >> 1) + 2 * i;
            uint32_t h0, l0, h1, l1;
            split2(v.x, v.y, h0, l0);
            split2(v.z, v.w, h1, l1);
            AsH[a_r][kp]     = h0;  AsL[a_r][kp]     = l0;
            AsH[a_r][kp + 1] = h1;  AsL[a_r][kp + 1] = l1;
        }
        #pragma unroll
        for (int j = 0; j < 8; j++) {
            int kp = b_kb + j;
            int k  = k0 + 2 * kp;
            float x = Bb[(size_t)k       * N + b_n];
            float y = Bb[(size_t)(k + 1) * N + b_n];
            uint32_t h, l;
            split2(x, y, h, l);
            BsH[b_n][kp] = h;  BsL[b_n][kp] = l;
        }
        __syncthreads();

        #pragma unroll
        for (int ks = 0; ks < 2; ks++) {
            int kb = ks * 8;
            uint32_t ah[4][4], al[4][4], bh[4][2], bl[4][2];
            #pragma unroll
            for (int mi = 0; mi < 4; mi++) {
                int mb = m0 + mi * 16 + g;
                ah[mi][0] = AsH[mb][kb + tg];         al[mi][0] = AsL[mb][kb + tg];
                ah[mi][1] = AsH[mb + 8][kb + tg];     al[mi][1] = AsL[mb + 8][kb + tg];
                ah[mi][2] = AsH[mb][kb + 4 + tg];     al[mi][2] = AsL[mb][kb + 4 + tg];
                ah[mi][3] = AsH[mb + 8][kb + 4 + tg]; al[mi][3] = AsL[mb + 8][kb + 4 + tg];
            }
            #pragma unroll
            for (int ni = 0; ni < 4; ni++) {
                int nb = n0 + ni * 8 + g;
                bh[ni][0] = BsH[nb][kb + tg];      bl[ni][0] = BsL[nb][kb + tg];
                bh[ni][1] = BsH[nb][kb + 4 + tg];  bl[ni][1] = BsL[nb][kb + 4 + tg];
            }
            #pragma unroll
            for (int mi = 0; mi < 4; mi++)
                #pragma unroll
                for (int ni = 0; ni < 4; ni++) {
                    mma_bf16(acc[mi][ni], ah[mi], bh[ni]);
                    mma_bf16(acc[mi][ni], ah[mi], bl[ni]);
                    mma_bf16(acc[mi][ni], al[mi], bh[ni]);
                }
        }
        __syncthreads();
    }

    if (MODE == 3) {
        // fused dot epilogue: qn2[r] += sum_c (acc + bias[c]) * Res[r][c]
        #pragma unroll
        for (int mi = 0; mi < 4; mi++)
            #pragma unroll
            for (int half = 0; half < 2; half++) {
                int r = bm * 128 + m0 + mi * 16 + g + half * 8;
                float part = 0.f;
                #pragma unroll
                for (int ni = 0; ni < 4; ni++) {
                    int c = bn * 128 + n0 + ni * 8 + 2 * tg;
                    part += (acc[mi][ni][half * 2 + 0] + bias[c])     * Res[(size_t)r * N + c];
                    part += (acc[mi][ni][half * 2 + 1] + bias[c + 1]) * Res[(size_t)r * N + c + 1];
                }
                part += __shfl_xor_sync(0xffffffffu, part, 1);
                part += __shfl_xor_sync(0xffffffffu, part, 2);
                if (tg == 0) atomicAdd(&g_qn2[r], part);
            }
        return;
    }

    #pragma unroll
    for (int mi = 0; mi < 4; mi++)
        #pragma unroll
        for (int half = 0; half < 2; half++) {
            int r = bm * 128 + m0 + mi * 16 + g + half * 8;
            #pragma unroll
            for (int ni = 0; ni < 4; ni++) {
                int c = bn * 128 + n0 + ni * 8 + 2 * tg;
                float v0 = acc[mi][ni][half * 2 + 0] + bias[c];
                float v1 = acc[mi][ni][half * 2 + 1] + bias[c + 1];
                if (MODE == 1) { v0 = v0 * normcdff(v0); v1 = v1 * normcdff(v1); }
                if (MODE == 2) {
                    v0 += Res[(size_t)r * N + c];
                    v1 += Res[(size_t)r * N + c + 1];
                }
                float2 o = { v0, v1 };
                *(float2*)(Out + (size_t)r * N + c) = o;
            }
        }
}

// ---------------------------------------------------------------------------
// Attention core: rawsim = visln @ P_b + pb (fp32, exact ranking), scale by
// 1/||q|| from g_qn2, top-5 + softmax + sparse value gather + residual + LN2.
// Per block: 16 tokens, 256 threads.
// ---------------------------------------------------------------------------
__global__ __launch_bounds__(256) void attn_kernel(
    const float* __restrict__ resid, const float* __restrict__ g2,
    const float* __restrict__ be2)
{
    __shared__ float qs[16][32];
    __shared__ float ks2[32][128];
    __shared__ float simbuf[16][128];
    __shared__ float invn[16];
    __shared__ float pb_s[KTXT];
    int tid = threadIdx.x, lane = tid & 31, warp = tid >> 5;
    int t0 = blockIdx.x * 16;
    int b  = t0 >> 12;

    if (tid < 16) {
        float qn2 = g_qn2[t0 + tid] + g_nb2[0];
        float n = sqrtf(fmaxf(qn2, 0.f));
        invn[tid] = 1.0f / fmaxf(n, 1e-12f);
    }
    if (tid < KTXT) pb_s[tid] = g_pb[b * KTXT + tid];
    __syncthreads();

    // rawsim GEMM: 16 x 128, K = 512 in chunks of 32
    float acc[2][4] = {};
    const float* Pb = g_P + (size_t)b * CDIM * KTXT;
    for (int kk = 0; kk < CDIM; kk += 32) {
        {
            int idx = tid * 2;
            int qr_ = idx >> 5, qc = idx & 31;
            const float* qp = g_visln + (size_t)(t0 + qr_) * CDIM + kk + qc;
            qs[qr_][qc]     = qp[0];
            qs[qr_][qc + 1] = qp[1];
        }
        #pragma unroll
        for (int i = 0; i < 16; i++) {
            int lin = tid + 256 * i;          // 0..4095 = 32 x 128
            int cc = lin >> 7, col = lin & 127;
            ks2[cc][col] = Pb[(size_t)(kk + cc) * KTXT + col];
        }
        __syncthreads();
        #pragma unroll
        for (int k = 0; k < 32; k++) {
            float q0 = qs[warp][k], q1 = qs[warp + 8][k];
            #pragma unroll
            for (int j = 0; j < 4; j++) {
                float kv = ks2[k][lane + 32 * j];
                acc[0][j] += q0 * kv;
                acc[1][j] += q1 * kv;
            }
        }
        __syncthreads();
    }
    #pragma unroll
    for (int j = 0; j < 4; j++) {
        simbuf[warp][lane + 32 * j]     = acc[0][j];
        simbuf[warp + 8][lane + 32 * j] = acc[1][j];
    }
    __syncthreads();

    for (int rr = 0; rr < 2; rr++) {
        int row = warp * 2 + rr;
        float sc = invn[row];
        float tv[4];
        #pragma unroll
        for (int j = 0; j < 4; j++) {
            int col = lane + 32 * j;
            tv[j] = (simbuf[row][col] + pb_s[col]) * sc;
        }

        float mval[TOPM]; int midx[TOPM];
        #pragma unroll
        for (int it = 0; it < TOPM; it++) {
            float lm = tv[0]; int lj = 0;
            #pragma unroll
            for (int j = 1; j < 4; j++) if (tv[j] > lm) { lm = tv[j]; lj = j; }
            int li = lane + 32 * lj;
            #pragma unroll
            for (int o = 16; o; o >>= 1) {
                float ov = __shfl_xor_sync(0xffffffffu, lm, o);
                int   oi = __shfl_xor_sync(0xffffffffu, li, o);
                if (ov > lm || (ov == lm && oi < li)) { lm = ov; li = oi; }
            }
            mval[it] = lm; midx[it] = li;
            if ((li & 31) == lane) tv[li >> 5] = -INFINITY;
        }

        float p[TOPM], psum = 0.f;
        #pragma unroll
        for (int it = 0; it < TOPM; it++) {
            p[it] = expf((mval[it] - mval[0]) * TEMP_INV);
            psum += p[it];
        }
        float rnorm = 1.0f / psum;

        float f[16];
        #pragma unroll
        for (int i = 0; i < 16; i++) f[i] = 0.f;
        const float* Vb = g_value + (size_t)b * KTXT * CDIM;
        #pragma unroll
        for (int it = 0; it < TOPM; it++) {
            const float* vr = Vb + (size_t)midx[it] * CDIM;
            float a_ = p[it] * rnorm;
            #pragma unroll
            for (int i = 0; i < 16; i++) f[i] += a_ * vr[lane + 32 * i];
        }

        const float* rp = resid + (size_t)(t0 + row) * CDIM;
        float s = 0.f, s2 = 0.f;
        #pragma unroll
        for (int i = 0; i < 16; i++) {
            f[i] += rp[lane + 32 * i];
            s  += f[i];
            s2 += f[i] * f[i];
        }
        #pragma unroll
        for (int o = 16; o; o >>= 1) {
            s  += __shfl_xor_sync(0xffffffffu, s, o);
            s2 += __shfl_xor_sync(0xffffffffu, s2, o);
        }
        float mu  = s * (1.0f / CDIM);
        float var = s2 * (1.0f / CDIM) - mu * mu;
        float rstd = rsqrtf(var + LN_EPS);
        float* xp = g_X + (size_t)(t0 + row) * CDIM;
        #pragma unroll
        for (int i = 0; i < 16; i++) {
            int c = lane + 32 * i;
            xp[c] = (f[i] - mu) * rstd * g2[c] + be2[c];
        }
    }
}

// ---------------------------------------------------------------------------
// Launch
// ---------------------------------------------------------------------------
extern "C" void kernel_launch(void* const* d_in, const int* in_sizes, int n_in,
                              void* d_out, int out_size)
{
    const float* vis  = (const float*)d_in[0];
    const float* text = (const float*)d_in[1];
    const float* Wq   = (const float*)d_in[2];
    const float* bq   = (const float*)d_in[3];
    const float* Wv   = (const float*)d_in[4];
    const float* bv   = (const float*)d_in[5];
    const float* W1   = (const float*)d_in[6];
    const float* b1   = (const float*)d_in[7];
    const float* W2   = (const float*)d_in[8];
    const float* b2   = (const float*)d_in[9];
    const float* g1   = (const float*)d_in[10];
    const float* be1  = (const float*)d_in[11];
    const float* g2   = (const float*)d_in[12];
    const float* be2  = (const float*)d_in[13];
    float* out = (float*)d_out;

    float *p_visln, *p_X, *p_hid, *p_P, *p_G, *p_keyt, *p_wb2, *p_qn2;
    cudaGetSymbolAddress((void**)&p_visln, g_visln);
    cudaGetSymbolAddress((void**)&p_X,     g_X);
    cudaGetSymbolAddress((void**)&p_hid,   g_hid);
    cudaGetSymbolAddress((void**)&p_P,     g_P);
    cudaGetSymbolAddress((void**)&p_G,     g_G);
    cudaGetSymbolAddress((void**)&p_keyt,  g_keyt);
    cudaGetSymbolAddress((void**)&p_wb2,   g_wb2);
    cudaGetSymbolAddress((void**)&p_qn2,   g_qn2);

    // 1) text prep (keyt, value)
    prep_text_kernel<<<(BQ * KTXT) / 8, 256>>>(text, Wv, bv);
    // 2) P_b = Wq @ keyt_b^T  (per batch), fp32
    sgemm_tn_kernel<<<dim3(1, CDIM / 128, BQ), 256>>>(
        Wq, p_keyt, p_P, TDIM, KTXT,
        0, (size_t)KTXT * TDIM, (size_t)CDIM * KTXT);
    // 3) G = Wq @ Wq^T, fp32
    sgemm_tn_kernel<<<dim3(CDIM / 128, CDIM / 128, 1), 256>>>(
        Wq, Wq, p_G, TDIM, CDIM, 0, 0, 0);
    // 4) pb, wb2, nb2
    prep_small_kernel<<<BQ + CDIM / 128, 128>>>(Wq, bq);
    // 5) LN1
    ln_kernel<<<MTOT / 8, 256>>>(vis, g1, be1, p_visln);
    // 6) qn2 = v^T (G v + 2 Wq bq)   (bf16x3 tensor cores, fused dot)
    cudaMemsetAsync(p_qn2, 0, MTOT * sizeof(float));
    tgemm_kernel<3><<<dim3(CDIM / 128, MTOT / 128), 256>>>(
        p_visln, p_G, p_wb2, p_visln, nullptr, MTOT, CDIM, CDIM);
    // 7) attention + residual + LN2 -> X
    attn_kernel<<<MTOT / 16, 256>>>(vis, g2, be2);
    // 8) H = gelu(X @ W1 + b1)
    tgemm_kernel<1><<<dim3(HID / 128, MTOT / 128), 256>>>(
        p_X, W1, b1, nullptr, p_hid, MTOT, HID, CDIM);
    // 9) out = X + H @ W2 + b2
    tgemm_kernel<2><<<dim3(CDIM / 128, MTOT / 128), 256>>>(
        p_hid, W2, b2, p_X, out, MTOT, CDIM, HID);
}

// round 6
// speedup vs baseline: 1.0441x; 1.0441x over previous
#include <cuda_runtime.h>
#include <cuda_bf16.h>
#include <math.h>
#include <stdint.h>

// ---------------------------------------------------------------------------
// Problem constants
// ---------------------------------------------------------------------------
#define BQ    8
#define MTOT  32768
#define CDIM  512
#define TDIM  768
#define KTXT  128
#define HID   2048
#define TOPM  5
#define TEMP_INV (1.0f/0.07f)
#define LN_EPS 1e-5f

// ---------------------------------------------------------------------------
// Scratch (device globals)
// ---------------------------------------------------------------------------
static __device__ float    g_visln[MTOT * CDIM];            // 64 MB fp32 (attn + MODE3 Res)
static __device__ uint32_t g_vh[MTOT * CDIM / 2];           // packed bf16 hi
static __device__ uint32_t g_vl[MTOT * CDIM / 2];           // packed bf16 lo
static __device__ float    g_X [MTOT * CDIM];               // fp32 (MODE2 Res)
static __device__ uint32_t g_Xh[MTOT * CDIM / 2];
static __device__ uint32_t g_Xl[MTOT * CDIM / 2];
static __device__ uint32_t g_Hh[(size_t)MTOT * HID / 2];    // 128 MB
static __device__ uint32_t g_Hl[(size_t)MTOT * HID / 2];    // 128 MB
static __device__ float    g_keyt [BQ * KTXT * TDIM];
static __device__ float    g_value[BQ * KTXT * CDIM];
static __device__ float    g_P [BQ * CDIM * KTXT];
static __device__ float    g_G [CDIM * CDIM];
static __device__ uint32_t g_Gh [CDIM * CDIM / 2];          // B-fmt [N][K/2]
static __device__ uint32_t g_Gl [CDIM * CDIM / 2];
static __device__ uint32_t g_W1h[(size_t)HID * CDIM / 2];   // [2048][256]
static __device__ uint32_t g_W1l[(size_t)HID * CDIM / 2];
static __device__ uint32_t g_W2h[(size_t)CDIM * HID / 2];   // [512][1024]
static __device__ uint32_t g_W2l[(size_t)CDIM * HID / 2];
static __device__ float    g_pb [BQ * KTXT];
static __device__ float    g_wb2[CDIM];
static __device__ float    g_nb2[1];
static __device__ float    g_qn2[MTOT];

// ---------------------------------------------------------------------------
// Helpers
// ---------------------------------------------------------------------------
__device__ __forceinline__ void split2(float x, float y,
                                       uint32_t& hi, uint32_t& lo) {
    __nv_bfloat16 hx = __float2bfloat16_rn(x);
    __nv_bfloat16 hy = __float2bfloat16_rn(y);
    float rx = x - __bfloat162float(hx);
    float ry = y - __bfloat162float(hy);
    __nv_bfloat162 h2 = __halves2bfloat162(hx, hy);
    __nv_bfloat162 l2 = __floats2bfloat162_rn(rx, ry);
    hi = *reinterpret_cast<uint32_t*>(&h2);
    lo = *reinterpret_cast<uint32_t*>(&l2);
}

__device__ __forceinline__ void mma_bf16(float* c, const uint32_t* a, const uint32_t* b) {
    asm volatile(
        "mma.sync.aligned.m16n8k16.row.col.f32.bf16.bf16.f32 "
        "{%0,%1,%2,%3}, {%4,%5,%6,%7}, {%8,%9}, {%0,%1,%2,%3};\n"
        : "+f"(c[0]), "+f"(c[1]), "+f"(c[2]), "+f"(c[3])
        : "r"(a[0]), "r"(a[1]), "r"(a[2]), "r"(a[3]), "r"(b[0]), "r"(b[1]));
}

__device__ __forceinline__ void cp16(uint32_t* dst_smem, const uint32_t* src) {
    uint32_t s = (uint32_t)__cvta_generic_to_shared(dst_smem);
    asm volatile("cp.async.cg.shared.global [%0], [%1], 16;\n" :: "r"(s), "l"(src));
}
__device__ __forceinline__ void cp_commit() {
    asm volatile("cp.async.commit_group;\n");
}
__device__ __forceinline__ void cp_wait1() {
    asm volatile("cp.async.wait_group 1;\n");
}

// ---------------------------------------------------------------------------
// Kernel: text prep — keyt = l2norm(text), value = text @ Wv + bv
// ---------------------------------------------------------------------------
__global__ __launch_bounds__(256) void prep_text_kernel(
    const float* __restrict__ text, const float* __restrict__ Wv,
    const float* __restrict__ bv)
{
    __shared__ float ts[8][TDIM];
    int tid = threadIdx.x, lane = tid & 31, warp = tid >> 5;
    int b  = blockIdx.x >> 4;
    int kb = (blockIdx.x & 15) * 8;
    const float* tb = text + ((size_t)b * KTXT + kb) * TDIM;

    #pragma unroll
    for (int i = 0; i < 24; i++) {
        int lin = tid + 256 * i;
        int r = lin / TDIM, c = lin % TDIM;
        ts[r][c] = tb[(size_t)r * TDIM + c];
    }
    __syncthreads();

    {
        int r = warp;
        float s = 0.f;
        for (int i = lane; i < TDIM; i += 32) { float v = ts[r][i]; s += v * v; }
        #pragma unroll
        for (int o = 16; o; o >>= 1) s += __shfl_xor_sync(0xffffffffu, s, o);
        float inv = 1.0f / fmaxf(sqrtf(s), 1e-12f);
        float* kr = g_keyt + ((size_t)b * KTXT + kb + r) * TDIM;
        for (int i = lane; i < TDIM; i += 32) kr[i] = ts[r][i] * inv;
    }

    float acc[8][2];
    #pragma unroll
    for (int r = 0; r < 8; r++) { acc[r][0] = 0.f; acc[r][1] = 0.f; }
    int c0 = tid, c1 = tid + 256;
    for (int t = 0; t < TDIM; t++) {
        float w0 = Wv[(size_t)t * CDIM + c0];
        float w1 = Wv[(size_t)t * CDIM + c1];
        #pragma unroll
        for (int r = 0; r < 8; r++) {
            float tv = ts[r][t];
            acc[r][0] += tv * w0;
            acc[r][1] += tv * w1;
        }
    }
    float bb0 = bv[c0], bb1 = bv[c1];
    #pragma unroll
    for (int r = 0; r < 8; r++) {
        float* vr = g_value + ((size_t)b * KTXT + kb + r) * CDIM;
        vr[c0] = acc[r][0] + bb0;
        vr[c1] = acc[r][1] + bb1;
    }
}

// ---------------------------------------------------------------------------
// Kernel: small fp32 SGEMM  C[M,N] = A[M,K] @ B2[N,K]^T  (for P and G)
// ---------------------------------------------------------------------------
__global__ __launch_bounds__(256) void sgemm_tn_kernel(
    const float* __restrict__ A, const float* __restrict__ B2,
    float* __restrict__ C, int Kd, int N,
    size_t aStride, size_t bStride, size_t cStride)
{
    __shared__ float As[8][128];
    __shared__ float Bs[8][128];
    int tid = threadIdx.x;
    int tx = tid & 15, ty = tid >> 4;
    int bn = blockIdx.x, bm = blockIdx.y, bz = blockIdx.z;
    const float* Ab = A  + (size_t)bz * aStride + (size_t)bm * 128 * Kd;
    const float* Bb = B2 + (size_t)bz * bStride + (size_t)bn * 128 * Kd;
    int l_r = tid >> 1, l_k = (tid & 1) * 4;

    float acc[8][8];
    #pragma unroll
    for (int i = 0; i < 8; i++)
        #pragma unroll
        for (int j = 0; j < 8; j++) acc[i][j] = 0.f;

    for (int k0 = 0; k0 < Kd; k0 += 8) {
        float4 av = *(const float4*)(Ab + (size_t)l_r * Kd + k0 + l_k);
        As[l_k + 0][l_r] = av.x;
        As[l_k + 1][l_r] = av.y;
        As[l_k + 2][l_r] = av.z;
        As[l_k + 3][l_r] = av.w;
        float4 bv = *(const float4*)(Bb + (size_t)l_r * Kd + k0 + l_k);
        Bs[l_k + 0][l_r] = bv.x;
        Bs[l_k + 1][l_r] = bv.y;
        Bs[l_k + 2][l_r] = bv.z;
        Bs[l_k + 3][l_r] = bv.w;
        __syncthreads();
        #pragma unroll
        for (int k = 0; k < 8; k++) {
            float ar[8], br[8];
            #pragma unroll
            for (int i = 0; i < 4; i++) {
                ar[i]     = As[k][ty * 4 + i];
                ar[4 + i] = As[k][64 + ty * 4 + i];
                br[i]     = Bs[k][tx * 4 + i];
                br[4 + i] = Bs[k][64 + tx * 4 + i];
            }
            #pragma unroll
            for (int i = 0; i < 8; i++)
                #pragma unroll
                for (int j = 0; j < 8; j++) acc[i][j] += ar[i] * br[j];
        }
        __syncthreads();
    }

    float* Cb = C + (size_t)bz * cStride;
    #pragma unroll
    for (int gi = 0; gi < 2; gi++)
        #pragma unroll
        for (int ii = 0; ii < 4; ii++) {
            int r = bm * 128 + gi * 64 + ty * 4 + ii;
            #pragma unroll
            for (int gj = 0; gj < 2; gj++) {
                int cb = bn * 128 + gj * 64 + tx * 4;
                float4 o;
                o.x = acc[gi * 4 + ii][gj * 4 + 0];
                o.y = acc[gi * 4 + ii][gj * 4 + 1];
                o.z = acc[gi * 4 + ii][gj * 4 + 2];
                o.w = acc[gi * 4 + ii][gj * 4 + 3];
                *(float4*)(Cb + (size_t)r * N + cb) = o;
            }
        }
}

// ---------------------------------------------------------------------------
// Kernel: prep_small2 — warp-per-row dots
// global warp id: 0..1023 -> pb ; 1024..1535 -> wb2 ; 1536 -> nb2
// ---------------------------------------------------------------------------
__global__ __launch_bounds__(256) void prep_small2_kernel(
    const float* __restrict__ Wq, const float* __restrict__ bq)
{
    int gw = blockIdx.x * 8 + (threadIdx.x >> 5);
    int lane = threadIdx.x & 31;
    if (gw > 1536) return;
    const float4* bp = (const float4*)bq;
    float s = 0.f;
    if (gw < 1024) {
        const float4* kr = (const float4*)(g_keyt + (size_t)gw * TDIM);
        #pragma unroll
        for (int i = 0; i < 6; i++) {
            float4 a = kr[lane + 32 * i], c = bp[lane + 32 * i];
            s += a.x * c.x + a.y * c.y + a.z * c.z + a.w * c.w;
        }
        #pragma unroll
        for (int o = 16; o; o >>= 1) s += __shfl_xor_sync(0xffffffffu, s, o);
        if (!lane) g_pb[gw] = s;
    } else if (gw < 1536) {
        int c = gw - 1024;
        const float4* wr = (const float4*)(Wq + (size_t)c * TDIM);
        #pragma unroll
        for (int i = 0; i < 6; i++) {
            float4 a = wr[lane + 32 * i], d = bp[lane + 32 * i];
            s += a.x * d.x + a.y * d.y + a.z * d.z + a.w * d.w;
        }
        #pragma unroll
        for (int o = 16; o; o >>= 1) s += __shfl_xor_sync(0xffffffffu, s, o);
        if (!lane) g_wb2[c] = 2.0f * s;
    } else {
        #pragma unroll
        for (int i = 0; i < 6; i++) {
            float4 a = bp[lane + 32 * i];
            s += a.x * a.x + a.y * a.y + a.z * a.z + a.w * a.w;
        }
        #pragma unroll
        for (int o = 16; o; o >>= 1) s += __shfl_xor_sync(0xffffffffu, s, o);
        if (!lane) g_nb2[0] = s;
    }
}

// ---------------------------------------------------------------------------
// Kernel: convert fp32 B [K][N] -> packed bf16 planes [N][K/2] (transposed)
// ---------------------------------------------------------------------------
__global__ __launch_bounds__(256) void convert_b_kernel(
    const float* __restrict__ in, uint32_t* __restrict__ oh,
    uint32_t* __restrict__ ol, int Kd, int N)
{
    __shared__ float t[64][65];
    int k0 = blockIdx.y * 64, n0 = blockIdx.x * 64;
    int tid = threadIdx.x;
    #pragma unroll
    for (int i = 0; i < 16; i++) {
        int lin = tid + 256 * i;
        int r = lin >> 6, c = lin & 63;
        t[r][c] = in[(size_t)(k0 + r) * N + n0 + c];
    }
    __syncthreads();
    int K2 = Kd >> 1;
    #pragma unroll
    for (int i = 0; i < 8; i++) {
        int lin = tid + 256 * i;
        int n = lin >> 5, kp = lin & 31;
        uint32_t h, l;
        split2(t[2 * kp][n], t[2 * kp + 1][n], h, l);
        size_t o = (size_t)(n0 + n) * K2 + (k0 >> 1) + kp;
        oh[o] = h;  ol[o] = l;
    }
}

// ---------------------------------------------------------------------------
// Kernel: LayerNorm -> fp32 + packed hi/lo planes
// ---------------------------------------------------------------------------
__global__ __launch_bounds__(256) void ln_kernel(
    const float* __restrict__ in, const float* __restrict__ g,
    const float* __restrict__ be, float* __restrict__ out,
    uint32_t* __restrict__ oh, uint32_t* __restrict__ ol)
{
    int warp = threadIdx.x >> 5, lane = threadIdx.x & 31;
    size_t row = (size_t)blockIdx.x * 8 + warp;
    const float4* p = (const float4*)(in + row * CDIM);
    float4 x[4];
    float s = 0.f, s2 = 0.f;
    #pragma unroll
    for (int i = 0; i < 4; i++) {
        x[i] = p[lane + 32 * i];
        s  += x[i].x + x[i].y + x[i].z + x[i].w;
        s2 += x[i].x * x[i].x + x[i].y * x[i].y + x[i].z * x[i].z + x[i].w * x[i].w;
    }
    #pragma unroll
    for (int o = 16; o; o >>= 1) {
        s  += __shfl_xor_sync(0xffffffffu, s, o);
        s2 += __shfl_xor_sync(0xffffffffu, s2, o);
    }
    float mu  = s * (1.0f / CDIM);
    float var = s2 * (1.0f / CDIM) - mu * mu;
    float rs  = rsqrtf(var + LN_EPS);
    float4* o4 = (float4*)(out + row * CDIM);
    const float4* gp = (const float4*)g;
    const float4* bp = (const float4*)be;
    #pragma unroll
    for (int i = 0; i < 4; i++) {
        int c4 = lane + 32 * i;
        float4 gv = gp[c4], bv = bp[c4], r;
        r.x = (x[i].x - mu) * rs * gv.x + bv.x;
        r.y = (x[i].y - mu) * rs * gv.y + bv.y;
        r.z = (x[i].z - mu) * rs * gv.z + bv.z;
        r.w = (x[i].w - mu) * rs * gv.w + bv.w;
        o4[c4] = r;
        uint2 h, l;
        split2(r.x, r.y, h.x, l.x);
        split2(r.z, r.w, h.y, l.y);
        *(uint2*)(oh + row * (CDIM / 2) + 2 * c4) = h;
        *(uint2*)(ol + row * (CDIM / 2) + 2 * c4) = l;
    }
}

// ---------------------------------------------------------------------------
// bf16x3 tensor-core GEMM on pre-split planes, cp.async double-buffered.
// A: [M][K/2] u32 hi/lo, B: [N][K/2] u32 hi/lo (both k-pair packed).
// MODE 1: gelu(acc+bias) -> packed Oh/Ol   (H for FFN2)
// MODE 2: acc+bias+Res -> Out fp32
// MODE 3: qn2[r] += sum_c (acc+bias[c]) * Res[r][c]
// 128x128 tile, BK=32 (16 kp), 256 threads, 8 warps (2m x 4n).
// ---------------------------------------------------------------------------
#define PLANE 2560           // 128 rows * 20 u32
#define STAGE (4 * PLANE)    // AsH AsL BsH BsL

template <int MODE>
__global__ __launch_bounds__(256) void tgemm2_kernel(
    const uint32_t* __restrict__ Ah, const uint32_t* __restrict__ Al,
    const uint32_t* __restrict__ Bh, const uint32_t* __restrict__ Bl,
    const float* __restrict__ bias, const float* __restrict__ Res,
    float* __restrict__ Out, uint32_t* __restrict__ Oh, uint32_t* __restrict__ Ol,
    int M, int N, int Kd)
{
    extern __shared__ uint32_t sm[];
    int K2 = Kd >> 1;
    int tid = threadIdx.x, lane = tid & 31, warp = tid >> 5;
    int g  = lane >> 2, tg = lane & 3;
    int wm = warp >> 2, wn = warp & 3;
    int m0 = wm * 64,  n0 = wn * 32;
    int bn = blockIdx.x, bm = blockIdx.y;

    const uint32_t* AhB = Ah + (size_t)bm * 128 * K2;
    const uint32_t* AlB = Al + (size_t)bm * 128 * K2;
    const uint32_t* BhB = Bh + (size_t)bn * 128 * K2;
    const uint32_t* BlB = Bl + (size_t)bn * 128 * K2;

    // loader: chunks t and t+256; chunk -> (row, kb)
    int lrow0 = tid >> 2, lkb = (tid & 3) * 4;

    float acc[4][4][4];
    #pragma unroll
    for (int mi = 0; mi < 4; mi++)
        #pragma unroll
        for (int ni = 0; ni < 4; ni++)
            #pragma unroll
            for (int r = 0; r < 4; r++) acc[mi][ni][r] = 0.f;

    int nT = K2 / 16;

    // prologue: prefetch tiles 0 and 1
    #pragma unroll
    for (int pf = 0; pf < 2; pf++) {
        uint32_t* st = sm + pf * STAGE;
        int kp0 = pf * 16;
        #pragma unroll
        for (int c = 0; c < 2; c++) {
            int row = lrow0 + 64 * c;
            size_t go = (size_t)row * K2 + kp0 + lkb;
            int so = row * 20 + lkb;
            cp16(st + so,             AhB + go);
            cp16(st + PLANE + so,     AlB + go);
            cp16(st + 2 * PLANE + so, BhB + go);
            cp16(st + 3 * PLANE + so, BlB + go);
        }
        cp_commit();
    }

    for (int t = 0; t < nT; t++) {
        cp_wait1();
        __syncthreads();
        uint32_t* st = sm + (t & 1) * STAGE;
        uint32_t* AsH = st;
        uint32_t* AsL = st + PLANE;
        uint32_t* BsH = st + 2 * PLANE;
        uint32_t* BsL = st + 3 * PLANE;

        #pragma unroll
        for (int ks = 0; ks < 2; ks++) {
            int kb = ks * 8;
            uint32_t ah[4][4], al[4][4], bh[4][2], bl[4][2];
            #pragma unroll
            for (int mi = 0; mi < 4; mi++) {
                int mb = m0 + mi * 16 + g;
                ah[mi][0] = AsH[mb * 20 + kb + tg];
                al[mi][0] = AsL[mb * 20 + kb + tg];
                ah[mi][1] = AsH[(mb + 8) * 20 + kb + tg];
                al[mi][1] = AsL[(mb + 8) * 20 + kb + tg];
                ah[mi][2] = AsH[mb * 20 + kb + 4 + tg];
                al[mi][2] = AsL[mb * 20 + kb + 4 + tg];
                ah[mi][3] = AsH[(mb + 8) * 20 + kb + 4 + tg];
                al[mi][3] = AsL[(mb + 8) * 20 + kb + 4 + tg];
            }
            #pragma unroll
            for (int ni = 0; ni < 4; ni++) {
                int nb = n0 + ni * 8 + g;
                bh[ni][0] = BsH[nb * 20 + kb + tg];
                bl[ni][0] = BsL[nb * 20 + kb + tg];
                bh[ni][1] = BsH[nb * 20 + kb + 4 + tg];
                bl[ni][1] = BsL[nb * 20 + kb + 4 + tg];
            }
            #pragma unroll
            for (int mi = 0; mi < 4; mi++)
                #pragma unroll
                for (int ni = 0; ni < 4; ni++) {
                    mma_bf16(acc[mi][ni], ah[mi], bh[ni]);
                    mma_bf16(acc[mi][ni], ah[mi], bl[ni]);
                    mma_bf16(acc[mi][ni], al[mi], bh[ni]);
                }
        }
        __syncthreads();
        if (t + 2 < nT) {
            uint32_t* dst = sm + (t & 1) * STAGE;
            int kp0 = (t + 2) * 16;
            #pragma unroll
            for (int c = 0; c < 2; c++) {
                int row = lrow0 + 64 * c;
                size_t go = (size_t)row * K2 + kp0 + lkb;
                int so = row * 20 + lkb;
                cp16(dst + so,             AhB + go);
                cp16(dst + PLANE + so,     AlB + go);
                cp16(dst + 2 * PLANE + so, BhB + go);
                cp16(dst + 3 * PLANE + so, BlB + go);
            }
        }
        cp_commit();
    }

    if (MODE == 3) {
        #pragma unroll
        for (int mi = 0; mi < 4; mi++)
            #pragma unroll
            for (int half = 0; half < 2; half++) {
                int r = bm * 128 + m0 + mi * 16 + g + half * 8;
                float part = 0.f;
                #pragma unroll
                for (int ni = 0; ni < 4; ni++) {
                    int c = bn * 128 + n0 + ni * 8 + 2 * tg;
                    part += (acc[mi][ni][half * 2 + 0] + bias[c])     * Res[(size_t)r * N + c];
                    part += (acc[mi][ni][half * 2 + 1] + bias[c + 1]) * Res[(size_t)r * N + c + 1];
                }
                part += __shfl_xor_sync(0xffffffffu, part, 1);
                part += __shfl_xor_sync(0xffffffffu, part, 2);
                if (tg == 0) atomicAdd(&g_qn2[r], part);
            }
        return;
    }

    #pragma unroll
    for (int mi = 0; mi < 4; mi++)
        #pragma unroll
        for (int half = 0; half < 2; half++) {
            int r = bm * 128 + m0 + mi * 16 + g + half * 8;
            #pragma unroll
            for (int ni = 0; ni < 4; ni++) {
                int c = bn * 128 + n0 + ni * 8 + 2 * tg;
                float v0 = acc[mi][ni][half * 2 + 0] + bias[c];
                float v1 = acc[mi][ni][half * 2 + 1] + bias[c + 1];
                if (MODE == 1) {
                    v0 = v0 * normcdff(v0);
                    v1 = v1 * normcdff(v1);
                    uint32_t h, l;
                    split2(v0, v1, h, l);
                    size_t o = (size_t)r * (N >> 1) + (c >> 1);
                    Oh[o] = h;  Ol[o] = l;
                } else {
                    v0 += Res[(size_t)r * N + c];
                    v1 += Res[(size_t)r * N + c + 1];
                    float2 ov = { v0, v1 };
                    *(float2*)(Out + (size_t)r * N + c) = ov;
                }
            }
        }
}

// ---------------------------------------------------------------------------
// Attention core: rawsim = visln @ P_b + pb (fp32 exact), 1/||q|| scale,
// top-5 + softmax + sparse gather + residual + LN2 -> X fp32 + packed planes
// ---------------------------------------------------------------------------
__global__ __launch_bounds__(256) void attn_kernel(
    const float* __restrict__ resid, const float* __restrict__ g2,
    const float* __restrict__ be2)
{
    __shared__ float qs[16][32];
    __shared__ float ks2[32][128];
    __shared__ float simbuf[16][128];
    __shared__ float invn[16];
    __shared__ float pb_s[KTXT];
    int tid = threadIdx.x, lane = tid & 31, warp = tid >> 5;
    int t0 = blockIdx.x * 16;
    int b  = t0 >> 12;

    if (tid < 16) {
        float qn2 = g_qn2[t0 + tid] + g_nb2[0];
        float n = sqrtf(fmaxf(qn2, 0.f));
        invn[tid] = 1.0f / fmaxf(n, 1e-12f);
    }
    if (tid < KTXT) pb_s[tid] = g_pb[b * KTXT + tid];
    __syncthreads();

    float acc[2][4] = {};
    const float* Pb = g_P + (size_t)b * CDIM * KTXT;
    for (int kk = 0; kk < CDIM; kk += 32) {
        {
            int idx = tid * 2;
            int qr_ = idx >> 5, qc = idx & 31;
            const float* qp = g_visln + (size_t)(t0 + qr_) * CDIM + kk + qc;
            qs[qr_][qc]     = qp[0];
            qs[qr_][qc + 1] = qp[1];
        }
        #pragma unroll
        for (int i = 0; i < 16; i++) {
            int lin = tid + 256 * i;
            int cc = lin >> 7, col = lin & 127;
            ks2[cc][col] = Pb[(size_t)(kk + cc) * KTXT + col];
        }
        __syncthreads();
        #pragma unroll
        for (int k = 0; k < 32; k++) {
            float q0 = qs[warp][k], q1 = qs[warp + 8][k];
            #pragma unroll
            for (int j = 0; j < 4; j++) {
                float kv = ks2[k][lane + 32 * j];
                acc[0][j] += q0 * kv;
                acc[1][j] += q1 * kv;
            }
        }
        __syncthreads();
    }
    #pragma unroll
    for (int j = 0; j < 4; j++) {
        simbuf[warp][lane + 32 * j]     = acc[0][j];
        simbuf[warp + 8][lane + 32 * j] = acc[1][j];
    }
    __syncthreads();

    for (int rr = 0; rr < 2; rr++) {
        int row = warp * 2 + rr;
        float sc = invn[row];
        float tv[4];
        #pragma unroll
        for (int j = 0; j < 4; j++) {
            int col = lane + 32 * j;
            tv[j] = (simbuf[row][col] + pb_s[col]) * sc;
        }

        float mval[TOPM]; int midx[TOPM];
        #pragma unroll
        for (int it = 0; it < TOPM; it++) {
            float lm = tv[0]; int lj = 0;
            #pragma unroll
            for (int j = 1; j < 4; j++) if (tv[j] > lm) { lm = tv[j]; lj = j; }
            int li = lane + 32 * lj;
            #pragma unroll
            for (int o = 16; o; o >>= 1) {
                float ov = __shfl_xor_sync(0xffffffffu, lm, o);
                int   oi = __shfl_xor_sync(0xffffffffu, li, o);
                if (ov > lm || (ov == lm && oi < li)) { lm = ov; li = oi; }
            }
            mval[it] = lm; midx[it] = li;
            if ((li & 31) == lane) tv[li >> 5] = -INFINITY;
        }

        float p[TOPM], psum = 0.f;
        #pragma unroll
        for (int it = 0; it < TOPM; it++) {
            p[it] = expf((mval[it] - mval[0]) * TEMP_INV);
            psum += p[it];
        }
        float rnorm = 1.0f / psum;

        // thread owns 16 contiguous cols: [lane*16, lane*16+16)
        float f[16];
        #pragma unroll
        for (int i = 0; i < 16; i++) f[i] = 0.f;
        const float* Vb = g_value + (size_t)b * KTXT * CDIM;
        #pragma unroll
        for (int it = 0; it < TOPM; it++) {
            const float4* vr = (const float4*)(Vb + (size_t)midx[it] * CDIM + lane * 16);
            float a_ = p[it] * rnorm;
            #pragma unroll
            for (int j = 0; j < 4; j++) {
                float4 v = vr[j];
                f[4 * j + 0] += a_ * v.x;
                f[4 * j + 1] += a_ * v.y;
                f[4 * j + 2] += a_ * v.z;
                f[4 * j + 3] += a_ * v.w;
            }
        }

        const float4* rp = (const float4*)(resid + (size_t)(t0 + row) * CDIM + lane * 16);
        float s = 0.f, s2 = 0.f;
        #pragma unroll
        for (int j = 0; j < 4; j++) {
            float4 v = rp[j];
            f[4 * j + 0] += v.x;  f[4 * j + 1] += v.y;
            f[4 * j + 2] += v.z;  f[4 * j + 3] += v.w;
        }
        #pragma unroll
        for (int i = 0; i < 16; i++) { s += f[i]; s2 += f[i] * f[i]; }
        #pragma unroll
        for (int o = 16; o; o >>= 1) {
            s  += __shfl_xor_sync(0xffffffffu, s, o);
            s2 += __shfl_xor_sync(0xffffffffu, s2, o);
        }
        float mu  = s * (1.0f / CDIM);
        float var = s2 * (1.0f / CDIM) - mu * mu;
        float rstd = rsqrtf(var + LN_EPS);

        size_t rbase = (size_t)(t0 + row);
        float*    xp = g_X  + rbase * CDIM + lane * 16;
        uint32_t* xh = g_Xh + rbase * (CDIM / 2) + lane * 8;
        uint32_t* xl = g_Xl + rbase * (CDIM / 2) + lane * 8;
        #pragma unroll
        for (int j = 0; j < 4; j++) {
            int c = lane * 16 + 4 * j;
            float4 o;
            o.x = (f[4 * j + 0] - mu) * rstd * g2[c + 0] + be2[c + 0];
            o.y = (f[4 * j + 1] - mu) * rstd * g2[c + 1] + be2[c + 1];
            o.z = (f[4 * j + 2] - mu) * rstd * g2[c + 2] + be2[c + 2];
            o.w = (f[4 * j + 3] - mu) * rstd * g2[c + 3] + be2[c + 3];
            *(float4*)(xp + 4 * j) = o;
            uint2 h, l;
            split2(o.x, o.y, h.x, l.x);
            split2(o.z, o.w, h.y, l.y);
            *(uint2*)(xh + 2 * j) = h;
            *(uint2*)(xl + 2 * j) = l;
        }
    }
}

// ---------------------------------------------------------------------------
// Launch
// ---------------------------------------------------------------------------
extern "C" void kernel_launch(void* const* d_in, const int* in_sizes, int n_in,
                              void* d_out, int out_size)
{
    const float* vis  = (const float*)d_in[0];
    const float* text = (const float*)d_in[1];
    const float* Wq   = (const float*)d_in[2];
    const float* bq   = (const float*)d_in[3];
    const float* Wv   = (const float*)d_in[4];
    const float* bv   = (const float*)d_in[5];
    const float* W1   = (const float*)d_in[6];
    const float* b1   = (const float*)d_in[7];
    const float* W2   = (const float*)d_in[8];
    const float* b2   = (const float*)d_in[9];
    const float* g1   = (const float*)d_in[10];
    const float* be1  = (const float*)d_in[11];
    const float* g2   = (const float*)d_in[12];
    const float* be2  = (const float*)d_in[13];
    float* out = (float*)d_out;

    float *p_visln, *p_X, *p_P, *p_G, *p_keyt, *p_wb2, *p_qn2;
    uint32_t *p_vh, *p_vl, *p_Xh, *p_Xl, *p_Hh, *p_Hl;
    uint32_t *p_Gh, *p_Gl, *p_W1h, *p_W1l, *p_W2h, *p_W2l;
    cudaGetSymbolAddress((void**)&p_visln, g_visln);
    cudaGetSymbolAddress((void**)&p_X,     g_X);
    cudaGetSymbolAddress((void**)&p_P,     g_P);
    cudaGetSymbolAddress((void**)&p_G,     g_G);
    cudaGetSymbolAddress((void**)&p_keyt,  g_keyt);
    cudaGetSymbolAddress((void**)&p_wb2,   g_wb2);
    cudaGetSymbolAddress((void**)&p_qn2,   g_qn2);
    cudaGetSymbolAddress((void**)&p_vh,    g_vh);
    cudaGetSymbolAddress((void**)&p_vl,    g_vl);
    cudaGetSymbolAddress((void**)&p_Xh,    g_Xh);
    cudaGetSymbolAddress((void**)&p_Xl,    g_Xl);
    cudaGetSymbolAddress((void**)&p_Hh,    g_Hh);
    cudaGetSymbolAddress((void**)&p_Hl,    g_Hl);
    cudaGetSymbolAddress((void**)&p_Gh,    g_Gh);
    cudaGetSymbolAddress((void**)&p_Gl,    g_Gl);
    cudaGetSymbolAddress((void**)&p_W1h,   g_W1h);
    cudaGetSymbolAddress((void**)&p_W1l,   g_W1l);
    cudaGetSymbolAddress((void**)&p_W2h,   g_W2h);
    cudaGetSymbolAddress((void**)&p_W2l,   g_W2l);

    const int SMEM = 2 * STAGE * 4;   // 80 KB
    cudaFuncSetAttribute(tgemm2_kernel<1>, cudaFuncAttributeMaxDynamicSharedMemorySize, SMEM);
    cudaFuncSetAttribute(tgemm2_kernel<2>, cudaFuncAttributeMaxDynamicSharedMemorySize, SMEM);
    cudaFuncSetAttribute(tgemm2_kernel<3>, cudaFuncAttributeMaxDynamicSharedMemorySize, SMEM);

    // 1) text prep (keyt, value)
    prep_text_kernel<<<(BQ * KTXT) / 8, 256>>>(text, Wv, bv);
    // 2) P_b = Wq @ keyt_b^T  per batch (fp32)
    sgemm_tn_kernel<<<dim3(1, CDIM / 128, BQ), 256>>>(
        Wq, p_keyt, p_P, TDIM, KTXT,
        0, (size_t)KTXT * TDIM, (size_t)CDIM * KTXT);
    // 3) G = Wq @ Wq^T (fp32)
    sgemm_tn_kernel<<<dim3(CDIM / 128, CDIM / 128, 1), 256>>>(
        Wq, Wq, p_G, TDIM, CDIM, 0, 0, 0);
    // 4) pb, wb2, nb2
    prep_small2_kernel<<<193, 256>>>(Wq, bq);
    // 5) convert weights to packed planes
    convert_b_kernel<<<dim3(CDIM / 64, CDIM / 64), 256>>>(p_G, p_Gh, p_Gl, CDIM, CDIM);
    convert_b_kernel<<<dim3(HID / 64, CDIM / 64), 256>>>(W1, p_W1h, p_W1l, CDIM, HID);
    convert_b_kernel<<<dim3(CDIM / 64, HID / 64), 256>>>(W2, p_W2h, p_W2l, HID, CDIM);
    // 6) LN1 -> visln fp32 + vh/vl
    ln_kernel<<<MTOT / 8, 256>>>(vis, g1, be1, p_visln, p_vh, p_vl);
    // 7) qn2 = v^T (G v + 2 Wq bq)
    cudaMemsetAsync(p_qn2, 0, MTOT * sizeof(float));
    tgemm2_kernel<3><<<dim3(CDIM / 128, MTOT / 128), 256, SMEM>>>(
        p_vh, p_vl, p_Gh, p_Gl, p_wb2, p_visln, nullptr, nullptr, nullptr,
        MTOT, CDIM, CDIM);
    // 8) attention + residual + LN2 -> X fp32 + Xh/Xl
    attn_kernel<<<MTOT / 16, 256>>>(vis, g2, be2);
    // 9) H = gelu(X @ W1 + b1) -> packed Hh/Hl
    tgemm2_kernel<1><<<dim3(HID / 128, MTOT / 128), 256, SMEM>>>(
        p_Xh, p_Xl, p_W1h, p_W1l, b1, nullptr, nullptr, p_Hh, p_Hl,
        MTOT, HID, CDIM);
    // 10) out = X + H @ W2 + b2
    tgemm2_kernel<2><<<dim3(CDIM / 128, MTOT / 128), 256, SMEM>>>(
        p_Hh, p_Hl, p_W2h, p_W2l, b2, p_X, out, nullptr, nullptr,
        MTOT, CDIM, HID);
}

// round 8
// speedup vs baseline: 1.1283x; 1.0806x over previous
#include <cuda_runtime.h>
#include <cuda_bf16.h>
#include <math.h>
#include <stdint.h>

// ---------------------------------------------------------------------------
// Problem constants
// ---------------------------------------------------------------------------
#define BQ    8
#define MTOT  32768
#define CDIM  512
#define TDIM  768
#define KTXT  128
#define HID   2048
#define TOPM  5
#define TEMP_INV (1.0f/0.07f)
#define LN_EPS 1e-5f

// ---------------------------------------------------------------------------
// Scratch (device globals)
// ---------------------------------------------------------------------------
static __device__ float    g_visln[MTOT * CDIM];
static __device__ uint32_t g_vh[MTOT * CDIM / 2];
static __device__ uint32_t g_vl[MTOT * CDIM / 2];
static __device__ float    g_X [MTOT * CDIM];
static __device__ uint32_t g_Xh[MTOT * CDIM / 2];
static __device__ uint32_t g_Xl[MTOT * CDIM / 2];
static __device__ uint32_t g_Hh[(size_t)MTOT * HID / 2];
static __device__ uint32_t g_Hl[(size_t)MTOT * HID / 2];
static __device__ float    g_keyt [BQ * KTXT * TDIM];
static __device__ float    g_value[BQ * KTXT * CDIM];
static __device__ float    g_P [BQ * CDIM * KTXT];
static __device__ float    g_G [CDIM * CDIM];
static __device__ uint32_t g_Gh [CDIM * CDIM / 2];
static __device__ uint32_t g_Gl [CDIM * CDIM / 2];
static __device__ uint32_t g_W1h[(size_t)HID * CDIM / 2];
static __device__ uint32_t g_W1l[(size_t)HID * CDIM / 2];
static __device__ uint32_t g_W2h[(size_t)CDIM * HID / 2];
static __device__ uint32_t g_W2l[(size_t)CDIM * HID / 2];
static __device__ float    g_pb [BQ * KTXT];
static __device__ float    g_wb2[CDIM];
static __device__ float    g_nb2[1];
static __device__ float    g_qn2[MTOT];

// ---------------------------------------------------------------------------
// Helpers
// ---------------------------------------------------------------------------
__device__ __forceinline__ void split2(float x, float y,
                                       uint32_t& hi, uint32_t& lo) {
    __nv_bfloat16 hx = __float2bfloat16_rn(x);
    __nv_bfloat16 hy = __float2bfloat16_rn(y);
    float rx = x - __bfloat162float(hx);
    float ry = y - __bfloat162float(hy);
    __nv_bfloat162 h2 = __halves2bfloat162(hx, hy);
    __nv_bfloat162 l2 = __floats2bfloat162_rn(rx, ry);
    hi = *reinterpret_cast<uint32_t*>(&h2);
    lo = *reinterpret_cast<uint32_t*>(&l2);
}

__device__ __forceinline__ void mma_bf16(float* c, const uint32_t* a, const uint32_t* b) {
    asm volatile(
        "mma.sync.aligned.m16n8k16.row.col.f32.bf16.bf16.f32 "
        "{%0,%1,%2,%3}, {%4,%5,%6,%7}, {%8,%9}, {%0,%1,%2,%3};\n"
        : "+f"(c[0]), "+f"(c[1]), "+f"(c[2]), "+f"(c[3])
        : "r"(a[0]), "r"(a[1]), "r"(a[2]), "r"(a[3]), "r"(b[0]), "r"(b[1]));
}

__device__ __forceinline__ uint32_t smem_u32(const void* p) {
    uint32_t a;
    asm("{ .reg .u64 t; cvta.to.shared.u64 t, %1; cvt.u32.u64 %0, t; }"
        : "=r"(a) : "l"(p));
    return a;
}

__device__ __forceinline__ void ldsm_x4(uint32_t& r0, uint32_t& r1,
                                        uint32_t& r2, uint32_t& r3,
                                        uint32_t addr) {
    asm volatile(
        "ldmatrix.sync.aligned.m8n8.x4.shared.b16 {%0,%1,%2,%3}, [%4];"
        : "=r"(r0), "=r"(r1), "=r"(r2), "=r"(r3) : "r"(addr));
}

__device__ __forceinline__ void cp16(uint32_t* dst_smem, const uint32_t* src) {
    uint32_t s = (uint32_t)__cvta_generic_to_shared(dst_smem);
    asm volatile("cp.async.cg.shared.global [%0], [%1], 16;\n" :: "r"(s), "l"(src));
}
__device__ __forceinline__ void cp_commit() {
    asm volatile("cp.async.commit_group;\n");
}
__device__ __forceinline__ void cp_wait1() {
    asm volatile("cp.async.wait_group 1;\n");
}

// ---------------------------------------------------------------------------
// Kernel: text prep — keyt = l2norm(text), value = text @ Wv + bv
// ---------------------------------------------------------------------------
__global__ __launch_bounds__(256) void prep_text_kernel(
    const float* __restrict__ text, const float* __restrict__ Wv,
    const float* __restrict__ bv)
{
    __shared__ float ts[8][TDIM];
    int tid = threadIdx.x, lane = tid & 31, warp = tid >> 5;
    int b  = blockIdx.x >> 4;
    int kb = (blockIdx.x & 15) * 8;
    const float* tb = text + ((size_t)b * KTXT + kb) * TDIM;

    #pragma unroll
    for (int i = 0; i < 24; i++) {
        int lin = tid + 256 * i;
        int r = lin / TDIM, c = lin % TDIM;
        ts[r][c] = tb[(size_t)r * TDIM + c];
    }
    __syncthreads();

    {
        int r = warp;
        float s = 0.f;
        for (int i = lane; i < TDIM; i += 32) { float v = ts[r][i]; s += v * v; }
        #pragma unroll
        for (int o = 16; o; o >>= 1) s += __shfl_xor_sync(0xffffffffu, s, o);
        float inv = 1.0f / fmaxf(sqrtf(s), 1e-12f);
        float* kr = g_keyt + ((size_t)b * KTXT + kb + r) * TDIM;
        for (int i = lane; i < TDIM; i += 32) kr[i] = ts[r][i] * inv;
    }

    float acc[8][2];
    #pragma unroll
    for (int r = 0; r < 8; r++) { acc[r][0] = 0.f; acc[r][1] = 0.f; }
    int c0 = tid, c1 = tid + 256;
    for (int t = 0; t < TDIM; t++) {
        float w0 = Wv[(size_t)t * CDIM + c0];
        float w1 = Wv[(size_t)t * CDIM + c1];
        #pragma unroll
        for (int r = 0; r < 8; r++) {
            float tv = ts[r][t];
            acc[r][0] += tv * w0;
            acc[r][1] += tv * w1;
        }
    }
    float bb0 = bv[c0], bb1 = bv[c1];
    #pragma unroll
    for (int r = 0; r < 8; r++) {
        float* vr = g_value + ((size_t)b * KTXT + kb + r) * CDIM;
        vr[c0] = acc[r][0] + bb0;
        vr[c1] = acc[r][1] + bb1;
    }
}

// ---------------------------------------------------------------------------
// Kernel: small fp32 SGEMM  C[M,N] = A[M,K] @ B2[N,K]^T  (for P and G)
// ---------------------------------------------------------------------------
__global__ __launch_bounds__(256) void sgemm_tn_kernel(
    const float* __restrict__ A, const float* __restrict__ B2,
    float* __restrict__ C, int Kd, int N,
    size_t aStride, size_t bStride, size_t cStride)
{
    __shared__ float As[8][128];
    __shared__ float Bs[8][128];
    int tid = threadIdx.x;
    int tx = tid & 15, ty = tid >> 4;
    int bn = blockIdx.x, bm = blockIdx.y, bz = blockIdx.z;
    const float* Ab = A  + (size_t)bz * aStride + (size_t)bm * 128 * Kd;
    const float* Bb = B2 + (size_t)bz * bStride + (size_t)bn * 128 * Kd;
    int l_r = tid >> 1, l_k = (tid & 1) * 4;

    float acc[8][8];
    #pragma unroll
    for (int i = 0; i < 8; i++)
        #pragma unroll
        for (int j = 0; j < 8; j++) acc[i][j] = 0.f;

    for (int k0 = 0; k0 < Kd; k0 += 8) {
        float4 av = *(const float4*)(Ab + (size_t)l_r * Kd + k0 + l_k);
        As[l_k + 0][l_r] = av.x;
        As[l_k + 1][l_r] = av.y;
        As[l_k + 2][l_r] = av.z;
        As[l_k + 3][l_r] = av.w;
        float4 bv = *(const float4*)(Bb + (size_t)l_r * Kd + k0 + l_k);
        Bs[l_k + 0][l_r] = bv.x;
        Bs[l_k + 1][l_r] = bv.y;
        Bs[l_k + 2][l_r] = bv.z;
        Bs[l_k + 3][l_r] = bv.w;
        __syncthreads();
        #pragma unroll
        for (int k = 0; k < 8; k++) {
            float ar[8], br[8];
            #pragma unroll
            for (int i = 0; i < 4; i++) {
                ar[i]     = As[k][ty * 4 + i];
                ar[4 + i] = As[k][64 + ty * 4 + i];
                br[i]     = Bs[k][tx * 4 + i];
                br[4 + i] = Bs[k][64 + tx * 4 + i];
            }
            #pragma unroll
            for (int i = 0; i < 8; i++)
                #pragma unroll
                for (int j = 0; j < 8; j++) acc[i][j] += ar[i] * br[j];
        }
        __syncthreads();
    }

    float* Cb = C + (size_t)bz * cStride;
    #pragma unroll
    for (int gi = 0; gi < 2; gi++)
        #pragma unroll
        for (int ii = 0; ii < 4; ii++) {
            int r = bm * 128 + gi * 64 + ty * 4 + ii;
            #pragma unroll
            for (int gj = 0; gj < 2; gj++) {
                int cb = bn * 128 + gj * 64 + tx * 4;
                float4 o;
                o.x = acc[gi * 4 + ii][gj * 4 + 0];
                o.y = acc[gi * 4 + ii][gj * 4 + 1];
                o.z = acc[gi * 4 + ii][gj * 4 + 2];
                o.w = acc[gi * 4 + ii][gj * 4 + 3];
                *(float4*)(Cb + (size_t)r * N + cb) = o;
            }
        }
}

// ---------------------------------------------------------------------------
// Kernel: prep_small2 — warp-per-row dots
// ---------------------------------------------------------------------------
__global__ __launch_bounds__(256) void prep_small2_kernel(
    const float* __restrict__ Wq, const float* __restrict__ bq)
{
    int gw = blockIdx.x * 8 + (threadIdx.x >> 5);
    int lane = threadIdx.x & 31;
    if (gw > 1536) return;
    const float4* bp = (const float4*)bq;
    float s = 0.f;
    if (gw < 1024) {
        const float4* kr = (const float4*)(g_keyt + (size_t)gw * TDIM);
        #pragma unroll
        for (int i = 0; i < 6; i++) {
            float4 a = kr[lane + 32 * i], c = bp[lane + 32 * i];
            s += a.x * c.x + a.y * c.y + a.z * c.z + a.w * c.w;
        }
        #pragma unroll
        for (int o = 16; o; o >>= 1) s += __shfl_xor_sync(0xffffffffu, s, o);
        if (!lane) g_pb[gw] = s;
    } else if (gw < 1536) {
        int c = gw - 1024;
        const float4* wr = (const float4*)(Wq + (size_t)c * TDIM);
        #pragma unroll
        for (int i = 0; i < 6; i++) {
            float4 a = wr[lane + 32 * i], d = bp[lane + 32 * i];
            s += a.x * d.x + a.y * d.y + a.z * d.z + a.w * d.w;
        }
        #pragma unroll
        for (int o = 16; o; o >>= 1) s += __shfl_xor_sync(0xffffffffu, s, o);
        if (!lane) g_wb2[c] = 2.0f * s;
    } else {
        #pragma unroll
        for (int i = 0; i < 6; i++) {
            float4 a = bp[lane + 32 * i];
            s += a.x * a.x + a.y * a.y + a.z * a.z + a.w * a.w;
        }
        #pragma unroll
        for (int o = 16; o; o >>= 1) s += __shfl_xor_sync(0xffffffffu, s, o);
        if (!lane) g_nb2[0] = s;
    }
}

// ---------------------------------------------------------------------------
// Kernel: convert fp32 B [K][N] -> packed bf16 planes [N][K/2] (transposed)
// ---------------------------------------------------------------------------
__global__ __launch_bounds__(256) void convert_b_kernel(
    const float* __restrict__ in, uint32_t* __restrict__ oh,
    uint32_t* __restrict__ ol, int Kd, int N)
{
    __shared__ float t[64][65];
    int k0 = blockIdx.y * 64, n0 = blockIdx.x * 64;
    int tid = threadIdx.x;
    #pragma unroll
    for (int i = 0; i < 16; i++) {
        int lin = tid + 256 * i;
        int r = lin >> 6, c = lin & 63;
        t[r][c] = in[(size_t)(k0 + r) * N + n0 + c];
    }
    __syncthreads();
    int K2 = Kd >> 1;
    #pragma unroll
    for (int i = 0; i < 8; i++) {
        int lin = tid + 256 * i;
        int n = lin >> 5, kp = lin & 31;
        uint32_t h, l;
        split2(t[2 * kp][n], t[2 * kp + 1][n], h, l);
        size_t o = (size_t)(n0 + n) * K2 + (k0 >> 1) + kp;
        oh[o] = h;  ol[o] = l;
    }
}

// ---------------------------------------------------------------------------
// Kernel: LayerNorm -> fp32 + packed hi/lo planes
// ---------------------------------------------------------------------------
__global__ __launch_bounds__(256) void ln_kernel(
    const float* __restrict__ in, const float* __restrict__ g,
    const float* __restrict__ be, float* __restrict__ out,
    uint32_t* __restrict__ oh, uint32_t* __restrict__ ol)
{
    int warp = threadIdx.x >> 5, lane = threadIdx.x & 31;
    size_t row = (size_t)blockIdx.x * 8 + warp;
    const float4* p = (const float4*)(in + row * CDIM);
    float4 x[4];
    float s = 0.f, s2 = 0.f;
    #pragma unroll
    for (int i = 0; i < 4; i++) {
        x[i] = p[lane + 32 * i];
        s  += x[i].x + x[i].y + x[i].z + x[i].w;
        s2 += x[i].x * x[i].x + x[i].y * x[i].y + x[i].z * x[i].z + x[i].w * x[i].w;
    }
    #pragma unroll
    for (int o = 16; o; o >>= 1) {
        s  += __shfl_xor_sync(0xffffffffu, s, o);
        s2 += __shfl_xor_sync(0xffffffffu, s2, o);
    }
    float mu  = s * (1.0f / CDIM);
    float var = s2 * (1.0f / CDIM) - mu * mu;
    float rs  = rsqrtf(var + LN_EPS);
    float4* o4 = (float4*)(out + row * CDIM);
    const float4* gp = (const float4*)g;
    const float4* bp = (const float4*)be;
    #pragma unroll
    for (int i = 0; i < 4; i++) {
        int c4 = lane + 32 * i;
        float4 gv = gp[c4], bv = bp[c4], r;
        r.x = (x[i].x - mu) * rs * gv.x + bv.x;
        r.y = (x[i].y - mu) * rs * gv.y + bv.y;
        r.z = (x[i].z - mu) * rs * gv.z + bv.z;
        r.w = (x[i].w - mu) * rs * gv.w + bv.w;
        o4[c4] = r;
        uint2 h, l;
        split2(r.x, r.y, h.x, l.x);
        split2(r.z, r.w, h.y, l.y);
        *(uint2*)(oh + row * (CDIM / 2) + 2 * c4) = h;
        *(uint2*)(ol + row * (CDIM / 2) + 2 * c4) = l;
    }
}

// ---------------------------------------------------------------------------
// bf16x3 tensor-core GEMM on pre-split planes, cp.async double-buffered,
// fragment loads via ldmatrix.m8n8.x4 (stride-20 rows are conflict-free:
// banks 20r mod 32 enumerate all 8 groups; 80B rows are 16B-aligned).
// A: [M][K/2] u32 hi/lo, B: [N][K/2] u32 hi/lo.
// MODE 1: gelu(acc+bias) -> packed Oh/Ol
// MODE 2: acc+bias+Res -> Out fp32
// MODE 3: qn2[r] += sum_c (acc+bias[c]) * Res[r][c]
// ---------------------------------------------------------------------------
#define PLANE 2560           // 128 rows * 20 u32
#define STAGE (4 * PLANE)    // AsH AsL BsH BsL

template <int MODE>
__global__ __launch_bounds__(256) void tgemm2_kernel(
    const uint32_t* __restrict__ Ah, const uint32_t* __restrict__ Al,
    const uint32_t* __restrict__ Bh, const uint32_t* __restrict__ Bl,
    const float* __restrict__ bias, const float* __restrict__ Res,
    float* __restrict__ Out, uint32_t* __restrict__ Oh, uint32_t* __restrict__ Ol,
    int M, int N, int Kd)
{
    extern __shared__ uint32_t sm[];
    uint32_t sbase = smem_u32(sm);
    int K2 = Kd >> 1;
    int tid = threadIdx.x, lane = tid & 31, warp = tid >> 5;
    int g  = lane >> 2, tg = lane & 3;
    int wm = warp >> 2, wn = warp & 3;
    int m0 = wm * 64,  n0 = wn * 32;
    int bn = blockIdx.x, bm = blockIdx.y;

    const uint32_t* AhB = Ah + (size_t)bm * 128 * K2;
    const uint32_t* AlB = Al + (size_t)bm * 128 * K2;
    const uint32_t* BhB = Bh + (size_t)bn * 128 * K2;
    const uint32_t* BlB = Bl + (size_t)bn * 128 * K2;

    // cp.async loader mapping
    int lrow0 = tid >> 2, lkb = (tid & 3) * 4;

    // ldmatrix per-lane byte offsets within a plane
    // A x4: lanes 0-7: rows+0 @kb | 8-15: rows+8 @kb | 16-23: rows+0 @kb+4 | 24-31: rows+8 @kb+4
    uint32_t a_ld = (uint32_t)((m0 + (lane & 7) + ((lane >> 3) & 1) * 8) * 20
                               + ((lane >> 4) & 1) * 4) * 4;
    // B x4 (ni pair): lanes 0-7: rows+0 @kb | 8-15: rows+0 @kb+4 | 16-23: rows+8 @kb | 24-31: rows+8 @kb+4
    uint32_t b_ld = (uint32_t)((n0 + (lane & 7) + ((lane >> 4) & 1) * 8) * 20
                               + ((lane >> 3) & 1) * 4) * 4;

    float acc[4][4][4];
    #pragma unroll
    for (int mi = 0; mi < 4; mi++)
        #pragma unroll
        for (int ni = 0; ni < 4; ni++)
            #pragma unroll
            for (int r = 0; r < 4; r++) acc[mi][ni][r] = 0.f;

    int nT = K2 / 16;

    // prologue: prefetch tiles 0 and 1
    #pragma unroll
    for (int pf = 0; pf < 2; pf++) {
        uint32_t* st = sm + pf * STAGE;
        int kp0 = pf * 16;
        #pragma unroll
        for (int c = 0; c < 2; c++) {
            int row = lrow0 + 64 * c;
            size_t go = (size_t)row * K2 + kp0 + lkb;
            int so = row * 20 + lkb;
            cp16(st + so,             AhB + go);
            cp16(st + PLANE + so,     AlB + go);
            cp16(st + 2 * PLANE + so, BhB + go);
            cp16(st + 3 * PLANE + so, BlB + go);
        }
        cp_commit();
    }

    for (int t = 0; t < nT; t++) {
        cp_wait1();
        __syncthreads();
        uint32_t stb = sbase + (uint32_t)((t & 1) * STAGE * 4);

        #pragma unroll
        for (int ks = 0; ks < 2; ks++) {
            uint32_t ksoff = (uint32_t)(ks * 32);   // 8 kp = 32 bytes
            uint32_t ah[4][4], al[4][4], bh[4][2], bl[4][2];
            // A fragments: 4 x4-ldmatrix per plane
            #pragma unroll
            for (int mi = 0; mi < 4; mi++) {
                uint32_t ao = stb + a_ld + ksoff + (uint32_t)(mi * 16 * 80);
                ldsm_x4(ah[mi][0], ah[mi][1], ah[mi][2], ah[mi][3], ao);
                ldsm_x4(al[mi][0], al[mi][1], al[mi][2], al[mi][3],
                        ao + PLANE * 4);
            }
            // B fragments: 2 x4-ldmatrix per plane (ni pairs {0,1},{2,3})
            #pragma unroll
            for (int p = 0; p < 2; p++) {
                uint32_t bo = stb + 2 * PLANE * 4 + b_ld + ksoff
                            + (uint32_t)(p * 16 * 80);
                ldsm_x4(bh[2 * p][0], bh[2 * p][1], bh[2 * p + 1][0], bh[2 * p + 1][1], bo);
                ldsm_x4(bl[2 * p][0], bl[2 * p][1], bl[2 * p + 1][0], bl[2 * p + 1][1],
                        bo + PLANE * 4);
            }
            #pragma unroll
            for (int mi = 0; mi < 4; mi++)
                #pragma unroll
                for (int ni = 0; ni < 4; ni++) {
                    mma_bf16(acc[mi][ni], ah[mi], bh[ni]);
                    mma_bf16(acc[mi][ni], ah[mi], bl[ni]);
                    mma_bf16(acc[mi][ni], al[mi], bh[ni]);
                }
        }
        __syncthreads();
        if (t + 2 < nT) {
            uint32_t* dst = sm + (t & 1) * STAGE;
            int kp0 = (t + 2) * 16;
            #pragma unroll
            for (int c = 0; c < 2; c++) {
                int row = lrow0 + 64 * c;
                size_t go = (size_t)row * K2 + kp0 + lkb;
                int so = row * 20 + lkb;
                cp16(dst + so,             AhB + go);
                cp16(dst + PLANE + so,     AlB + go);
                cp16(dst + 2 * PLANE + so, BhB + go);
                cp16(dst + 3 * PLANE + so, BlB + go);
            }
        }
        cp_commit();
    }

    if (MODE == 3) {
        #pragma unroll
        for (int mi = 0; mi < 4; mi++)
            #pragma unroll
            for (int half = 0; half < 2; half++) {
                int r = bm * 128 + m0 + mi * 16 + g + half * 8;
                float part = 0.f;
                #pragma unroll
                for (int ni = 0; ni < 4; ni++) {
                    int c = bn * 128 + n0 + ni * 8 + 2 * tg;
                    part += (acc[mi][ni][half * 2 + 0] + bias[c])     * Res[(size_t)r * N + c];
                    part += (acc[mi][ni][half * 2 + 1] + bias[c + 1]) * Res[(size_t)r * N + c + 1];
                }
                part += __shfl_xor_sync(0xffffffffu, part, 1);
                part += __shfl_xor_sync(0xffffffffu, part, 2);
                if (tg == 0) atomicAdd(&g_qn2[r], part);
            }
        return;
    }

    #pragma unroll
    for (int mi = 0; mi < 4; mi++)
        #pragma unroll
        for (int half = 0; half < 2; half++) {
            int r = bm * 128 + m0 + mi * 16 + g + half * 8;
            #pragma unroll
            for (int ni = 0; ni < 4; ni++) {
                int c = bn * 128 + n0 + ni * 8 + 2 * tg;
                float v0 = acc[mi][ni][half * 2 + 0] + bias[c];
                float v1 = acc[mi][ni][half * 2 + 1] + bias[c + 1];
                if (MODE == 1) {
                    v0 = v0 * normcdff(v0);
                    v1 = v1 * normcdff(v1);
                    uint32_t h, l;
                    split2(v0, v1, h, l);
                    size_t o = (size_t)r * (N >> 1) + (c >> 1);
                    Oh[o] = h;  Ol[o] = l;
                } else {
                    v0 += Res[(size_t)r * N + c];
                    v1 += Res[(size_t)r * N + c + 1];
                    float2 ov = { v0, v1 };
                    *(float2*)(Out + (size_t)r * N + c) = ov;
                }
            }
        }
}

// ---------------------------------------------------------------------------
// Attention core (proven since R5)
// ---------------------------------------------------------------------------
__global__ __launch_bounds__(256) void attn_kernel(
    const float* __restrict__ resid, const float* __restrict__ g2,
    const float* __restrict__ be2)
{
    __shared__ float qs[16][32];
    __shared__ float ks2[32][128];
    __shared__ float simbuf[16][128];
    __shared__ float invn[16];
    __shared__ float pb_s[KTXT];
    int tid = threadIdx.x, lane = tid & 31, warp = tid >> 5;
    int t0 = blockIdx.x * 16;
    int b  = t0 >> 12;

    if (tid < 16) {
        float qn2 = g_qn2[t0 + tid] + g_nb2[0];
        float n = sqrtf(fmaxf(qn2, 0.f));
        invn[tid] = 1.0f / fmaxf(n, 1e-12f);
    }
    if (tid < KTXT) pb_s[tid] = g_pb[b * KTXT + tid];
    __syncthreads();

    float acc[2][4] = {};
    const float* Pb = g_P + (size_t)b * CDIM * KTXT;
    for (int kk = 0; kk < CDIM; kk += 32) {
        {
            int idx = tid * 2;
            int qr_ = idx >> 5, qc = idx & 31;
            const float* qp = g_visln + (size_t)(t0 + qr_) * CDIM + kk + qc;
            qs[qr_][qc]     = qp[0];
            qs[qr_][qc + 1] = qp[1];
        }
        #pragma unroll
        for (int i = 0; i < 16; i++) {
            int lin = tid + 256 * i;
            int cc = lin >> 7, col = lin & 127;
            ks2[cc][col] = Pb[(size_t)(kk + cc) * KTXT + col];
        }
        __syncthreads();
        #pragma unroll
        for (int k = 0; k < 32; k++) {
            float q0 = qs[warp][k], q1 = qs[warp + 8][k];
            #pragma unroll
            for (int j = 0; j < 4; j++) {
                float kv = ks2[k][lane + 32 * j];
                acc[0][j] += q0 * kv;
                acc[1][j] += q1 * kv;
            }
        }
        __syncthreads();
    }
    #pragma unroll
    for (int j = 0; j < 4; j++) {
        simbuf[warp][lane + 32 * j]     = acc[0][j];
        simbuf[warp + 8][lane + 32 * j] = acc[1][j];
    }
    __syncthreads();

    for (int rr = 0; rr < 2; rr++) {
        int row = warp * 2 + rr;
        float sc = invn[row];
        float tv[4];
        #pragma unroll
        for (int j = 0; j < 4; j++) {
            int col = lane + 32 * j;
            tv[j] = (simbuf[row][col] + pb_s[col]) * sc;
        }

        float mval[TOPM]; int midx[TOPM];
        #pragma unroll
        for (int it = 0; it < TOPM; it++) {
            float lm = tv[0]; int lj = 0;
            #pragma unroll
            for (int j = 1; j < 4; j++) if (tv[j] > lm) { lm = tv[j]; lj = j; }
            int li = lane + 32 * lj;
            #pragma unroll
            for (int o = 16; o; o >>= 1) {
                float ov = __shfl_xor_sync(0xffffffffu, lm, o);
                int   oi = __shfl_xor_sync(0xffffffffu, li, o);
                if (ov > lm || (ov == lm && oi < li)) { lm = ov; li = oi; }
            }
            mval[it] = lm; midx[it] = li;
            if ((li & 31) == lane) tv[li >> 5] = -INFINITY;
        }

        float p[TOPM], psum = 0.f;
        #pragma unroll
        for (int it = 0; it < TOPM; it++) {
            p[it] = expf((mval[it] - mval[0]) * TEMP_INV);
            psum += p[it];
        }
        float rnorm = 1.0f / psum;

        float f[16];
        #pragma unroll
        for (int i = 0; i < 16; i++) f[i] = 0.f;
        const float* Vb = g_value + (size_t)b * KTXT * CDIM;
        #pragma unroll
        for (int it = 0; it < TOPM; it++) {
            const float4* vr = (const float4*)(Vb + (size_t)midx[it] * CDIM + lane * 16);
            float a_ = p[it] * rnorm;
            #pragma unroll
            for (int j = 0; j < 4; j++) {
                float4 v = vr[j];
                f[4 * j + 0] += a_ * v.x;
                f[4 * j + 1] += a_ * v.y;
                f[4 * j + 2] += a_ * v.z;
                f[4 * j + 3] += a_ * v.w;
            }
        }

        const float4* rp = (const float4*)(resid + (size_t)(t0 + row) * CDIM + lane * 16);
        float s = 0.f, s2 = 0.f;
        #pragma unroll
        for (int j = 0; j < 4; j++) {
            float4 v = rp[j];
            f[4 * j + 0] += v.x;  f[4 * j + 1] += v.y;
            f[4 * j + 2] += v.z;  f[4 * j + 3] += v.w;
        }
        #pragma unroll
        for (int i = 0; i < 16; i++) { s += f[i]; s2 += f[i] * f[i]; }
        #pragma unroll
        for (int o = 16; o; o >>= 1) {
            s  += __shfl_xor_sync(0xffffffffu, s, o);
            s2 += __shfl_xor_sync(0xffffffffu, s2, o);
        }
        float mu  = s * (1.0f / CDIM);
        float var = s2 * (1.0f / CDIM) - mu * mu;
        float rstd = rsqrtf(var + LN_EPS);

        size_t rbase = (size_t)(t0 + row);
        float*    xp = g_X  + rbase * CDIM + lane * 16;
        uint32_t* xh = g_Xh + rbase * (CDIM / 2) + lane * 8;
        uint32_t* xl = g_Xl + rbase * (CDIM / 2) + lane * 8;
        #pragma unroll
        for (int j = 0; j < 4; j++) {
            int c = lane * 16 + 4 * j;
            float4 o;
            o.x = (f[4 * j + 0] - mu) * rstd * g2[c + 0] + be2[c + 0];
            o.y = (f[4 * j + 1] - mu) * rstd * g2[c + 1] + be2[c + 1];
            o.z = (f[4 * j + 2] - mu) * rstd * g2[c + 2] + be2[c + 2];
            o.w = (f[4 * j + 3] - mu) * rstd * g2[c + 3] + be2[c + 3];
            *(float4*)(xp + 4 * j) = o;
            uint2 h, l;
            split2(o.x, o.y, h.x, l.x);
            split2(o.z, o.w, h.y, l.y);
            *(uint2*)(xh + 2 * j) = h;
            *(uint2*)(xl + 2 * j) = l;
        }
    }
}

// ---------------------------------------------------------------------------
// Launch
// ---------------------------------------------------------------------------
extern "C" void kernel_launch(void* const* d_in, const int* in_sizes, int n_in,
                              void* d_out, int out_size)
{
    const float* vis  = (const float*)d_in[0];
    const float* text = (const float*)d_in[1];
    const float* Wq   = (const float*)d_in[2];
    const float* bq   = (const float*)d_in[3];
    const float* Wv   = (const float*)d_in[4];
    const float* bv   = (const float*)d_in[5];
    const float* W1   = (const float*)d_in[6];
    const float* b1   = (const float*)d_in[7];
    const float* W2   = (const float*)d_in[8];
    const float* b2   = (const float*)d_in[9];
    const float* g1   = (const float*)d_in[10];
    const float* be1  = (const float*)d_in[11];
    const float* g2   = (const float*)d_in[12];
    const float* be2  = (const float*)d_in[13];
    float* out = (float*)d_out;

    float *p_visln, *p_X, *p_P, *p_G, *p_keyt, *p_wb2, *p_qn2;
    uint32_t *p_vh, *p_vl, *p_Xh, *p_Xl, *p_Hh, *p_Hl;
    uint32_t *p_Gh, *p_Gl, *p_W1h, *p_W1l, *p_W2h, *p_W2l;
    cudaGetSymbolAddress((void**)&p_visln, g_visln);
    cudaGetSymbolAddress((void**)&p_X,     g_X);
    cudaGetSymbolAddress((void**)&p_P,     g_P);
    cudaGetSymbolAddress((void**)&p_G,     g_G);
    cudaGetSymbolAddress((void**)&p_keyt,  g_keyt);
    cudaGetSymbolAddress((void**)&p_wb2,   g_wb2);
    cudaGetSymbolAddress((void**)&p_qn2,   g_qn2);
    cudaGetSymbolAddress((void**)&p_vh,    g_vh);
    cudaGetSymbolAddress((void**)&p_vl,    g_vl);
    cudaGetSymbolAddress((void**)&p_Xh,    g_Xh);
    cudaGetSymbolAddress((void**)&p_Xl,    g_Xl);
    cudaGetSymbolAddress((void**)&p_Hh,    g_Hh);
    cudaGetSymbolAddress((void**)&p_Hl,    g_Hl);
    cudaGetSymbolAddress((void**)&p_Gh,    g_Gh);
    cudaGetSymbolAddress((void**)&p_Gl,    g_Gl);
    cudaGetSymbolAddress((void**)&p_W1h,   g_W1h);
    cudaGetSymbolAddress((void**)&p_W1l,   g_W1l);
    cudaGetSymbolAddress((void**)&p_W2h,   g_W2h);
    cudaGetSymbolAddress((void**)&p_W2l,   g_W2l);

    const int SMEM = 2 * STAGE * 4;   // 80 KB
    cudaFuncSetAttribute(tgemm2_kernel<1>, cudaFuncAttributeMaxDynamicSharedMemorySize, SMEM);
    cudaFuncSetAttribute(tgemm2_kernel<2>, cudaFuncAttributeMaxDynamicSharedMemorySize, SMEM);
    cudaFuncSetAttribute(tgemm2_kernel<3>, cudaFuncAttributeMaxDynamicSharedMemorySize, SMEM);

    // 1) text prep (keyt, value)
    prep_text_kernel<<<(BQ * KTXT) / 8, 256>>>(text, Wv, bv);
    // 2) P_b = Wq @ keyt_b^T per batch (fp32)
    sgemm_tn_kernel<<<dim3(1, CDIM / 128, BQ), 256>>>(
        Wq, p_keyt, p_P, TDIM, KTXT,
        0, (size_t)KTXT * TDIM, (size_t)CDIM * KTXT);
    // 3) G = Wq @ Wq^T (fp32)
    sgemm_tn_kernel<<<dim3(CDIM / 128, CDIM / 128, 1), 256>>>(
        Wq, Wq, p_G, TDIM, CDIM, 0, 0, 0);
    // 4) pb, wb2, nb2
    prep_small2_kernel<<<193, 256>>>(Wq, bq);
    // 5) convert weights to packed planes
    convert_b_kernel<<<dim3(CDIM / 64, CDIM / 64), 256>>>(p_G, p_Gh, p_Gl, CDIM, CDIM);
    convert_b_kernel<<<dim3(HID / 64, CDIM / 64), 256>>>(W1, p_W1h, p_W1l, CDIM, HID);
    convert_b_kernel<<<dim3(CDIM / 64, HID / 64), 256>>>(W2, p_W2h, p_W2l, HID, CDIM);
    // 6) LN1 -> visln fp32 + vh/vl
    ln_kernel<<<MTOT / 8, 256>>>(vis, g1, be1, p_visln, p_vh, p_vl);
    // 7) qn2 = v^T (G v + 2 Wq bq)
    cudaMemsetAsync(p_qn2, 0, MTOT * sizeof(float));
    tgemm2_kernel<3><<<dim3(CDIM / 128, MTOT / 128), 256, SMEM>>>(
        p_vh, p_vl, p_Gh, p_Gl, p_wb2, p_visln, nullptr, nullptr, nullptr,
        MTOT, CDIM, CDIM);
    // 8) attention + residual + LN2 -> X fp32 + Xh/Xl
    attn_kernel<<<MTOT / 16, 256>>>(vis, g2, be2);
    // 9) H = gelu(X @ W1 + b1) -> packed Hh/Hl
    tgemm2_kernel<1><<<dim3(HID / 128, MTOT / 128), 256, SMEM>>>(
        p_Xh, p_Xl, p_W1h, p_W1l, b1, nullptr, nullptr, p_Hh, p_Hl,
        MTOT, HID, CDIM);
    // 10) out = X + H @ W2 + b2
    tgemm2_kernel<2><<<dim3(CDIM / 128, MTOT / 128), 256, SMEM>>>(
        p_Hh, p_Hl, p_W2h, p_W2l, b2, p_X, out, nullptr, nullptr,
        MTOT, CDIM, HID);
}

// round 9
// speedup vs baseline: 1.4940x; 1.3242x over previous
#include <cuda_runtime.h>
#include <cuda_fp16.h>
#include <math.h>
#include <stdint.h>

// ---------------------------------------------------------------------------
// Problem constants
// ---------------------------------------------------------------------------
#define BQ    8
#define MTOT  32768
#define CDIM  512
#define TDIM  768
#define KTXT  128
#define HID   2048
#define TOPM  5
#define TEMP_INV (1.0f/0.07f)
#define LN_EPS 1e-5f
#define WSCALE 256.0f
#define WINV   (1.0f/256.0f)

// ---------------------------------------------------------------------------
// Scratch (device globals)
// ---------------------------------------------------------------------------
static __device__ float    g_visln[MTOT * CDIM];            // fp32 (attn + MODE3)
static __device__ uint32_t g_vh[MTOT * CDIM / 2];           // fp16 hi plane
static __device__ float    g_X [MTOT * CDIM];               // fp32 (MODE2 Res)
static __device__ uint32_t g_Xh[MTOT * CDIM / 2];           // fp16
static __device__ uint32_t g_Hh[(size_t)MTOT * HID / 2];    // fp16 (gelu out)
static __device__ float    g_keyt [BQ * KTXT * TDIM];
static __device__ float    g_value[BQ * KTXT * CDIM];
static __device__ float    g_P [BQ * CDIM * KTXT];
static __device__ float    g_G [CDIM * CDIM];
static __device__ uint32_t g_Gh [CDIM * CDIM / 2];          // fp16 hi (x256)
static __device__ uint32_t g_Gl [CDIM * CDIM / 2];          // fp16 lo
static __device__ uint32_t g_W1h[(size_t)HID * CDIM / 2];
static __device__ uint32_t g_W1l[(size_t)HID * CDIM / 2];
static __device__ uint32_t g_W2h[(size_t)CDIM * HID / 2];
static __device__ uint32_t g_W2l[(size_t)CDIM * HID / 2];
static __device__ float    g_pb [BQ * KTXT];
static __device__ float    g_wb2[CDIM];
static __device__ float    g_nb2[1];
static __device__ float    g_qn2[MTOT];

// ---------------------------------------------------------------------------
// Helpers
// ---------------------------------------------------------------------------
__device__ __forceinline__ uint32_t packh2(float x, float y) {
    __half2 h = __floats2half2_rn(x, y);
    return *reinterpret_cast<uint32_t*>(&h);
}

// weight split with x256 scaling: hi = fp16(256x), lo = fp16(256x - hi)
__device__ __forceinline__ void wsplit2(float x, float y,
                                        uint32_t& hi, uint32_t& lo) {
    float sx = x * WSCALE, sy = y * WSCALE;
    __half hx = __float2half_rn(sx);
    __half hy = __float2half_rn(sy);
    float rx = sx - __half2float(hx);
    float ry = sy - __half2float(hy);
    __half2 h2 = __halves2half2(hx, hy);
    __half2 l2 = __floats2half2_rn(rx, ry);
    hi = *reinterpret_cast<uint32_t*>(&h2);
    lo = *reinterpret_cast<uint32_t*>(&l2);
}

__device__ __forceinline__ void mma_f16(float* c, const uint32_t* a, const uint32_t* b) {
    asm volatile(
        "mma.sync.aligned.m16n8k16.row.col.f32.f16.f16.f32 "
        "{%0,%1,%2,%3}, {%4,%5,%6,%7}, {%8,%9}, {%0,%1,%2,%3};\n"
        : "+f"(c[0]), "+f"(c[1]), "+f"(c[2]), "+f"(c[3])
        : "r"(a[0]), "r"(a[1]), "r"(a[2]), "r"(a[3]), "r"(b[0]), "r"(b[1]));
}

__device__ __forceinline__ uint32_t smem_u32(const void* p) {
    uint32_t a;
    asm("{ .reg .u64 t; cvta.to.shared.u64 t, %1; cvt.u32.u64 %0, t; }"
        : "=r"(a) : "l"(p));
    return a;
}

__device__ __forceinline__ void ldsm_x4(uint32_t& r0, uint32_t& r1,
                                        uint32_t& r2, uint32_t& r3,
                                        uint32_t addr) {
    asm volatile(
        "ldmatrix.sync.aligned.m8n8.x4.shared.b16 {%0,%1,%2,%3}, [%4];"
        : "=r"(r0), "=r"(r1), "=r"(r2), "=r"(r3) : "r"(addr));
}

__device__ __forceinline__ void cp16(uint32_t* dst_smem, const uint32_t* src) {
    uint32_t s = (uint32_t)__cvta_generic_to_shared(dst_smem);
    asm volatile("cp.async.cg.shared.global [%0], [%1], 16;\n" :: "r"(s), "l"(src));
}
__device__ __forceinline__ void cp_commit() {
    asm volatile("cp.async.commit_group;\n");
}
__device__ __forceinline__ void cp_wait1() {
    asm volatile("cp.async.wait_group 1;\n");
}

// ---------------------------------------------------------------------------
// Kernel: text prep — keyt = l2norm(text), value = text @ Wv + bv
// ---------------------------------------------------------------------------
__global__ __launch_bounds__(256) void prep_text_kernel(
    const float* __restrict__ text, const float* __restrict__ Wv,
    const float* __restrict__ bv)
{
    __shared__ float ts[8][TDIM];
    int tid = threadIdx.x, lane = tid & 31, warp = tid >> 5;
    int b  = blockIdx.x >> 4;
    int kb = (blockIdx.x & 15) * 8;
    const float* tb = text + ((size_t)b * KTXT + kb) * TDIM;

    #pragma unroll
    for (int i = 0; i < 24; i++) {
        int lin = tid + 256 * i;
        int r = lin / TDIM, c = lin % TDIM;
        ts[r][c] = tb[(size_t)r * TDIM + c];
    }
    __syncthreads();

    {
        int r = warp;
        float s = 0.f;
        for (int i = lane; i < TDIM; i += 32) { float v = ts[r][i]; s += v * v; }
        #pragma unroll
        for (int o = 16; o; o >>= 1) s += __shfl_xor_sync(0xffffffffu, s, o);
        float inv = 1.0f / fmaxf(sqrtf(s), 1e-12f);
        float* kr = g_keyt + ((size_t)b * KTXT + kb + r) * TDIM;
        for (int i = lane; i < TDIM; i += 32) kr[i] = ts[r][i] * inv;
    }

    float acc[8][2];
    #pragma unroll
    for (int r = 0; r < 8; r++) { acc[r][0] = 0.f; acc[r][1] = 0.f; }
    int c0 = tid, c1 = tid + 256;
    for (int t = 0; t < TDIM; t++) {
        float w0 = Wv[(size_t)t * CDIM + c0];
        float w1 = Wv[(size_t)t * CDIM + c1];
        #pragma unroll
        for (int r = 0; r < 8; r++) {
            float tv = ts[r][t];
            acc[r][0] += tv * w0;
            acc[r][1] += tv * w1;
        }
    }
    float bb0 = bv[c0], bb1 = bv[c1];
    #pragma unroll
    for (int r = 0; r < 8; r++) {
        float* vr = g_value + ((size_t)b * KTXT + kb + r) * CDIM;
        vr[c0] = acc[r][0] + bb0;
        vr[c1] = acc[r][1] + bb1;
    }
}

// ---------------------------------------------------------------------------
// Kernel: small fp32 SGEMM  C[M,N] = A[M,K] @ B2[N,K]^T  (for P and G)
// ---------------------------------------------------------------------------
__global__ __launch_bounds__(256) void sgemm_tn_kernel(
    const float* __restrict__ A, const float* __restrict__ B2,
    float* __restrict__ C, int Kd, int N,
    size_t aStride, size_t bStride, size_t cStride)
{
    __shared__ float As[8][128];
    __shared__ float Bs[8][128];
    int tid = threadIdx.x;
    int tx = tid & 15, ty = tid >> 4;
    int bn = blockIdx.x, bm = blockIdx.y, bz = blockIdx.z;
    const float* Ab = A  + (size_t)bz * aStride + (size_t)bm * 128 * Kd;
    const float* Bb = B2 + (size_t)bz * bStride + (size_t)bn * 128 * Kd;
    int l_r = tid >> 1, l_k = (tid & 1) * 4;

    float acc[8][8];
    #pragma unroll
    for (int i = 0; i < 8; i++)
        #pragma unroll
        for (int j = 0; j < 8; j++) acc[i][j] = 0.f;

    for (int k0 = 0; k0 < Kd; k0 += 8) {
        float4 av = *(const float4*)(Ab + (size_t)l_r * Kd + k0 + l_k);
        As[l_k + 0][l_r] = av.x;
        As[l_k + 1][l_r] = av.y;
        As[l_k + 2][l_r] = av.z;
        As[l_k + 3][l_r] = av.w;
        float4 bv = *(const float4*)(Bb + (size_t)l_r * Kd + k0 + l_k);
        Bs[l_k + 0][l_r] = bv.x;
        Bs[l_k + 1][l_r] = bv.y;
        Bs[l_k + 2][l_r] = bv.z;
        Bs[l_k + 3][l_r] = bv.w;
        __syncthreads();
        #pragma unroll
        for (int k = 0; k < 8; k++) {
            float ar[8], br[8];
            #pragma unroll
            for (int i = 0; i < 4; i++) {
                ar[i]     = As[k][ty * 4 + i];
                ar[4 + i] = As[k][64 + ty * 4 + i];
                br[i]     = Bs[k][tx * 4 + i];
                br[4 + i] = Bs[k][64 + tx * 4 + i];
            }
            #pragma unroll
            for (int i = 0; i < 8; i++)
                #pragma unroll
                for (int j = 0; j < 8; j++) acc[i][j] += ar[i] * br[j];
        }
        __syncthreads();
    }

    float* Cb = C + (size_t)bz * cStride;
    #pragma unroll
    for (int gi = 0; gi < 2; gi++)
        #pragma unroll
        for (int ii = 0; ii < 4; ii++) {
            int r = bm * 128 + gi * 64 + ty * 4 + ii;
            #pragma unroll
            for (int gj = 0; gj < 2; gj++) {
                int cb = bn * 128 + gj * 64 + tx * 4;
                float4 o;
                o.x = acc[gi * 4 + ii][gj * 4 + 0];
                o.y = acc[gi * 4 + ii][gj * 4 + 1];
                o.z = acc[gi * 4 + ii][gj * 4 + 2];
                o.w = acc[gi * 4 + ii][gj * 4 + 3];
                *(float4*)(Cb + (size_t)r * N + cb) = o;
            }
        }
}

// ---------------------------------------------------------------------------
// Kernel: prep_small2 — warp-per-row dots
// ---------------------------------------------------------------------------
__global__ __launch_bounds__(256) void prep_small2_kernel(
    const float* __restrict__ Wq, const float* __restrict__ bq)
{
    int gw = blockIdx.x * 8 + (threadIdx.x >> 5);
    int lane = threadIdx.x & 31;
    if (gw > 1536) return;
    const float4* bp = (const float4*)bq;
    float s = 0.f;
    if (gw < 1024) {
        const float4* kr = (const float4*)(g_keyt + (size_t)gw * TDIM);
        #pragma unroll
        for (int i = 0; i < 6; i++) {
            float4 a = kr[lane + 32 * i], c = bp[lane + 32 * i];
            s += a.x * c.x + a.y * c.y + a.z * c.z + a.w * c.w;
        }
        #pragma unroll
        for (int o = 16; o; o >>= 1) s += __shfl_xor_sync(0xffffffffu, s, o);
        if (!lane) g_pb[gw] = s;
    } else if (gw < 1536) {
        int c = gw - 1024;
        const float4* wr = (const float4*)(Wq + (size_t)c * TDIM);
        #pragma unroll
        for (int i = 0; i < 6; i++) {
            float4 a = wr[lane + 32 * i], d = bp[lane + 32 * i];
            s += a.x * d.x + a.y * d.y + a.z * d.z + a.w * d.w;
        }
        #pragma unroll
        for (int o = 16; o; o >>= 1) s += __shfl_xor_sync(0xffffffffu, s, o);
        if (!lane) g_wb2[c] = 2.0f * s;
    } else {
        #pragma unroll
        for (int i = 0; i < 6; i++) {
            float4 a = bp[lane + 32 * i];
            s += a.x * a.x + a.y * a.y + a.z * a.z + a.w * a.w;
        }
        #pragma unroll
        for (int o = 16; o; o >>= 1) s += __shfl_xor_sync(0xffffffffu, s, o);
        if (!lane) g_nb2[0] = s;
    }
}

// ---------------------------------------------------------------------------
// Kernel: convert fp32 B [K][N] -> fp16 hi/lo planes [N][K/2], scaled x256
// ---------------------------------------------------------------------------
__global__ __launch_bounds__(256) void convert_b_kernel(
    const float* __restrict__ in, uint32_t* __restrict__ oh,
    uint32_t* __restrict__ ol, int Kd, int N)
{
    __shared__ float t[64][65];
    int k0 = blockIdx.y * 64, n0 = blockIdx.x * 64;
    int tid = threadIdx.x;
    #pragma unroll
    for (int i = 0; i < 16; i++) {
        int lin = tid + 256 * i;
        int r = lin >> 6, c = lin & 63;
        t[r][c] = in[(size_t)(k0 + r) * N + n0 + c];
    }
    __syncthreads();
    int K2 = Kd >> 1;
    #pragma unroll
    for (int i = 0; i < 8; i++) {
        int lin = tid + 256 * i;
        int n = lin >> 5, kp = lin & 31;
        uint32_t h, l;
        wsplit2(t[2 * kp][n], t[2 * kp + 1][n], h, l);
        size_t o = (size_t)(n0 + n) * K2 + (k0 >> 1) + kp;
        oh[o] = h;  ol[o] = l;
    }
}

// ---------------------------------------------------------------------------
// Kernel: LayerNorm -> fp32 + fp16 plane
// ---------------------------------------------------------------------------
__global__ __launch_bounds__(256) void ln_kernel(
    const float* __restrict__ in, const float* __restrict__ g,
    const float* __restrict__ be, float* __restrict__ out,
    uint32_t* __restrict__ oh)
{
    int warp = threadIdx.x >> 5, lane = threadIdx.x & 31;
    size_t row = (size_t)blockIdx.x * 8 + warp;
    const float4* p = (const float4*)(in + row * CDIM);
    float4 x[4];
    float s = 0.f, s2 = 0.f;
    #pragma unroll
    for (int i = 0; i < 4; i++) {
        x[i] = p[lane + 32 * i];
        s  += x[i].x + x[i].y + x[i].z + x[i].w;
        s2 += x[i].x * x[i].x + x[i].y * x[i].y + x[i].z * x[i].z + x[i].w * x[i].w;
    }
    #pragma unroll
    for (int o = 16; o; o >>= 1) {
        s  += __shfl_xor_sync(0xffffffffu, s, o);
        s2 += __shfl_xor_sync(0xffffffffu, s2, o);
    }
    float mu  = s * (1.0f / CDIM);
    float var = s2 * (1.0f / CDIM) - mu * mu;
    float rs  = rsqrtf(var + LN_EPS);
    float4* o4 = (float4*)(out + row * CDIM);
    const float4* gp = (const float4*)g;
    const float4* bp = (const float4*)be;
    #pragma unroll
    for (int i = 0; i < 4; i++) {
        int c4 = lane + 32 * i;
        float4 gv = gp[c4], bv = bp[c4], r;
        r.x = (x[i].x - mu) * rs * gv.x + bv.x;
        r.y = (x[i].y - mu) * rs * gv.y + bv.y;
        r.z = (x[i].z - mu) * rs * gv.z + bv.z;
        r.w = (x[i].w - mu) * rs * gv.w + bv.w;
        o4[c4] = r;
        uint2 h;
        h.x = packh2(r.x, r.y);
        h.y = packh2(r.z, r.w);
        *(uint2*)(oh + row * (CDIM / 2) + 2 * c4) = h;
    }
}

// ---------------------------------------------------------------------------
// fp16 2-product tensor-core GEMM: D = Ah @ (Bh + Bl), B pre-scaled x256.
// A: fp16 plane [M][K/2] u32; B: fp16 hi/lo planes [N][K/2] u32.
// cp.async double-buffered; fragments via ldmatrix (stride-20 rows conflict-free).
// MODE 1: gelu(acc/256+bias) -> fp16 plane Oh
// MODE 2: acc/256+bias+Res -> Out fp32
// MODE 3: qn2[r] += sum_c (acc/256)[r,c]*(2*Res - fp16(Res))[r,c] + bias[c]*Res[r,c]
// ---------------------------------------------------------------------------
#define PLANE 2560           // 128 rows * 20 u32
#define STAGE (3 * PLANE)    // As, BsH, BsL

template <int MODE>
__global__ __launch_bounds__(256) void tgemm3_kernel(
    const uint32_t* __restrict__ Ah,
    const uint32_t* __restrict__ Bh, const uint32_t* __restrict__ Bl,
    const float* __restrict__ bias, const float* __restrict__ Res,
    float* __restrict__ Out, uint32_t* __restrict__ Oh,
    int M, int N, int Kd)
{
    extern __shared__ uint32_t sm[];
    uint32_t sbase = smem_u32(sm);
    int K2 = Kd >> 1;
    int tid = threadIdx.x, lane = tid & 31, warp = tid >> 5;
    int g  = lane >> 2, tg = lane & 3;
    int wm = warp >> 2, wn = warp & 3;
    int m0 = wm * 64,  n0 = wn * 32;
    int bn = blockIdx.x, bm = blockIdx.y;

    const uint32_t* AhB = Ah + (size_t)bm * 128 * K2;
    const uint32_t* BhB = Bh + (size_t)bn * 128 * K2;
    const uint32_t* BlB = Bl + (size_t)bn * 128 * K2;

    int lrow0 = tid >> 2, lkb = (tid & 3) * 4;

    // ldmatrix per-lane byte offsets within a plane (stride 20 u32 = 80 B)
    uint32_t a_ld = (uint32_t)((m0 + (lane & 7) + ((lane >> 3) & 1) * 8) * 20
                               + ((lane >> 4) & 1) * 4) * 4;
    uint32_t b_ld = (uint32_t)((n0 + (lane & 7) + ((lane >> 4) & 1) * 8) * 20
                               + ((lane >> 3) & 1) * 4) * 4;

    float acc[4][4][4];
    #pragma unroll
    for (int mi = 0; mi < 4; mi++)
        #pragma unroll
        for (int ni = 0; ni < 4; ni++)
            #pragma unroll
            for (int r = 0; r < 4; r++) acc[mi][ni][r] = 0.f;

    int nT = K2 / 16;

    // prologue: prefetch tiles 0 and 1
    #pragma unroll
    for (int pf = 0; pf < 2; pf++) {
        uint32_t* st = sm + pf * STAGE;
        int kp0 = pf * 16;
        #pragma unroll
        for (int c = 0; c < 2; c++) {
            int row = lrow0 + 64 * c;
            size_t go = (size_t)row * K2 + kp0 + lkb;
            int so = row * 20 + lkb;
            cp16(st + so,             AhB + go);
            cp16(st + PLANE + so,     BhB + go);
            cp16(st + 2 * PLANE + so, BlB + go);
        }
        cp_commit();
    }

    for (int t = 0; t < nT; t++) {
        cp_wait1();
        __syncthreads();
        uint32_t stb = sbase + (uint32_t)((t & 1) * STAGE * 4);

        #pragma unroll
        for (int ks = 0; ks < 2; ks++) {
            uint32_t ksoff = (uint32_t)(ks * 32);
            uint32_t a[4][4], bh[4][2], bl[4][2];
            #pragma unroll
            for (int mi = 0; mi < 4; mi++) {
                uint32_t ao = stb + a_ld + ksoff + (uint32_t)(mi * 16 * 80);
                ldsm_x4(a[mi][0], a[mi][1], a[mi][2], a[mi][3], ao);
            }
            #pragma unroll
            for (int p = 0; p < 2; p++) {
                uint32_t bo = stb + PLANE * 4 + b_ld + ksoff + (uint32_t)(p * 16 * 80);
                ldsm_x4(bh[2 * p][0], bh[2 * p][1], bh[2 * p + 1][0], bh[2 * p + 1][1], bo);
                ldsm_x4(bl[2 * p][0], bl[2 * p][1], bl[2 * p + 1][0], bl[2 * p + 1][1],
                        bo + PLANE * 4);
            }
            #pragma unroll
            for (int mi = 0; mi < 4; mi++)
                #pragma unroll
                for (int ni = 0; ni < 4; ni++) {
                    mma_f16(acc[mi][ni], a[mi], bh[ni]);
                    mma_f16(acc[mi][ni], a[mi], bl[ni]);
                }
        }
        __syncthreads();
        if (t + 2 < nT) {
            uint32_t* dst = sm + (t & 1) * STAGE;
            int kp0 = (t + 2) * 16;
            #pragma unroll
            for (int c = 0; c < 2; c++) {
                int row = lrow0 + 64 * c;
                size_t go = (size_t)row * K2 + kp0 + lkb;
                int so = row * 20 + lkb;
                cp16(dst + so,             AhB + go);
                cp16(dst + PLANE + so,     BhB + go);
                cp16(dst + 2 * PLANE + so, BlB + go);
            }
        }
        cp_commit();
    }

    if (MODE == 3) {
        #pragma unroll
        for (int mi = 0; mi < 4; mi++)
            #pragma unroll
            for (int half = 0; half < 2; half++) {
                int r = bm * 128 + m0 + mi * 16 + g + half * 8;
                float part = 0.f;
                #pragma unroll
                for (int ni = 0; ni < 4; ni++) {
                    int c = bn * 128 + n0 + ni * 8 + 2 * tg;
                    #pragma unroll
                    for (int jj = 0; jj < 2; jj++) {
                        float rv = Res[(size_t)r * N + c + jj];
                        float vh = __half2float(__float2half_rn(rv));
                        float z  = acc[mi][ni][half * 2 + jj] * WINV;
                        part += z * (2.0f * rv - vh) + bias[c + jj] * rv;
                    }
                }
                part += __shfl_xor_sync(0xffffffffu, part, 1);
                part += __shfl_xor_sync(0xffffffffu, part, 2);
                if (tg == 0) atomicAdd(&g_qn2[r], part);
            }
        return;
    }

    #pragma unroll
    for (int mi = 0; mi < 4; mi++)
        #pragma unroll
        for (int half = 0; half < 2; half++) {
            int r = bm * 128 + m0 + mi * 16 + g + half * 8;
            #pragma unroll
            for (int ni = 0; ni < 4; ni++) {
                int c = bn * 128 + n0 + ni * 8 + 2 * tg;
                float v0 = acc[mi][ni][half * 2 + 0] * WINV + bias[c];
                float v1 = acc[mi][ni][half * 2 + 1] * WINV + bias[c + 1];
                if (MODE == 1) {
                    v0 = v0 * normcdff(v0);
                    v1 = v1 * normcdff(v1);
                    Oh[(size_t)r * (N >> 1) + (c >> 1)] = packh2(v0, v1);
                } else {
                    v0 += Res[(size_t)r * N + c];
                    v1 += Res[(size_t)r * N + c + 1];
                    float2 ov = { v0, v1 };
                    *(float2*)(Out + (size_t)r * N + c) = ov;
                }
            }
        }
}

// ---------------------------------------------------------------------------
// Attention core (proven since R5); X written fp32 + fp16 plane
// ---------------------------------------------------------------------------
__global__ __launch_bounds__(256) void attn_kernel(
    const float* __restrict__ resid, const float* __restrict__ g2,
    const float* __restrict__ be2)
{
    __shared__ float qs[16][32];
    __shared__ float ks2[32][128];
    __shared__ float simbuf[16][128];
    __shared__ float invn[16];
    __shared__ float pb_s[KTXT];
    int tid = threadIdx.x, lane = tid & 31, warp = tid >> 5;
    int t0 = blockIdx.x * 16;
    int b  = t0 >> 12;

    if (tid < 16) {
        float qn2 = g_qn2[t0 + tid] + g_nb2[0];
        float n = sqrtf(fmaxf(qn2, 0.f));
        invn[tid] = 1.0f / fmaxf(n, 1e-12f);
    }
    if (tid < KTXT) pb_s[tid] = g_pb[b * KTXT + tid];
    __syncthreads();

    float acc[2][4] = {};
    const float* Pb = g_P + (size_t)b * CDIM * KTXT;
    for (int kk = 0; kk < CDIM; kk += 32) {
        {
            int idx = tid * 2;
            int qr_ = idx >> 5, qc = idx & 31;
            const float* qp = g_visln + (size_t)(t0 + qr_) * CDIM + kk + qc;
            qs[qr_][qc]     = qp[0];
            qs[qr_][qc + 1] = qp[1];
        }
        #pragma unroll
        for (int i = 0; i < 16; i++) {
            int lin = tid + 256 * i;
            int cc = lin >> 7, col = lin & 127;
            ks2[cc][col] = Pb[(size_t)(kk + cc) * KTXT + col];
        }
        __syncthreads();
        #pragma unroll
        for (int k = 0; k < 32; k++) {
            float q0 = qs[warp][k], q1 = qs[warp + 8][k];
            #pragma unroll
            for (int j = 0; j < 4; j++) {
                float kv = ks2[k][lane + 32 * j];
                acc[0][j] += q0 * kv;
                acc[1][j] += q1 * kv;
            }
        }
        __syncthreads();
    }
    #pragma unroll
    for (int j = 0; j < 4; j++) {
        simbuf[warp][lane + 32 * j]     = acc[0][j];
        simbuf[warp + 8][lane + 32 * j] = acc[1][j];
    }
    __syncthreads();

    for (int rr = 0; rr < 2; rr++) {
        int row = warp * 2 + rr;
        float sc = invn[row];
        float tv[4];
        #pragma unroll
        for (int j = 0; j < 4; j++) {
            int col = lane + 32 * j;
            tv[j] = (simbuf[row][col] + pb_s[col]) * sc;
        }

        float mval[TOPM]; int midx[TOPM];
        #pragma unroll
        for (int it = 0; it < TOPM; it++) {
            float lm = tv[0]; int lj = 0;
            #pragma unroll
            for (int j = 1; j < 4; j++) if (tv[j] > lm) { lm = tv[j]; lj = j; }
            int li = lane + 32 * lj;
            #pragma unroll
            for (int o = 16; o; o >>= 1) {
                float ov = __shfl_xor_sync(0xffffffffu, lm, o);
                int   oi = __shfl_xor_sync(0xffffffffu, li, o);
                if (ov > lm || (ov == lm && oi < li)) { lm = ov; li = oi; }
            }
            mval[it] = lm; midx[it] = li;
            if ((li & 31) == lane) tv[li >> 5] = -INFINITY;
        }

        float p[TOPM], psum = 0.f;
        #pragma unroll
        for (int it = 0; it < TOPM; it++) {
            p[it] = expf((mval[it] - mval[0]) * TEMP_INV);
            psum += p[it];
        }
        float rnorm = 1.0f / psum;

        float f[16];
        #pragma unroll
        for (int i = 0; i < 16; i++) f[i] = 0.f;
        const float* Vb = g_value + (size_t)b * KTXT * CDIM;
        #pragma unroll
        for (int it = 0; it < TOPM; it++) {
            const float4* vr = (const float4*)(Vb + (size_t)midx[it] * CDIM + lane * 16);
            float a_ = p[it] * rnorm;
            #pragma unroll
            for (int j = 0; j < 4; j++) {
                float4 v = vr[j];
                f[4 * j + 0] += a_ * v.x;
                f[4 * j + 1] += a_ * v.y;
                f[4 * j + 2] += a_ * v.z;
                f[4 * j + 3] += a_ * v.w;
            }
        }

        const float4* rp = (const float4*)(resid + (size_t)(t0 + row) * CDIM + lane * 16);
        float s = 0.f, s2 = 0.f;
        #pragma unroll
        for (int j = 0; j < 4; j++) {
            float4 v = rp[j];
            f[4 * j + 0] += v.x;  f[4 * j + 1] += v.y;
            f[4 * j + 2] += v.z;  f[4 * j + 3] += v.w;
        }
        #pragma unroll
        for (int i = 0; i < 16; i++) { s += f[i]; s2 += f[i] * f[i]; }
        #pragma unroll
        for (int o = 16; o; o >>= 1) {
            s  += __shfl_xor_sync(0xffffffffu, s, o);
            s2 += __shfl_xor_sync(0xffffffffu, s2, o);
        }
        float mu  = s * (1.0f / CDIM);
        float var = s2 * (1.0f / CDIM) - mu * mu;
        float rstd = rsqrtf(var + LN_EPS);

        size_t rbase = (size_t)(t0 + row);
        float*    xp = g_X  + rbase * CDIM + lane * 16;
        uint32_t* xh = g_Xh + rbase * (CDIM / 2) + lane * 8;
        #pragma unroll
        for (int j = 0; j < 4; j++) {
            int c = lane * 16 + 4 * j;
            float4 o;
            o.x = (f[4 * j + 0] - mu) * rstd * g2[c + 0] + be2[c + 0];
            o.y = (f[4 * j + 1] - mu) * rstd * g2[c + 1] + be2[c + 1];
            o.z = (f[4 * j + 2] - mu) * rstd * g2[c + 2] + be2[c + 2];
            o.w = (f[4 * j + 3] - mu) * rstd * g2[c + 3] + be2[c + 3];
            *(float4*)(xp + 4 * j) = o;
            uint2 h;
            h.x = packh2(o.x, o.y);
            h.y = packh2(o.z, o.w);
            *(uint2*)(xh + 2 * j) = h;
        }
    }
}

// ---------------------------------------------------------------------------
// Launch
// ---------------------------------------------------------------------------
extern "C" void kernel_launch(void* const* d_in, const int* in_sizes, int n_in,
                              void* d_out, int out_size)
{
    const float* vis  = (const float*)d_in[0];
    const float* text = (const float*)d_in[1];
    const float* Wq   = (const float*)d_in[2];
    const float* bq   = (const float*)d_in[3];
    const float* Wv   = (const float*)d_in[4];
    const float* bv   = (const float*)d_in[5];
    const float* W1   = (const float*)d_in[6];
    const float* b1   = (const float*)d_in[7];
    const float* W2   = (const float*)d_in[8];
    const float* b2   = (const float*)d_in[9];
    const float* g1   = (const float*)d_in[10];
    const float* be1  = (const float*)d_in[11];
    const float* g2   = (const float*)d_in[12];
    const float* be2  = (const float*)d_in[13];
    float* out = (float*)d_out;

    float *p_visln, *p_X, *p_P, *p_G, *p_keyt, *p_wb2, *p_qn2;
    uint32_t *p_vh, *p_Xh, *p_Hh;
    uint32_t *p_Gh, *p_Gl, *p_W1h, *p_W1l, *p_W2h, *p_W2l;
    cudaGetSymbolAddress((void**)&p_visln, g_visln);
    cudaGetSymbolAddress((void**)&p_X,     g_X);
    cudaGetSymbolAddress((void**)&p_P,     g_P);
    cudaGetSymbolAddress((void**)&p_G,     g_G);
    cudaGetSymbolAddress((void**)&p_keyt,  g_keyt);
    cudaGetSymbolAddress((void**)&p_wb2,   g_wb2);
    cudaGetSymbolAddress((void**)&p_qn2,   g_qn2);
    cudaGetSymbolAddress((void**)&p_vh,    g_vh);
    cudaGetSymbolAddress((void**)&p_Xh,    g_Xh);
    cudaGetSymbolAddress((void**)&p_Hh,    g_Hh);
    cudaGetSymbolAddress((void**)&p_Gh,    g_Gh);
    cudaGetSymbolAddress((void**)&p_Gl,    g_Gl);
    cudaGetSymbolAddress((void**)&p_W1h,   g_W1h);
    cudaGetSymbolAddress((void**)&p_W1l,   g_W1l);
    cudaGetSymbolAddress((void**)&p_W2h,   g_W2h);
    cudaGetSymbolAddress((void**)&p_W2l,   g_W2l);

    const int SMEM = 2 * STAGE * 4;   // 61440 B
    cudaFuncSetAttribute(tgemm3_kernel<1>, cudaFuncAttributeMaxDynamicSharedMemorySize, SMEM);
    cudaFuncSetAttribute(tgemm3_kernel<2>, cudaFuncAttributeMaxDynamicSharedMemorySize, SMEM);
    cudaFuncSetAttribute(tgemm3_kernel<3>, cudaFuncAttributeMaxDynamicSharedMemorySize, SMEM);

    // 1) text prep (keyt, value)
    prep_text_kernel<<<(BQ * KTXT) / 8, 256>>>(text, Wv, bv);
    // 2) P_b = Wq @ keyt_b^T per batch (fp32)
    sgemm_tn_kernel<<<dim3(1, CDIM / 128, BQ), 256>>>(
        Wq, p_keyt, p_P, TDIM, KTXT,
        0, (size_t)KTXT * TDIM, (size_t)CDIM * KTXT);
    // 3) G = Wq @ Wq^T (fp32)
    sgemm_tn_kernel<<<dim3(CDIM / 128, CDIM / 128, 1), 256>>>(
        Wq, Wq, p_G, TDIM, CDIM, 0, 0, 0);
    // 4) pb, wb2, nb2
    prep_small2_kernel<<<193, 256>>>(Wq, bq);
    // 5) convert weights to fp16 hi/lo planes (x256)
    convert_b_kernel<<<dim3(CDIM / 64, CDIM / 64), 256>>>(p_G, p_Gh, p_Gl, CDIM, CDIM);
    convert_b_kernel<<<dim3(HID / 64, CDIM / 64), 256>>>(W1, p_W1h, p_W1l, CDIM, HID);
    convert_b_kernel<<<dim3(CDIM / 64, HID / 64), 256>>>(W2, p_W2h, p_W2l, HID, CDIM);
    // 6) LN1 -> visln fp32 + vh fp16
    ln_kernel<<<MTOT / 8, 256>>>(vis, g1, be1, p_visln, p_vh);
    // 7) qn2 = vh@G dotted with (2v - vh) + wb2.v  (exact to ~2^-24)
    cudaMemsetAsync(p_qn2, 0, MTOT * sizeof(float));
    tgemm3_kernel<3><<<dim3(CDIM / 128, MTOT / 128), 256, SMEM>>>(
        p_vh, p_Gh, p_Gl, p_wb2, p_visln, nullptr, nullptr,
        MTOT, CDIM, CDIM);
    // 8) attention + residual + LN2 -> X fp32 + Xh fp16
    attn_kernel<<<MTOT / 16, 256>>>(vis, g2, be2);
    // 9) H = gelu(X @ W1 + b1) -> fp16 plane Hh
    tgemm3_kernel<1><<<dim3(HID / 128, MTOT / 128), 256, SMEM>>>(
        p_Xh, p_W1h, p_W1l, b1, nullptr, nullptr, p_Hh,
        MTOT, HID, CDIM);
    // 10) out = X + H @ W2 + b2
    tgemm3_kernel<2><<<dim3(CDIM / 128, MTOT / 128), 256, SMEM>>>(
        p_Hh, p_W2h, p_W2l, b2, p_X, out, nullptr,
        MTOT, CDIM, HID);
}

// round 10
// speedup vs baseline: 1.5233x; 1.0196x over previous
#include <cuda_runtime.h>
#include <cuda_fp16.h>
#include <math.h>
#include <stdint.h>

// ---------------------------------------------------------------------------
// Problem constants
// ---------------------------------------------------------------------------
#define BQ    8
#define MTOT  32768
#define CDIM  512
#define TDIM  768
#define KTXT  128
#define HID   2048
#define TOPM  5
#define TEMP_INV (1.0f/0.07f)
#define LN_EPS 1e-5f
#define WSCALE 256.0f
#define WINV   (1.0f/256.0f)

// ---------------------------------------------------------------------------
// Scratch (device globals)
// ---------------------------------------------------------------------------
static __device__ float    g_visln[MTOT * CDIM];
static __device__ uint32_t g_vh[MTOT * CDIM / 2];
static __device__ float    g_X [MTOT * CDIM];
static __device__ uint32_t g_Xh[MTOT * CDIM / 2];
static __device__ uint32_t g_Hh[(size_t)MTOT * HID / 2];
static __device__ float    g_keyt [BQ * KTXT * TDIM];
static __device__ float    g_value[BQ * KTXT * CDIM];
static __device__ float    g_P [BQ * CDIM * KTXT];
static __device__ float    g_G [CDIM * CDIM];
static __device__ uint32_t g_Gh [CDIM * CDIM / 2];
static __device__ uint32_t g_Gl [CDIM * CDIM / 2];
static __device__ uint32_t g_W1h[(size_t)HID * CDIM / 2];
static __device__ uint32_t g_W1l[(size_t)HID * CDIM / 2];
static __device__ uint32_t g_W2h[(size_t)CDIM * HID / 2];
static __device__ uint32_t g_W2l[(size_t)CDIM * HID / 2];
static __device__ float    g_pb [BQ * KTXT];
static __device__ float    g_wb2[CDIM];
static __device__ float    g_nb2[1];
static __device__ float    g_qn2[MTOT];

// ---------------------------------------------------------------------------
// Helpers
// ---------------------------------------------------------------------------
__device__ __forceinline__ uint32_t packh2(float x, float y) {
    __half2 h = __floats2half2_rn(x, y);
    return *reinterpret_cast<uint32_t*>(&h);
}

__device__ __forceinline__ void wsplit2(float x, float y,
                                        uint32_t& hi, uint32_t& lo) {
    float sx = x * WSCALE, sy = y * WSCALE;
    __half hx = __float2half_rn(sx);
    __half hy = __float2half_rn(sy);
    float rx = sx - __half2float(hx);
    float ry = sy - __half2float(hy);
    __half2 h2 = __halves2half2(hx, hy);
    __half2 l2 = __floats2half2_rn(rx, ry);
    hi = *reinterpret_cast<uint32_t*>(&h2);
    lo = *reinterpret_cast<uint32_t*>(&l2);
}

__device__ __forceinline__ void mma_f16(float* c, const uint32_t* a, const uint32_t* b) {
    asm volatile(
        "mma.sync.aligned.m16n8k16.row.col.f32.f16.f16.f32 "
        "{%0,%1,%2,%3}, {%4,%5,%6,%7}, {%8,%9}, {%0,%1,%2,%3};\n"
        : "+f"(c[0]), "+f"(c[1]), "+f"(c[2]), "+f"(c[3])
        : "r"(a[0]), "r"(a[1]), "r"(a[2]), "r"(a[3]), "r"(b[0]), "r"(b[1]));
}

__device__ __forceinline__ uint32_t smem_u32(const void* p) {
    uint32_t a;
    asm("{ .reg .u64 t; cvta.to.shared.u64 t, %1; cvt.u32.u64 %0, t; }"
        : "=r"(a) : "l"(p));
    return a;
}

__device__ __forceinline__ void ldsm_x4(uint32_t& r0, uint32_t& r1,
                                        uint32_t& r2, uint32_t& r3,
                                        uint32_t addr) {
    asm volatile(
        "ldmatrix.sync.aligned.m8n8.x4.shared.b16 {%0,%1,%2,%3}, [%4];"
        : "=r"(r0), "=r"(r1), "=r"(r2), "=r"(r3) : "r"(addr));
}

__device__ __forceinline__ void cp16(uint32_t* dst_smem, const uint32_t* src) {
    uint32_t s = (uint32_t)__cvta_generic_to_shared(dst_smem);
    asm volatile("cp.async.cg.shared.global [%0], [%1], 16;\n" :: "r"(s), "l"(src));
}
__device__ __forceinline__ void cp_commit() {
    asm volatile("cp.async.commit_group;\n");
}
__device__ __forceinline__ void cp_wait1() {
    asm volatile("cp.async.wait_group 1;\n");
}

// ---------------------------------------------------------------------------
// Kernel: text prep — keyt = l2norm(text), value = text @ Wv + bv
// ---------------------------------------------------------------------------
__global__ __launch_bounds__(256) void prep_text_kernel(
    const float* __restrict__ text, const float* __restrict__ Wv,
    const float* __restrict__ bv)
{
    __shared__ float ts[8][TDIM];
    int tid = threadIdx.x, lane = tid & 31, warp = tid >> 5;
    int b  = blockIdx.x >> 4;
    int kb = (blockIdx.x & 15) * 8;
    const float* tb = text + ((size_t)b * KTXT + kb) * TDIM;

    #pragma unroll
    for (int i = 0; i < 24; i++) {
        int lin = tid + 256 * i;
        int r = lin / TDIM, c = lin % TDIM;
        ts[r][c] = tb[(size_t)r * TDIM + c];
    }
    __syncthreads();

    {
        int r = warp;
        float s = 0.f;
        for (int i = lane; i < TDIM; i += 32) { float v = ts[r][i]; s += v * v; }
        #pragma unroll
        for (int o = 16; o; o >>= 1) s += __shfl_xor_sync(0xffffffffu, s, o);
        float inv = 1.0f / fmaxf(sqrtf(s), 1e-12f);
        float* kr = g_keyt + ((size_t)b * KTXT + kb + r) * TDIM;
        for (int i = lane; i < TDIM; i += 32) kr[i] = ts[r][i] * inv;
    }

    float acc[8][2];
    #pragma unroll
    for (int r = 0; r < 8; r++) { acc[r][0] = 0.f; acc[r][1] = 0.f; }
    int c0 = tid, c1 = tid + 256;
    for (int t = 0; t < TDIM; t++) {
        float w0 = Wv[(size_t)t * CDIM + c0];
        float w1 = Wv[(size_t)t * CDIM + c1];
        #pragma unroll
        for (int r = 0; r < 8; r++) {
            float tv = ts[r][t];
            acc[r][0] += tv * w0;
            acc[r][1] += tv * w1;
        }
    }
    float bb0 = bv[c0], bb1 = bv[c1];
    #pragma unroll
    for (int r = 0; r < 8; r++) {
        float* vr = g_value + ((size_t)b * KTXT + kb + r) * CDIM;
        vr[c0] = acc[r][0] + bb0;
        vr[c1] = acc[r][1] + bb1;
    }
}

// ---------------------------------------------------------------------------
// Kernel: small fp32 SGEMM  C[M,N] = A[M,K] @ B2[N,K]^T  (for P and G)
// ---------------------------------------------------------------------------
__global__ __launch_bounds__(256) void sgemm_tn_kernel(
    const float* __restrict__ A, const float* __restrict__ B2,
    float* __restrict__ C, int Kd, int N,
    size_t aStride, size_t bStride, size_t cStride)
{
    __shared__ float As[8][128];
    __shared__ float Bs[8][128];
    int tid = threadIdx.x;
    int tx = tid & 15, ty = tid >> 4;
    int bn = blockIdx.x, bm = blockIdx.y, bz = blockIdx.z;
    const float* Ab = A  + (size_t)bz * aStride + (size_t)bm * 128 * Kd;
    const float* Bb = B2 + (size_t)bz * bStride + (size_t)bn * 128 * Kd;
    int l_r = tid >> 1, l_k = (tid & 1) * 4;

    float acc[8][8];
    #pragma unroll
    for (int i = 0; i < 8; i++)
        #pragma unroll
        for (int j = 0; j < 8; j++) acc[i][j] = 0.f;

    for (int k0 = 0; k0 < Kd; k0 += 8) {
        float4 av = *(const float4*)(Ab + (size_t)l_r * Kd + k0 + l_k);
        As[l_k + 0][l_r] = av.x;
        As[l_k + 1][l_r] = av.y;
        As[l_k + 2][l_r] = av.z;
        As[l_k + 3][l_r] = av.w;
        float4 bv = *(const float4*)(Bb + (size_t)l_r * Kd + k0 + l_k);
        Bs[l_k + 0][l_r] = bv.x;
        Bs[l_k + 1][l_r] = bv.y;
        Bs[l_k + 2][l_r] = bv.z;
        Bs[l_k + 3][l_r] = bv.w;
        __syncthreads();
        #pragma unroll
        for (int k = 0; k < 8; k++) {
            float ar[8], br[8];
            #pragma unroll
            for (int i = 0; i < 4; i++) {
                ar[i]     = As[k][ty * 4 + i];
                ar[4 + i] = As[k][64 + ty * 4 + i];
                br[i]     = Bs[k][tx * 4 + i];
                br[4 + i] = Bs[k][64 + tx * 4 + i];
            }
            #pragma unroll
            for (int i = 0; i < 8; i++)
                #pragma unroll
                for (int j = 0; j < 8; j++) acc[i][j] += ar[i] * br[j];
        }
        __syncthreads();
    }

    float* Cb = C + (size_t)bz * cStride;
    #pragma unroll
    for (int gi = 0; gi < 2; gi++)
        #pragma unroll
        for (int ii = 0; ii < 4; ii++) {
            int r = bm * 128 + gi * 64 + ty * 4 + ii;
            #pragma unroll
            for (int gj = 0; gj < 2; gj++) {
                int cb = bn * 128 + gj * 64 + tx * 4;
                float4 o;
                o.x = acc[gi * 4 + ii][gj * 4 + 0];
                o.y = acc[gi * 4 + ii][gj * 4 + 1];
                o.z = acc[gi * 4 + ii][gj * 4 + 2];
                o.w = acc[gi * 4 + ii][gj * 4 + 3];
                *(float4*)(Cb + (size_t)r * N + cb) = o;
            }
        }
}

// ---------------------------------------------------------------------------
// Kernel: prep_small2 — warp-per-row dots
// ---------------------------------------------------------------------------
__global__ __launch_bounds__(256) void prep_small2_kernel(
    const float* __restrict__ Wq, const float* __restrict__ bq)
{
    int gw = blockIdx.x * 8 + (threadIdx.x >> 5);
    int lane = threadIdx.x & 31;
    if (gw > 1536) return;
    const float4* bp = (const float4*)bq;
    float s = 0.f;
    if (gw < 1024) {
        const float4* kr = (const float4*)(g_keyt + (size_t)gw * TDIM);
        #pragma unroll
        for (int i = 0; i < 6; i++) {
            float4 a = kr[lane + 32 * i], c = bp[lane + 32 * i];
            s += a.x * c.x + a.y * c.y + a.z * c.z + a.w * c.w;
        }
        #pragma unroll
        for (int o = 16; o; o >>= 1) s += __shfl_xor_sync(0xffffffffu, s, o);
        if (!lane) g_pb[gw] = s;
    } else if (gw < 1536) {
        int c = gw - 1024;
        const float4* wr = (const float4*)(Wq + (size_t)c * TDIM);
        #pragma unroll
        for (int i = 0; i < 6; i++) {
            float4 a = wr[lane + 32 * i], d = bp[lane + 32 * i];
            s += a.x * d.x + a.y * d.y + a.z * d.z + a.w * d.w;
        }
        #pragma unroll
        for (int o = 16; o; o >>= 1) s += __shfl_xor_sync(0xffffffffu, s, o);
        if (!lane) g_wb2[c] = 2.0f * s;
    } else {
        #pragma unroll
        for (int i = 0; i < 6; i++) {
            float4 a = bp[lane + 32 * i];
            s += a.x * a.x + a.y * a.y + a.z * a.z + a.w * a.w;
        }
        #pragma unroll
        for (int o = 16; o; o >>= 1) s += __shfl_xor_sync(0xffffffffu, s, o);
        if (!lane) g_nb2[0] = s;
    }
}

// ---------------------------------------------------------------------------
// Kernel: convert fp32 B [K][N] -> fp16 hi/lo planes [N][K/2], scaled x256
// ---------------------------------------------------------------------------
__global__ __launch_bounds__(256) void convert_b_kernel(
    const float* __restrict__ in, uint32_t* __restrict__ oh,
    uint32_t* __restrict__ ol, int Kd, int N)
{
    __shared__ float t[64][65];
    int k0 = blockIdx.y * 64, n0 = blockIdx.x * 64;
    int tid = threadIdx.x;
    #pragma unroll
    for (int i = 0; i < 16; i++) {
        int lin = tid + 256 * i;
        int r = lin >> 6, c = lin & 63;
        t[r][c] = in[(size_t)(k0 + r) * N + n0 + c];
    }
    __syncthreads();
    int K2 = Kd >> 1;
    #pragma unroll
    for (int i = 0; i < 8; i++) {
        int lin = tid + 256 * i;
        int n = lin >> 5, kp = lin & 31;
        uint32_t h, l;
        wsplit2(t[2 * kp][n], t[2 * kp + 1][n], h, l);
        size_t o = (size_t)(n0 + n) * K2 + (k0 >> 1) + kp;
        oh[o] = h;  ol[o] = l;
    }
}

// ---------------------------------------------------------------------------
// Kernel: LayerNorm -> fp32 + fp16 plane
// ---------------------------------------------------------------------------
__global__ __launch_bounds__(256) void ln_kernel(
    const float* __restrict__ in, const float* __restrict__ g,
    const float* __restrict__ be, float* __restrict__ out,
    uint32_t* __restrict__ oh)
{
    int warp = threadIdx.x >> 5, lane = threadIdx.x & 31;
    size_t row = (size_t)blockIdx.x * 8 + warp;
    const float4* p = (const float4*)(in + row * CDIM);
    float4 x[4];
    float s = 0.f, s2 = 0.f;
    #pragma unroll
    for (int i = 0; i < 4; i++) {
        x[i] = p[lane + 32 * i];
        s  += x[i].x + x[i].y + x[i].z + x[i].w;
        s2 += x[i].x * x[i].x + x[i].y * x[i].y + x[i].z * x[i].z + x[i].w * x[i].w;
    }
    #pragma unroll
    for (int o = 16; o; o >>= 1) {
        s  += __shfl_xor_sync(0xffffffffu, s, o);
        s2 += __shfl_xor_sync(0xffffffffu, s2, o);
    }
    float mu  = s * (1.0f / CDIM);
    float var = s2 * (1.0f / CDIM) - mu * mu;
    float rs  = rsqrtf(var + LN_EPS);
    float4* o4 = (float4*)(out + row * CDIM);
    const float4* gp = (const float4*)g;
    const float4* bp = (const float4*)be;
    #pragma unroll
    for (int i = 0; i < 4; i++) {
        int c4 = lane + 32 * i;
        float4 gv = gp[c4], bv = bp[c4], r;
        r.x = (x[i].x - mu) * rs * gv.x + bv.x;
        r.y = (x[i].y - mu) * rs * gv.y + bv.y;
        r.z = (x[i].z - mu) * rs * gv.z + bv.z;
        r.w = (x[i].w - mu) * rs * gv.w + bv.w;
        o4[c4] = r;
        uint2 h;
        h.x = packh2(r.x, r.y);
        h.y = packh2(r.z, r.w);
        *(uint2*)(oh + row * (CDIM / 2) + 2 * c4) = h;
    }
}

// ---------------------------------------------------------------------------
// fp16 2-product tensor-core GEMM: D = Ah @ (Bh + Bl), B pre-scaled x256.
// 256x128 block tile, 512 threads = 16 warps (4m x 4n), warp tile 64x32.
// cp.async double-buffered; fragments via ldmatrix (stride-20 conflict-free).
// MODE 1: gelu(acc/256+bias) -> fp16 plane Oh
// MODE 2: acc/256+bias+Res -> Out fp32
// MODE 3: qn2[r] += sum_c (acc/256)*(2*Res - fp16(Res)) + bias*Res
// ---------------------------------------------------------------------------
#define A_PLANE 5120          // 256 rows * 20 u32
#define B_PLANE 2560          // 128 rows * 20 u32
#define STAGE4  (A_PLANE + 2 * B_PLANE)   // 10240 u32 = 40 KB
#define SMEM4   (2 * STAGE4 * 4)          // 81920 B

template <int MODE>
__global__ __launch_bounds__(512) void tgemm4_kernel(
    const uint32_t* __restrict__ Ah,
    const uint32_t* __restrict__ Bh, const uint32_t* __restrict__ Bl,
    const float* __restrict__ bias, const float* __restrict__ Res,
    float* __restrict__ Out, uint32_t* __restrict__ Oh,
    int M, int N, int Kd)
{
    extern __shared__ uint32_t sm[];
    uint32_t sbase = smem_u32(sm);
    int K2 = Kd >> 1;
    int tid = threadIdx.x, lane = tid & 31, warp = tid >> 5;
    int g  = lane >> 2, tg = lane & 3;
    int wm = warp >> 2, wn = warp & 3;          // 4m x 4n
    int m0 = wm * 64,  n0 = wn * 32;
    int bn = blockIdx.x, bm = blockIdx.y;

    const uint32_t* AhB = Ah + (size_t)bm * 256 * K2;
    const uint32_t* BhB = Bh + (size_t)bn * 128 * K2;
    const uint32_t* BlB = Bl + (size_t)bn * 128 * K2;

    // ldmatrix per-lane byte offsets within a plane (stride 20 u32 = 80 B)
    uint32_t a_ld = (uint32_t)((m0 + (lane & 7) + ((lane >> 3) & 1) * 8) * 20
                               + ((lane >> 4) & 1) * 4) * 4;
    uint32_t b_ld = (uint32_t)((n0 + (lane & 7) + ((lane >> 4) & 1) * 8) * 20
                               + ((lane >> 3) & 1) * 4) * 4;

    float acc[4][4][4];
    #pragma unroll
    for (int mi = 0; mi < 4; mi++)
        #pragma unroll
        for (int ni = 0; ni < 4; ni++)
            #pragma unroll
            for (int r = 0; r < 4; r++) acc[mi][ni][r] = 0.f;

    int nT = K2 / 16;

    // stage: A 256x16kp (2 chunks/thread), B 128x16kp per plane (1 chunk/thread)
    // prologue tiles 0 and 1
    #pragma unroll
    for (int pf = 0; pf < 2; pf++) {
        uint32_t* st = sm + pf * STAGE4;
        int kp0 = pf * 16;
        #pragma unroll
        for (int c = 0; c < 2; c++) {
            int idx = tid + 512 * c;
            int row = idx >> 2, kb = (idx & 3) * 4;
            cp16(st + row * 20 + kb, AhB + (size_t)row * K2 + kp0 + kb);
        }
        {
            int row = tid >> 2, kb = (tid & 3) * 4;
            size_t go = (size_t)row * K2 + kp0 + kb;
            int so = row * 20 + kb;
            cp16(st + A_PLANE + so,           BhB + go);
            cp16(st + A_PLANE + B_PLANE + so, BlB + go);
        }
        cp_commit();
    }

    for (int t = 0; t < nT; t++) {
        cp_wait1();
        __syncthreads();
        uint32_t stb = sbase + (uint32_t)((t & 1) * STAGE4 * 4);

        #pragma unroll
        for (int ks = 0; ks < 2; ks++) {
            uint32_t ksoff = (uint32_t)(ks * 32);
            uint32_t a[4][4], bh[4][2], bl[4][2];
            #pragma unroll
            for (int mi = 0; mi < 4; mi++) {
                uint32_t ao = stb + a_ld + ksoff + (uint32_t)(mi * 16 * 80);
                ldsm_x4(a[mi][0], a[mi][1], a[mi][2], a[mi][3], ao);
            }
            #pragma unroll
            for (int p = 0; p < 2; p++) {
                uint32_t bo = stb + A_PLANE * 4 + b_ld + ksoff + (uint32_t)(p * 16 * 80);
                ldsm_x4(bh[2 * p][0], bh[2 * p][1], bh[2 * p + 1][0], bh[2 * p + 1][1], bo);
                ldsm_x4(bl[2 * p][0], bl[2 * p][1], bl[2 * p + 1][0], bl[2 * p + 1][1],
                        bo + B_PLANE * 4);
            }
            #pragma unroll
            for (int mi = 0; mi < 4; mi++)
                #pragma unroll
                for (int ni = 0; ni < 4; ni++) {
                    mma_f16(acc[mi][ni], a[mi], bh[ni]);
                    mma_f16(acc[mi][ni], a[mi], bl[ni]);
                }
        }
        __syncthreads();
        if (t + 2 < nT) {
            uint32_t* dst = sm + (t & 1) * STAGE4;
            int kp0 = (t + 2) * 16;
            #pragma unroll
            for (int c = 0; c < 2; c++) {
                int idx = tid + 512 * c;
                int row = idx >> 2, kb = (idx & 3) * 4;
                cp16(dst + row * 20 + kb, AhB + (size_t)row * K2 + kp0 + kb);
            }
            {
                int row = tid >> 2, kb = (tid & 3) * 4;
                size_t go = (size_t)row * K2 + kp0 + kb;
                int so = row * 20 + kb;
                cp16(dst + A_PLANE + so,           BhB + go);
                cp16(dst + A_PLANE + B_PLANE + so, BlB + go);
            }
        }
        cp_commit();
    }

    if (MODE == 3) {
        #pragma unroll
        for (int mi = 0; mi < 4; mi++)
            #pragma unroll
            for (int half = 0; half < 2; half++) {
                int r = bm * 256 + m0 + mi * 16 + g + half * 8;
                float part = 0.f;
                #pragma unroll
                for (int ni = 0; ni < 4; ni++) {
                    int c = bn * 128 + n0 + ni * 8 + 2 * tg;
                    #pragma unroll
                    for (int jj = 0; jj < 2; jj++) {
                        float rv = Res[(size_t)r * N + c + jj];
                        float vh = __half2float(__float2half_rn(rv));
                        float z  = acc[mi][ni][half * 2 + jj] * WINV;
                        part += z * (2.0f * rv - vh) + bias[c + jj] * rv;
                    }
                }
                part += __shfl_xor_sync(0xffffffffu, part, 1);
                part += __shfl_xor_sync(0xffffffffu, part, 2);
                if (tg == 0) atomicAdd(&g_qn2[r], part);
            }
        return;
    }

    #pragma unroll
    for (int mi = 0; mi < 4; mi++)
        #pragma unroll
        for (int half = 0; half < 2; half++) {
            int r = bm * 256 + m0 + mi * 16 + g + half * 8;
            #pragma unroll
            for (int ni = 0; ni < 4; ni++) {
                int c = bn * 128 + n0 + ni * 8 + 2 * tg;
                float v0 = acc[mi][ni][half * 2 + 0] * WINV + bias[c];
                float v1 = acc[mi][ni][half * 2 + 1] * WINV + bias[c + 1];
                if (MODE == 1) {
                    v0 = v0 * normcdff(v0);
                    v1 = v1 * normcdff(v1);
                    Oh[(size_t)r * (N >> 1) + (c >> 1)] = packh2(v0, v1);
                } else {
                    v0 += Res[(size_t)r * N + c];
                    v1 += Res[(size_t)r * N + c + 1];
                    float2 ov = { v0, v1 };
                    *(float2*)(Out + (size_t)r * N + c) = ov;
                }
            }
        }
}

// ---------------------------------------------------------------------------
// Attention core: 32 tokens/block (warp = 4 rows, thread = 4 rows x 4 cols).
// Per-row accumulation order identical to R9 -> bitwise-identical sim.
// ---------------------------------------------------------------------------
__global__ __launch_bounds__(256) void attn_kernel(
    const float* __restrict__ resid, const float* __restrict__ g2,
    const float* __restrict__ be2)
{
    __shared__ float qs[32][32];
    __shared__ float ks2[32][128];
    __shared__ float simbuf[32][128];
    __shared__ float invn[32];
    __shared__ float pb_s[KTXT];
    int tid = threadIdx.x, lane = tid & 31, warp = tid >> 5;
    int t0 = blockIdx.x * 32;
    int b  = t0 >> 12;

    if (tid < 32) {
        float qn2 = g_qn2[t0 + tid] + g_nb2[0];
        float n = sqrtf(fmaxf(qn2, 0.f));
        invn[tid] = 1.0f / fmaxf(n, 1e-12f);
    }
    if (tid < KTXT) pb_s[tid] = g_pb[b * KTXT + tid];
    __syncthreads();

    float acc[4][4];
    #pragma unroll
    for (int r = 0; r < 4; r++)
        #pragma unroll
        for (int j = 0; j < 4; j++) acc[r][j] = 0.f;

    const float* Pb = g_P + (size_t)b * CDIM * KTXT;
    for (int kk = 0; kk < CDIM; kk += 32) {
        {
            int row = tid >> 3, k = (tid & 7) * 4;
            float4 qv = *(const float4*)(g_visln + (size_t)(t0 + row) * CDIM + kk + k);
            *(float4*)&qs[row][k] = qv;
        }
        #pragma unroll
        for (int i = 0; i < 16; i++) {
            int lin = tid + 256 * i;
            int cc = lin >> 7, col = lin & 127;
            ks2[cc][col] = Pb[(size_t)(kk + cc) * KTXT + col];
        }
        __syncthreads();
        #pragma unroll
        for (int k = 0; k < 32; k++) {
            float q0 = qs[warp * 4 + 0][k];
            float q1 = qs[warp * 4 + 1][k];
            float q2 = qs[warp * 4 + 2][k];
            float q3 = qs[warp * 4 + 3][k];
            #pragma unroll
            for (int j = 0; j < 4; j++) {
                float kv = ks2[k][lane + 32 * j];
                acc[0][j] += q0 * kv;
                acc[1][j] += q1 * kv;
                acc[2][j] += q2 * kv;
                acc[3][j] += q3 * kv;
            }
        }
        __syncthreads();
    }
    #pragma unroll
    for (int r = 0; r < 4; r++)
        #pragma unroll
        for (int j = 0; j < 4; j++)
            simbuf[warp * 4 + r][lane + 32 * j] = acc[r][j];
    __syncthreads();

    for (int rr = 0; rr < 4; rr++) {
        int row = warp * 4 + rr;
        float sc = invn[row];
        float tv[4];
        #pragma unroll
        for (int j = 0; j < 4; j++) {
            int col = lane + 32 * j;
            tv[j] = (simbuf[row][col] + pb_s[col]) * sc;
        }

        float mval[TOPM]; int midx[TOPM];
        #pragma unroll
        for (int it = 0; it < TOPM; it++) {
            float lm = tv[0]; int lj = 0;
            #pragma unroll
            for (int j = 1; j < 4; j++) if (tv[j] > lm) { lm = tv[j]; lj = j; }
            int li = lane + 32 * lj;
            #pragma unroll
            for (int o = 16; o; o >>= 1) {
                float ov = __shfl_xor_sync(0xffffffffu, lm, o);
                int   oi = __shfl_xor_sync(0xffffffffu, li, o);
                if (ov > lm || (ov == lm && oi < li)) { lm = ov; li = oi; }
            }
            mval[it] = lm; midx[it] = li;
            if ((li & 31) == lane) tv[li >> 5] = -INFINITY;
        }

        float p[TOPM], psum = 0.f;
        #pragma unroll
        for (int it = 0; it < TOPM; it++) {
            p[it] = expf((mval[it] - mval[0]) * TEMP_INV);
            psum += p[it];
        }
        float rnorm = 1.0f / psum;

        float f[16];
        #pragma unroll
        for (int i = 0; i < 16; i++) f[i] = 0.f;
        const float* Vb = g_value + (size_t)b * KTXT * CDIM;
        #pragma unroll
        for (int it = 0; it < TOPM; it++) {
            const float4* vr = (const float4*)(Vb + (size_t)midx[it] * CDIM + lane * 16);
            float a_ = p[it] * rnorm;
            #pragma unroll
            for (int j = 0; j < 4; j++) {
                float4 v = vr[j];
                f[4 * j + 0] += a_ * v.x;
                f[4 * j + 1] += a_ * v.y;
                f[4 * j + 2] += a_ * v.z;
                f[4 * j + 3] += a_ * v.w;
            }
        }

        const float4* rp = (const float4*)(resid + (size_t)(t0 + row) * CDIM + lane * 16);
        float s = 0.f, s2 = 0.f;
        #pragma unroll
        for (int j = 0; j < 4; j++) {
            float4 v = rp[j];
            f[4 * j + 0] += v.x;  f[4 * j + 1] += v.y;
            f[4 * j + 2] += v.z;  f[4 * j + 3] += v.w;
        }
        #pragma unroll
        for (int i = 0; i < 16; i++) { s += f[i]; s2 += f[i] * f[i]; }
        #pragma unroll
        for (int o = 16; o; o >>= 1) {
            s  += __shfl_xor_sync(0xffffffffu, s, o);
            s2 += __shfl_xor_sync(0xffffffffu, s2, o);
        }
        float mu  = s * (1.0f / CDIM);
        float var = s2 * (1.0f / CDIM) - mu * mu;
        float rstd = rsqrtf(var + LN_EPS);

        size_t rbase = (size_t)(t0 + row);
        float*    xp = g_X  + rbase * CDIM + lane * 16;
        uint32_t* xh = g_Xh + rbase * (CDIM / 2) + lane * 8;
        #pragma unroll
        for (int j = 0; j < 4; j++) {
            int c = lane * 16 + 4 * j;
            float4 o;
            o.x = (f[4 * j + 0] - mu) * rstd * g2[c + 0] + be2[c + 0];
            o.y = (f[4 * j + 1] - mu) * rstd * g2[c + 1] + be2[c + 1];
            o.z = (f[4 * j + 2] - mu) * rstd * g2[c + 2] + be2[c + 2];
            o.w = (f[4 * j + 3] - mu) * rstd * g2[c + 3] + be2[c + 3];
            *(float4*)(xp + 4 * j) = o;
            uint2 h;
            h.x = packh2(o.x, o.y);
            h.y = packh2(o.z, o.w);
            *(uint2*)(xh + 2 * j) = h;
        }
    }
}

// ---------------------------------------------------------------------------
// Launch
// ---------------------------------------------------------------------------
extern "C" void kernel_launch(void* const* d_in, const int* in_sizes, int n_in,
                              void* d_out, int out_size)
{
    const float* vis  = (const float*)d_in[0];
    const float* text = (const float*)d_in[1];
    const float* Wq   = (const float*)d_in[2];
    const float* bq   = (const float*)d_in[3];
    const float* Wv   = (const float*)d_in[4];
    const float* bv   = (const float*)d_in[5];
    const float* W1   = (const float*)d_in[6];
    const float* b1   = (const float*)d_in[7];
    const float* W2   = (const float*)d_in[8];
    const float* b2   = (const float*)d_in[9];
    const float* g1   = (const float*)d_in[10];
    const float* be1  = (const float*)d_in[11];
    const float* g2   = (const float*)d_in[12];
    const float* be2  = (const float*)d_in[13];
    float* out = (float*)d_out;

    float *p_visln, *p_X, *p_P, *p_G, *p_keyt, *p_wb2, *p_qn2;
    uint32_t *p_vh, *p_Xh, *p_Hh;
    uint32_t *p_Gh, *p_Gl, *p_W1h, *p_W1l, *p_W2h, *p_W2l;
    cudaGetSymbolAddress((void**)&p_visln, g_visln);
    cudaGetSymbolAddress((void**)&p_X,     g_X);
    cudaGetSymbolAddress((void**)&p_P,     g_P);
    cudaGetSymbolAddress((void**)&p_G,     g_G);
    cudaGetSymbolAddress((void**)&p_keyt,  g_keyt);
    cudaGetSymbolAddress((void**)&p_wb2,   g_wb2);
    cudaGetSymbolAddress((void**)&p_qn2,   g_qn2);
    cudaGetSymbolAddress((void**)&p_vh,    g_vh);
    cudaGetSymbolAddress((void**)&p_Xh,    g_Xh);
    cudaGetSymbolAddress((void**)&p_Hh,    g_Hh);
    cudaGetSymbolAddress((void**)&p_Gh,    g_Gh);
    cudaGetSymbolAddress((void**)&p_Gl,    g_Gl);
    cudaGetSymbolAddress((void**)&p_W1h,   g_W1h);
    cudaGetSymbolAddress((void**)&p_W1l,   g_W1l);
    cudaGetSymbolAddress((void**)&p_W2h,   g_W2h);
    cudaGetSymbolAddress((void**)&p_W2l,   g_W2l);

    cudaFuncSetAttribute(tgemm4_kernel<1>, cudaFuncAttributeMaxDynamicSharedMemorySize, SMEM4);
    cudaFuncSetAttribute(tgemm4_kernel<2>, cudaFuncAttributeMaxDynamicSharedMemorySize, SMEM4);
    cudaFuncSetAttribute(tgemm4_kernel<3>, cudaFuncAttributeMaxDynamicSharedMemorySize, SMEM4);

    // 1) text prep (keyt, value)
    prep_text_kernel<<<(BQ * KTXT) / 8, 256>>>(text, Wv, bv);
    // 2) P_b = Wq @ keyt_b^T per batch (fp32)
    sgemm_tn_kernel<<<dim3(1, CDIM / 128, BQ), 256>>>(
        Wq, p_keyt, p_P, TDIM, KTXT,
        0, (size_t)KTXT * TDIM, (size_t)CDIM * KTXT);
    // 3) G = Wq @ Wq^T (fp32)
    sgemm_tn_kernel<<<dim3(CDIM / 128, CDIM / 128, 1), 256>>>(
        Wq, Wq, p_G, TDIM, CDIM, 0, 0, 0);
    // 4) pb, wb2, nb2
    prep_small2_kernel<<<193, 256>>>(Wq, bq);
    // 5) convert weights to fp16 hi/lo planes (x256)
    convert_b_kernel<<<dim3(CDIM / 64, CDIM / 64), 256>>>(p_G, p_Gh, p_Gl, CDIM, CDIM);
    convert_b_kernel<<<dim3(HID / 64, CDIM / 64), 256>>>(W1, p_W1h, p_W1l, CDIM, HID);
    convert_b_kernel<<<dim3(CDIM / 64, HID / 64), 256>>>(W2, p_W2h, p_W2l, HID, CDIM);
    // 6) LN1 -> visln fp32 + vh fp16
    ln_kernel<<<MTOT / 8, 256>>>(vis, g1, be1, p_visln, p_vh);
    // 7) qn2 = vh@G dotted with (2v - vh) + wb2.v
    cudaMemsetAsync(p_qn2, 0, MTOT * sizeof(float));
    tgemm4_kernel<3><<<dim3(CDIM / 128, MTOT / 256), 512, SMEM4>>>(
        p_vh, p_Gh, p_Gl, p_wb2, p_visln, nullptr, nullptr,
        MTOT, CDIM, CDIM);
    // 8) attention + residual + LN2 -> X fp32 + Xh fp16
    attn_kernel<<<MTOT / 32, 256>>>(vis, g2, be2);
    // 9) H = gelu(X @ W1 + b1) -> fp16 plane Hh
    tgemm4_kernel<1><<<dim3(HID / 128, MTOT / 256), 512, SMEM4>>>(
        p_Xh, p_W1h, p_W1l, b1, nullptr, nullptr, p_Hh,
        MTOT, HID, CDIM);
    // 10) out = X + H @ W2 + b2
    tgemm4_kernel<2><<<dim3(CDIM / 128, MTOT / 256), 512, SMEM4>>>(
        p_Hh, p_W2h, p_W2l, b2, p_X, out, nullptr,
        MTOT, CDIM, HID);
}

// round 11
// speedup vs baseline: 1.8111x; 1.1889x over previous
#include <cuda_runtime.h>
#include <cuda_fp16.h>
#include <math.h>
#include <stdint.h>

// ---------------------------------------------------------------------------
// Problem constants
// ---------------------------------------------------------------------------
#define BQ    8
#define MTOT  32768
#define CDIM  512
#define TDIM  768
#define KTXT  128
#define HID   2048
#define TOPM  5
#define TEMP_INV (1.0f/0.07f)
#define LN_EPS 1e-5f
#define WSCALE 256.0f
#define WINV   (1.0f/256.0f)

// ---------------------------------------------------------------------------
// Scratch (device globals)
// ---------------------------------------------------------------------------
static __device__ float    g_visln[MTOT * CDIM];
static __device__ uint32_t g_vh[MTOT * CDIM / 2];
static __device__ float    g_X [MTOT * CDIM];
static __device__ uint32_t g_Xh[MTOT * CDIM / 2];
static __device__ uint32_t g_Hh[(size_t)MTOT * HID / 2];
static __device__ float    g_keyt [BQ * KTXT * TDIM];
static __device__ float    g_value[BQ * KTXT * CDIM];
static __device__ float    g_P [BQ * CDIM * KTXT];
static __device__ float    g_G [CDIM * CDIM];
static __device__ uint32_t g_Gh [CDIM * CDIM / 2];
static __device__ uint32_t g_Gl [CDIM * CDIM / 2];
static __device__ uint32_t g_W1h[(size_t)HID * CDIM / 2];
static __device__ uint32_t g_W1l[(size_t)HID * CDIM / 2];
static __device__ uint32_t g_W2h[(size_t)CDIM * HID / 2];
static __device__ uint32_t g_W2l[(size_t)CDIM * HID / 2];
static __device__ float    g_pb [BQ * KTXT];
static __device__ float    g_wb2[CDIM];
static __device__ float    g_nb2[1];
static __device__ float    g_qn2[MTOT];

// ---------------------------------------------------------------------------
// Helpers
// ---------------------------------------------------------------------------
__device__ __forceinline__ uint32_t packh2(float x, float y) {
    __half2 h = __floats2half2_rn(x, y);
    return *reinterpret_cast<uint32_t*>(&h);
}

__device__ __forceinline__ void wsplit2(float x, float y,
                                        uint32_t& hi, uint32_t& lo) {
    float sx = x * WSCALE, sy = y * WSCALE;
    __half hx = __float2half_rn(sx);
    __half hy = __float2half_rn(sy);
    float rx = sx - __half2float(hx);
    float ry = sy - __half2float(hy);
    __half2 h2 = __halves2half2(hx, hy);
    __half2 l2 = __floats2half2_rn(rx, ry);
    hi = *reinterpret_cast<uint32_t*>(&h2);
    lo = *reinterpret_cast<uint32_t*>(&l2);
}

__device__ __forceinline__ void mma_f16(float* c, const uint32_t* a, const uint32_t* b) {
    asm volatile(
        "mma.sync.aligned.m16n8k16.row.col.f32.f16.f16.f32 "
        "{%0,%1,%2,%3}, {%4,%5,%6,%7}, {%8,%9}, {%0,%1,%2,%3};\n"
        : "+f"(c[0]), "+f"(c[1]), "+f"(c[2]), "+f"(c[3])
        : "r"(a[0]), "r"(a[1]), "r"(a[2]), "r"(a[3]), "r"(b[0]), "r"(b[1]));
}

__device__ __forceinline__ uint32_t smem_u32(const void* p) {
    uint32_t a;
    asm("{ .reg .u64 t; cvta.to.shared.u64 t, %1; cvt.u32.u64 %0, t; }"
        : "=r"(a) : "l"(p));
    return a;
}

__device__ __forceinline__ void ldsm_x4(uint32_t& r0, uint32_t& r1,
                                        uint32_t& r2, uint32_t& r3,
                                        uint32_t addr) {
    asm volatile(
        "ldmatrix.sync.aligned.m8n8.x4.shared.b16 {%0,%1,%2,%3}, [%4];"
        : "=r"(r0), "=r"(r1), "=r"(r2), "=r"(r3) : "r"(addr));
}

__device__ __forceinline__ void cp16(uint32_t* dst_smem, const uint32_t* src) {
    uint32_t s = (uint32_t)__cvta_generic_to_shared(dst_smem);
    asm volatile("cp.async.cg.shared.global [%0], [%1], 16;\n" :: "r"(s), "l"(src));
}
__device__ __forceinline__ void cp_commit() {
    asm volatile("cp.async.commit_group;\n");
}
__device__ __forceinline__ void cp_wait1() {
    asm volatile("cp.async.wait_group 1;\n");
}

// ---------------------------------------------------------------------------
// Kernel: text prep — keyt = l2norm(text), value = text @ Wv + bv
// ---------------------------------------------------------------------------
__global__ __launch_bounds__(256) void prep_text_kernel(
    const float* __restrict__ text, const float* __restrict__ Wv,
    const float* __restrict__ bv)
{
    __shared__ float ts[8][TDIM];
    int tid = threadIdx.x, lane = tid & 31, warp = tid >> 5;
    int b  = blockIdx.x >> 4;
    int kb = (blockIdx.x & 15) * 8;
    const float* tb = text + ((size_t)b * KTXT + kb) * TDIM;

    #pragma unroll
    for (int i = 0; i < 24; i++) {
        int lin = tid + 256 * i;
        int r = lin / TDIM, c = lin % TDIM;
        ts[r][c] = tb[(size_t)r * TDIM + c];
    }
    __syncthreads();

    {
        int r = warp;
        float s = 0.f;
        for (int i = lane; i < TDIM; i += 32) { float v = ts[r][i]; s += v * v; }
        #pragma unroll
        for (int o = 16; o; o >>= 1) s += __shfl_xor_sync(0xffffffffu, s, o);
        float inv = 1.0f / fmaxf(sqrtf(s), 1e-12f);
        float* kr = g_keyt + ((size_t)b * KTXT + kb + r) * TDIM;
        for (int i = lane; i < TDIM; i += 32) kr[i] = ts[r][i] * inv;
    }

    float acc[8][2];
    #pragma unroll
    for (int r = 0; r < 8; r++) { acc[r][0] = 0.f; acc[r][1] = 0.f; }
    int c0 = tid, c1 = tid + 256;
    for (int t = 0; t < TDIM; t++) {
        float w0 = Wv[(size_t)t * CDIM + c0];
        float w1 = Wv[(size_t)t * CDIM + c1];
        #pragma unroll
        for (int r = 0; r < 8; r++) {
            float tv = ts[r][t];
            acc[r][0] += tv * w0;
            acc[r][1] += tv * w1;
        }
    }
    float bb0 = bv[c0], bb1 = bv[c1];
    #pragma unroll
    for (int r = 0; r < 8; r++) {
        float* vr = g_value + ((size_t)b * KTXT + kb + r) * CDIM;
        vr[c0] = acc[r][0] + bb0;
        vr[c1] = acc[r][1] + bb1;
    }
}

// ---------------------------------------------------------------------------
// Kernel: small fp32 SGEMM  C[M,N] = A[M,K] @ B2[N,K]^T  (for P and G)
// ---------------------------------------------------------------------------
__global__ __launch_bounds__(256) void sgemm_tn_kernel(
    const float* __restrict__ A, const float* __restrict__ B2,
    float* __restrict__ C, int Kd, int N,
    size_t aStride, size_t bStride, size_t cStride)
{
    __shared__ float As[8][128];
    __shared__ float Bs[8][128];
    int tid = threadIdx.x;
    int tx = tid & 15, ty = tid >> 4;
    int bn = blockIdx.x, bm = blockIdx.y, bz = blockIdx.z;
    const float* Ab = A  + (size_t)bz * aStride + (size_t)bm * 128 * Kd;
    const float* Bb = B2 + (size_t)bz * bStride + (size_t)bn * 128 * Kd;
    int l_r = tid >> 1, l_k = (tid & 1) * 4;

    float acc[8][8];
    #pragma unroll
    for (int i = 0; i < 8; i++)
        #pragma unroll
        for (int j = 0; j < 8; j++) acc[i][j] = 0.f;

    for (int k0 = 0; k0 < Kd; k0 += 8) {
        float4 av = *(const float4*)(Ab + (size_t)l_r * Kd + k0 + l_k);
        As[l_k + 0][l_r] = av.x;
        As[l_k + 1][l_r] = av.y;
        As[l_k + 2][l_r] = av.z;
        As[l_k + 3][l_r] = av.w;
        float4 bv = *(const float4*)(Bb + (size_t)l_r * Kd + k0 + l_k);
        Bs[l_k + 0][l_r] = bv.x;
        Bs[l_k + 1][l_r] = bv.y;
        Bs[l_k + 2][l_r] = bv.z;
        Bs[l_k + 3][l_r] = bv.w;
        __syncthreads();
        #pragma unroll
        for (int k = 0; k < 8; k++) {
            float ar[8], br[8];
            #pragma unroll
            for (int i = 0; i < 4; i++) {
                ar[i]     = As[k][ty * 4 + i];
                ar[4 + i] = As[k][64 + ty * 4 + i];
                br[i]     = Bs[k][tx * 4 + i];
                br[4 + i] = Bs[k][64 + tx * 4 + i];
            }
            #pragma unroll
            for (int i = 0; i < 8; i++)
                #pragma unroll
                for (int j = 0; j < 8; j++) acc[i][j] += ar[i] * br[j];
        }
        __syncthreads();
    }

    float* Cb = C + (size_t)bz * cStride;
    #pragma unroll
    for (int gi = 0; gi < 2; gi++)
        #pragma unroll
        for (int ii = 0; ii < 4; ii++) {
            int r = bm * 128 + gi * 64 + ty * 4 + ii;
            #pragma unroll
            for (int gj = 0; gj < 2; gj++) {
                int cb = bn * 128 + gj * 64 + tx * 4;
                float4 o;
                o.x = acc[gi * 4 + ii][gj * 4 + 0];
                o.y = acc[gi * 4 + ii][gj * 4 + 1];
                o.z = acc[gi * 4 + ii][gj * 4 + 2];
                o.w = acc[gi * 4 + ii][gj * 4 + 3];
                *(float4*)(Cb + (size_t)r * N + cb) = o;
            }
        }
}

// ---------------------------------------------------------------------------
// Kernel: prep_small2 — warp-per-row dots
// ---------------------------------------------------------------------------
__global__ __launch_bounds__(256) void prep_small2_kernel(
    const float* __restrict__ Wq, const float* __restrict__ bq)
{
    int gw = blockIdx.x * 8 + (threadIdx.x >> 5);
    int lane = threadIdx.x & 31;
    if (gw > 1536) return;
    const float4* bp = (const float4*)bq;
    float s = 0.f;
    if (gw < 1024) {
        const float4* kr = (const float4*)(g_keyt + (size_t)gw * TDIM);
        #pragma unroll
        for (int i = 0; i < 6; i++) {
            float4 a = kr[lane + 32 * i], c = bp[lane + 32 * i];
            s += a.x * c.x + a.y * c.y + a.z * c.z + a.w * c.w;
        }
        #pragma unroll
        for (int o = 16; o; o >>= 1) s += __shfl_xor_sync(0xffffffffu, s, o);
        if (!lane) g_pb[gw] = s;
    } else if (gw < 1536) {
        int c = gw - 1024;
        const float4* wr = (const float4*)(Wq + (size_t)c * TDIM);
        #pragma unroll
        for (int i = 0; i < 6; i++) {
            float4 a = wr[lane + 32 * i], d = bp[lane + 32 * i];
            s += a.x * d.x + a.y * d.y + a.z * d.z + a.w * d.w;
        }
        #pragma unroll
        for (int o = 16; o; o >>= 1) s += __shfl_xor_sync(0xffffffffu, s, o);
        if (!lane) g_wb2[c] = 2.0f * s;
    } else {
        #pragma unroll
        for (int i = 0; i < 6; i++) {
            float4 a = bp[lane + 32 * i];
            s += a.x * a.x + a.y * a.y + a.z * a.z + a.w * a.w;
        }
        #pragma unroll
        for (int o = 16; o; o >>= 1) s += __shfl_xor_sync(0xffffffffu, s, o);
        if (!lane) g_nb2[0] = s;
    }
}

// ---------------------------------------------------------------------------
// Kernel: convert fp32 B [K][N] -> fp16 hi/lo planes [N][K/2], scaled x256
// ---------------------------------------------------------------------------
__global__ __launch_bounds__(256) void convert_b_kernel(
    const float* __restrict__ in, uint32_t* __restrict__ oh,
    uint32_t* __restrict__ ol, int Kd, int N)
{
    __shared__ float t[64][65];
    int k0 = blockIdx.y * 64, n0 = blockIdx.x * 64;
    int tid = threadIdx.x;
    #pragma unroll
    for (int i = 0; i < 16; i++) {
        int lin = tid + 256 * i;
        int r = lin >> 6, c = lin & 63;
        t[r][c] = in[(size_t)(k0 + r) * N + n0 + c];
    }
    __syncthreads();
    int K2 = Kd >> 1;
    #pragma unroll
    for (int i = 0; i < 8; i++) {
        int lin = tid + 256 * i;
        int n = lin >> 5, kp = lin & 31;
        uint32_t h, l;
        wsplit2(t[2 * kp][n], t[2 * kp + 1][n], h, l);
        size_t o = (size_t)(n0 + n) * K2 + (k0 >> 1) + kp;
        oh[o] = h;  ol[o] = l;
    }
}

// ---------------------------------------------------------------------------
// Kernel: LayerNorm -> fp32 + fp16 plane
// ---------------------------------------------------------------------------
__global__ __launch_bounds__(256) void ln_kernel(
    const float* __restrict__ in, const float* __restrict__ g,
    const float* __restrict__ be, float* __restrict__ out,
    uint32_t* __restrict__ oh)
{
    int warp = threadIdx.x >> 5, lane = threadIdx.x & 31;
    size_t row = (size_t)blockIdx.x * 8 + warp;
    const float4* p = (const float4*)(in + row * CDIM);
    float4 x[4];
    float s = 0.f, s2 = 0.f;
    #pragma unroll
    for (int i = 0; i < 4; i++) {
        x[i] = p[lane + 32 * i];
        s  += x[i].x + x[i].y + x[i].z + x[i].w;
        s2 += x[i].x * x[i].x + x[i].y * x[i].y + x[i].z * x[i].z + x[i].w * x[i].w;
    }
    #pragma unroll
    for (int o = 16; o; o >>= 1) {
        s  += __shfl_xor_sync(0xffffffffu, s, o);
        s2 += __shfl_xor_sync(0xffffffffu, s2, o);
    }
    float mu  = s * (1.0f / CDIM);
    float var = s2 * (1.0f / CDIM) - mu * mu;
    float rs  = rsqrtf(var + LN_EPS);
    float4* o4 = (float4*)(out + row * CDIM);
    const float4* gp = (const float4*)g;
    const float4* bp = (const float4*)be;
    #pragma unroll
    for (int i = 0; i < 4; i++) {
        int c4 = lane + 32 * i;
        float4 gv = gp[c4], bv = bp[c4], r;
        r.x = (x[i].x - mu) * rs * gv.x + bv.x;
        r.y = (x[i].y - mu) * rs * gv.y + bv.y;
        r.z = (x[i].z - mu) * rs * gv.z + bv.z;
        r.w = (x[i].w - mu) * rs * gv.w + bv.w;
        o4[c4] = r;
        uint2 h;
        h.x = packh2(r.x, r.y);
        h.y = packh2(r.z, r.w);
        *(uint2*)(oh + row * (CDIM / 2) + 2 * c4) = h;
    }
}

// ---------------------------------------------------------------------------
// fp16 tensor-core GEMM: D = Ah @ (Bh [+ Bl]), B pre-scaled x256.
// NPROD = 1: weight hi only (FFN; activation rounding dominates anyway)
// NPROD = 2: weight hi+lo (qn2 path; norm scale error is row-correlated)
// 256x128 block tile, 512 threads = 16 warps (4m x 4n), warp tile 64x32.
// MODE 1: gelu(acc/256+bias) -> fp16 plane Oh
// MODE 2: acc/256+bias+Res -> Out fp32
// MODE 3: qn2[r] += sum_c (acc/256)*(2*Res - fp16(Res)) + bias*Res
// ---------------------------------------------------------------------------
#define A_PLANE 5120          // 256 rows * 20 u32
#define B_PLANE 2560          // 128 rows * 20 u32

template <int MODE, int NPROD>
__global__ __launch_bounds__(512) void tgemm4_kernel(
    const uint32_t* __restrict__ Ah,
    const uint32_t* __restrict__ Bh, const uint32_t* __restrict__ Bl,
    const float* __restrict__ bias, const float* __restrict__ Res,
    float* __restrict__ Out, uint32_t* __restrict__ Oh,
    int M, int N, int Kd)
{
    const int STG = A_PLANE + NPROD * B_PLANE;
    extern __shared__ uint32_t sm[];
    uint32_t sbase = smem_u32(sm);
    int K2 = Kd >> 1;
    int tid = threadIdx.x, lane = tid & 31, warp = tid >> 5;
    int g  = lane >> 2, tg = lane & 3;
    int wm = warp >> 2, wn = warp & 3;
    int m0 = wm * 64,  n0 = wn * 32;
    int bn = blockIdx.x, bm = blockIdx.y;

    const uint32_t* AhB = Ah + (size_t)bm * 256 * K2;
    const uint32_t* BhB = Bh + (size_t)bn * 128 * K2;
    const uint32_t* BlB = Bl + (size_t)bn * 128 * K2;

    uint32_t a_ld = (uint32_t)((m0 + (lane & 7) + ((lane >> 3) & 1) * 8) * 20
                               + ((lane >> 4) & 1) * 4) * 4;
    uint32_t b_ld = (uint32_t)((n0 + (lane & 7) + ((lane >> 4) & 1) * 8) * 20
                               + ((lane >> 3) & 1) * 4) * 4;

    float acc[4][4][4];
    #pragma unroll
    for (int mi = 0; mi < 4; mi++)
        #pragma unroll
        for (int ni = 0; ni < 4; ni++)
            #pragma unroll
            for (int r = 0; r < 4; r++) acc[mi][ni][r] = 0.f;

    int nT = K2 / 16;

    #pragma unroll
    for (int pf = 0; pf < 2; pf++) {
        uint32_t* st = sm + pf * STG;
        int kp0 = pf * 16;
        #pragma unroll
        for (int c = 0; c < 2; c++) {
            int idx = tid + 512 * c;
            int row = idx >> 2, kb = (idx & 3) * 4;
            cp16(st + row * 20 + kb, AhB + (size_t)row * K2 + kp0 + kb);
        }
        {
            int row = tid >> 2, kb = (tid & 3) * 4;
            size_t go = (size_t)row * K2 + kp0 + kb;
            int so = row * 20 + kb;
            cp16(st + A_PLANE + so, BhB + go);
            if (NPROD == 2)
                cp16(st + A_PLANE + B_PLANE + so, BlB + go);
        }
        cp_commit();
    }

    for (int t = 0; t < nT; t++) {
        cp_wait1();
        __syncthreads();
        uint32_t stb = sbase + (uint32_t)((t & 1) * STG * 4);

        #pragma unroll
        for (int ks = 0; ks < 2; ks++) {
            uint32_t ksoff = (uint32_t)(ks * 32);
            uint32_t a[4][4], bh[4][2], bl[4][2];
            #pragma unroll
            for (int mi = 0; mi < 4; mi++) {
                uint32_t ao = stb + a_ld + ksoff + (uint32_t)(mi * 16 * 80);
                ldsm_x4(a[mi][0], a[mi][1], a[mi][2], a[mi][3], ao);
            }
            #pragma unroll
            for (int p = 0; p < 2; p++) {
                uint32_t bo = stb + A_PLANE * 4 + b_ld + ksoff + (uint32_t)(p * 16 * 80);
                ldsm_x4(bh[2 * p][0], bh[2 * p][1], bh[2 * p + 1][0], bh[2 * p + 1][1], bo);
                if (NPROD == 2)
                    ldsm_x4(bl[2 * p][0], bl[2 * p][1], bl[2 * p + 1][0], bl[2 * p + 1][1],
                            bo + B_PLANE * 4);
            }
            #pragma unroll
            for (int mi = 0; mi < 4; mi++)
                #pragma unroll
                for (int ni = 0; ni < 4; ni++) {
                    mma_f16(acc[mi][ni], a[mi], bh[ni]);
                    if (NPROD == 2) mma_f16(acc[mi][ni], a[mi], bl[ni]);
                }
        }
        __syncthreads();
        if (t + 2 < nT) {
            uint32_t* dst = sm + (t & 1) * STG;
            int kp0 = (t + 2) * 16;
            #pragma unroll
            for (int c = 0; c < 2; c++) {
                int idx = tid + 512 * c;
                int row = idx >> 2, kb = (idx & 3) * 4;
                cp16(dst + row * 20 + kb, AhB + (size_t)row * K2 + kp0 + kb);
            }
            {
                int row = tid >> 2, kb = (tid & 3) * 4;
                size_t go = (size_t)row * K2 + kp0 + kb;
                int so = row * 20 + kb;
                cp16(dst + A_PLANE + so, BhB + go);
                if (NPROD == 2)
                    cp16(dst + A_PLANE + B_PLANE + so, BlB + go);
            }
        }
        cp_commit();
    }

    if (MODE == 3) {
        #pragma unroll
        for (int mi = 0; mi < 4; mi++)
            #pragma unroll
            for (int half = 0; half < 2; half++) {
                int r = bm * 256 + m0 + mi * 16 + g + half * 8;
                float part = 0.f;
                #pragma unroll
                for (int ni = 0; ni < 4; ni++) {
                    int c = bn * 128 + n0 + ni * 8 + 2 * tg;
                    #pragma unroll
                    for (int jj = 0; jj < 2; jj++) {
                        float rv = Res[(size_t)r * N + c + jj];
                        float vh = __half2float(__float2half_rn(rv));
                        float z  = acc[mi][ni][half * 2 + jj] * WINV;
                        part += z * (2.0f * rv - vh) + bias[c + jj] * rv;
                    }
                }
                part += __shfl_xor_sync(0xffffffffu, part, 1);
                part += __shfl_xor_sync(0xffffffffu, part, 2);
                if (tg == 0) atomicAdd(&g_qn2[r], part);
            }
        return;
    }

    #pragma unroll
    for (int mi = 0; mi < 4; mi++)
        #pragma unroll
        for (int half = 0; half < 2; half++) {
            int r = bm * 256 + m0 + mi * 16 + g + half * 8;
            #pragma unroll
            for (int ni = 0; ni < 4; ni++) {
                int c = bn * 128 + n0 + ni * 8 + 2 * tg;
                float v0 = acc[mi][ni][half * 2 + 0] * WINV + bias[c];
                float v1 = acc[mi][ni][half * 2 + 1] * WINV + bias[c + 1];
                if (MODE == 1) {
                    v0 = v0 * normcdff(v0);
                    v1 = v1 * normcdff(v1);
                    Oh[(size_t)r * (N >> 1) + (c >> 1)] = packh2(v0, v1);
                } else {
                    v0 += Res[(size_t)r * N + c];
                    v1 += Res[(size_t)r * N + c + 1];
                    float2 ov = { v0, v1 };
                    *(float2*)(Out + (size_t)r * N + c) = ov;
                }
            }
        }
}

// ---------------------------------------------------------------------------
// Attention core: 32 tokens/block (proven in R10)
// ---------------------------------------------------------------------------
__global__ __launch_bounds__(256) void attn_kernel(
    const float* __restrict__ resid, const float* __restrict__ g2,
    const float* __restrict__ be2)
{
    __shared__ float qs[32][32];
    __shared__ float ks2[32][128];
    __shared__ float simbuf[32][128];
    __shared__ float invn[32];
    __shared__ float pb_s[KTXT];
    int tid = threadIdx.x, lane = tid & 31, warp = tid >> 5;
    int t0 = blockIdx.x * 32;
    int b  = t0 >> 12;

    if (tid < 32) {
        float qn2 = g_qn2[t0 + tid] + g_nb2[0];
        float n = sqrtf(fmaxf(qn2, 0.f));
        invn[tid] = 1.0f / fmaxf(n, 1e-12f);
    }
    if (tid < KTXT) pb_s[tid] = g_pb[b * KTXT + tid];
    __syncthreads();

    float acc[4][4];
    #pragma unroll
    for (int r = 0; r < 4; r++)
        #pragma unroll
        for (int j = 0; j < 4; j++) acc[r][j] = 0.f;

    const float* Pb = g_P + (size_t)b * CDIM * KTXT;
    for (int kk = 0; kk < CDIM; kk += 32) {
        {
            int row = tid >> 3, k = (tid & 7) * 4;
            float4 qv = *(const float4*)(g_visln + (size_t)(t0 + row) * CDIM + kk + k);
            *(float4*)&qs[row][k] = qv;
        }
        #pragma unroll
        for (int i = 0; i < 16; i++) {
            int lin = tid + 256 * i;
            int cc = lin >> 7, col = lin & 127;
            ks2[cc][col] = Pb[(size_t)(kk + cc) * KTXT + col];
        }
        __syncthreads();
        #pragma unroll
        for (int k = 0; k < 32; k++) {
            float q0 = qs[warp * 4 + 0][k];
            float q1 = qs[warp * 4 + 1][k];
            float q2 = qs[warp * 4 + 2][k];
            float q3 = qs[warp * 4 + 3][k];
            #pragma unroll
            for (int j = 0; j < 4; j++) {
                float kv = ks2[k][lane + 32 * j];
                acc[0][j] += q0 * kv;
                acc[1][j] += q1 * kv;
                acc[2][j] += q2 * kv;
                acc[3][j] += q3 * kv;
            }
        }
        __syncthreads();
    }
    #pragma unroll
    for (int r = 0; r < 4; r++)
        #pragma unroll
        for (int j = 0; j < 4; j++)
            simbuf[warp * 4 + r][lane + 32 * j] = acc[r][j];
    __syncthreads();

    for (int rr = 0; rr < 4; rr++) {
        int row = warp * 4 + rr;
        float sc = invn[row];
        float tv[4];
        #pragma unroll
        for (int j = 0; j < 4; j++) {
            int col = lane + 32 * j;
            tv[j] = (simbuf[row][col] + pb_s[col]) * sc;
        }

        float mval[TOPM]; int midx[TOPM];
        #pragma unroll
        for (int it = 0; it < TOPM; it++) {
            float lm = tv[0]; int lj = 0;
            #pragma unroll
            for (int j = 1; j < 4; j++) if (tv[j] > lm) { lm = tv[j]; lj = j; }
            int li = lane + 32 * lj;
            #pragma unroll
            for (int o = 16; o; o >>= 1) {
                float ov = __shfl_xor_sync(0xffffffffu, lm, o);
                int   oi = __shfl_xor_sync(0xffffffffu, li, o);
                if (ov > lm || (ov == lm && oi < li)) { lm = ov; li = oi; }
            }
            mval[it] = lm; midx[it] = li;
            if ((li & 31) == lane) tv[li >> 5] = -INFINITY;
        }

        float p[TOPM], psum = 0.f;
        #pragma unroll
        for (int it = 0; it < TOPM; it++) {
            p[it] = expf((mval[it] - mval[0]) * TEMP_INV);
            psum += p[it];
        }
        float rnorm = 1.0f / psum;

        float f[16];
        #pragma unroll
        for (int i = 0; i < 16; i++) f[i] = 0.f;
        const float* Vb = g_value + (size_t)b * KTXT * CDIM;
        #pragma unroll
        for (int it = 0; it < TOPM; it++) {
            const float4* vr = (const float4*)(Vb + (size_t)midx[it] * CDIM + lane * 16);
            float a_ = p[it] * rnorm;
            #pragma unroll
            for (int j = 0; j < 4; j++) {
                float4 v = vr[j];
                f[4 * j + 0] += a_ * v.x;
                f[4 * j + 1] += a_ * v.y;
                f[4 * j + 2] += a_ * v.z;
                f[4 * j + 3] += a_ * v.w;
            }
        }

        const float4* rp = (const float4*)(resid + (size_t)(t0 + row) * CDIM + lane * 16);
        float s = 0.f, s2 = 0.f;
        #pragma unroll
        for (int j = 0; j < 4; j++) {
            float4 v = rp[j];
            f[4 * j + 0] += v.x;  f[4 * j + 1] += v.y;
            f[4 * j + 2] += v.z;  f[4 * j + 3] += v.w;
        }
        #pragma unroll
        for (int i = 0; i < 16; i++) { s += f[i]; s2 += f[i] * f[i]; }
        #pragma unroll
        for (int o = 16; o; o >>= 1) {
            s  += __shfl_xor_sync(0xffffffffu, s, o);
            s2 += __shfl_xor_sync(0xffffffffu, s2, o);
        }
        float mu  = s * (1.0f / CDIM);
        float var = s2 * (1.0f / CDIM) - mu * mu;
        float rstd = rsqrtf(var + LN_EPS);

        size_t rbase = (size_t)(t0 + row);
        float*    xp = g_X  + rbase * CDIM + lane * 16;
        uint32_t* xh = g_Xh + rbase * (CDIM / 2) + lane * 8;
        #pragma unroll
        for (int j = 0; j < 4; j++) {
            int c = lane * 16 + 4 * j;
            float4 o;
            o.x = (f[4 * j + 0] - mu) * rstd * g2[c + 0] + be2[c + 0];
            o.y = (f[4 * j + 1] - mu) * rstd * g2[c + 1] + be2[c + 1];
            o.z = (f[4 * j + 2] - mu) * rstd * g2[c + 2] + be2[c + 2];
            o.w = (f[4 * j + 3] - mu) * rstd * g2[c + 3] + be2[c + 3];
            *(float4*)(xp + 4 * j) = o;
            uint2 h;
            h.x = packh2(o.x, o.y);
            h.y = packh2(o.z, o.w);
            *(uint2*)(xh + 2 * j) = h;
        }
    }
}

// ---------------------------------------------------------------------------
// Launch
// ---------------------------------------------------------------------------
extern "C" void kernel_launch(void* const* d_in, const int* in_sizes, int n_in,
                              void* d_out, int out_size)
{
    const float* vis  = (const float*)d_in[0];
    const float* text = (const float*)d_in[1];
    const float* Wq   = (const float*)d_in[2];
    const float* bq   = (const float*)d_in[3];
    const float* Wv   = (const float*)d_in[4];
    const float* bv   = (const float*)d_in[5];
    const float* W1   = (const float*)d_in[6];
    const float* b1   = (const float*)d_in[7];
    const float* W2   = (const float*)d_in[8];
    const float* b2   = (const float*)d_in[9];
    const float* g1   = (const float*)d_in[10];
    const float* be1  = (const float*)d_in[11];
    const float* g2   = (const float*)d_in[12];
    const float* be2  = (const float*)d_in[13];
    float* out = (float*)d_out;

    float *p_visln, *p_X, *p_P, *p_G, *p_keyt, *p_wb2, *p_qn2;
    uint32_t *p_vh, *p_Xh, *p_Hh;
    uint32_t *p_Gh, *p_Gl, *p_W1h, *p_W1l, *p_W2h, *p_W2l;
    cudaGetSymbolAddress((void**)&p_visln, g_visln);
    cudaGetSymbolAddress((void**)&p_X,     g_X);
    cudaGetSymbolAddress((void**)&p_P,     g_P);
    cudaGetSymbolAddress((void**)&p_G,     g_G);
    cudaGetSymbolAddress((void**)&p_keyt,  g_keyt);
    cudaGetSymbolAddress((void**)&p_wb2,   g_wb2);
    cudaGetSymbolAddress((void**)&p_qn2,   g_qn2);
    cudaGetSymbolAddress((void**)&p_vh,    g_vh);
    cudaGetSymbolAddress((void**)&p_Xh,    g_Xh);
    cudaGetSymbolAddress((void**)&p_Hh,    g_Hh);
    cudaGetSymbolAddress((void**)&p_Gh,    g_Gh);
    cudaGetSymbolAddress((void**)&p_Gl,    g_Gl);
    cudaGetSymbolAddress((void**)&p_W1h,   g_W1h);
    cudaGetSymbolAddress((void**)&p_W1l,   g_W1l);
    cudaGetSymbolAddress((void**)&p_W2h,   g_W2h);
    cudaGetSymbolAddress((void**)&p_W2l,   g_W2l);

    const int SMEM_2P = 2 * (A_PLANE + 2 * B_PLANE) * 4;   // 81920 B
    const int SMEM_1P = 2 * (A_PLANE + 1 * B_PLANE) * 4;   // 61440 B
    cudaFuncSetAttribute((const void*)tgemm4_kernel<1, 1>,
                         cudaFuncAttributeMaxDynamicSharedMemorySize, SMEM_1P);
    cudaFuncSetAttribute((const void*)tgemm4_kernel<2, 1>,
                         cudaFuncAttributeMaxDynamicSharedMemorySize, SMEM_1P);
    cudaFuncSetAttribute((const void*)tgemm4_kernel<3, 2>,
                         cudaFuncAttributeMaxDynamicSharedMemorySize, SMEM_2P);

    // 1) text prep (keyt, value)
    prep_text_kernel<<<(BQ * KTXT) / 8, 256>>>(text, Wv, bv);
    // 2) P_b = Wq @ keyt_b^T per batch (fp32)
    sgemm_tn_kernel<<<dim3(1, CDIM / 128, BQ), 256>>>(
        Wq, p_keyt, p_P, TDIM, KTXT,
        0, (size_t)KTXT * TDIM, (size_t)CDIM * KTXT);
    // 3) G = Wq @ Wq^T (fp32)
    sgemm_tn_kernel<<<dim3(CDIM / 128, CDIM / 128, 1), 256>>>(
        Wq, Wq, p_G, TDIM, CDIM, 0, 0, 0);
    // 4) pb, wb2, nb2
    prep_small2_kernel<<<193, 256>>>(Wq, bq);
    // 5) convert weights to fp16 hi/lo planes (x256)
    convert_b_kernel<<<dim3(CDIM / 64, CDIM / 64), 256>>>(p_G, p_Gh, p_Gl, CDIM, CDIM);
    convert_b_kernel<<<dim3(HID / 64, CDIM / 64), 256>>>(W1, p_W1h, p_W1l, CDIM, HID);
    convert_b_kernel<<<dim3(CDIM / 64, HID / 64), 256>>>(W2, p_W2h, p_W2l, HID, CDIM);
    // 6) LN1 -> visln fp32 + vh fp16
    ln_kernel<<<MTOT / 8, 256>>>(vis, g1, be1, p_visln, p_vh);
    // 7) qn2 (2-product: per-row norm error is correlated -> keep exact-ish)
    cudaMemsetAsync(p_qn2, 0, MTOT * sizeof(float));
    tgemm4_kernel<3, 2><<<dim3(CDIM / 128, MTOT / 256), 512, SMEM_2P>>>(
        p_vh, p_Gh, p_Gl, p_wb2, p_visln, nullptr, nullptr,
        MTOT, CDIM, CDIM);
    // 8) attention + residual + LN2 -> X fp32 + Xh fp16
    attn_kernel<<<MTOT / 32, 256>>>(vis, g2, be2);
    // 9) H = gelu(X @ W1 + b1) -> fp16 plane Hh   (1 product)
    tgemm4_kernel<1, 1><<<dim3(HID / 128, MTOT / 256), 512, SMEM_1P>>>(
        p_Xh, p_W1h, p_W1l, b1, nullptr, nullptr, p_Hh,
        MTOT, HID, CDIM);
    // 10) out = X + H @ W2 + b2   (1 product)
    tgemm4_kernel<2, 1><<<dim3(CDIM / 128, MTOT / 256), 512, SMEM_1P>>>(
        p_Hh, p_W2h, p_W2l, b2, p_X, out, nullptr,
        MTOT, CDIM, HID);
}

// round 12
// speedup vs baseline: 1.8973x; 1.0476x over previous
#include <cuda_runtime.h>
#include <cuda_fp16.h>
#include <math.h>
#include <stdint.h>

// ---------------------------------------------------------------------------
// Problem constants
// ---------------------------------------------------------------------------
#define BQ    8
#define MTOT  32768
#define CDIM  512
#define TDIM  768
#define KTXT  128
#define HID   2048
#define TOPM  5
#define TEMP_INV (1.0f/0.07f)
#define LN_EPS 1e-5f
#define WSCALE 256.0f
#define WINV   (1.0f/256.0f)

// ---------------------------------------------------------------------------
// Scratch (device globals)
// ---------------------------------------------------------------------------
static __device__ float    g_visln[MTOT * CDIM];
static __device__ uint32_t g_vh[MTOT * CDIM / 2];
static __device__ uint32_t g_vl[MTOT * CDIM / 2];
static __device__ float    g_X [MTOT * CDIM];
static __device__ uint32_t g_Xh[MTOT * CDIM / 2];
static __device__ uint32_t g_Hh[(size_t)MTOT * HID / 2];
static __device__ float    g_sim[(size_t)MTOT * KTXT];      // raw sim (16 MB)
static __device__ float    g_keyt [BQ * KTXT * TDIM];
static __device__ float    g_value[BQ * KTXT * CDIM];
static __device__ float    g_P [BQ * CDIM * KTXT];
static __device__ float    g_G [CDIM * CDIM];
static __device__ uint32_t g_Gh [CDIM * CDIM / 2];
static __device__ uint32_t g_Gl [CDIM * CDIM / 2];
static __device__ uint32_t g_Ph [BQ * KTXT * CDIM / 2];     // per-batch P planes
static __device__ uint32_t g_Pl [BQ * KTXT * CDIM / 2];
static __device__ uint32_t g_W1h[(size_t)HID * CDIM / 2];
static __device__ uint32_t g_W1l[(size_t)HID * CDIM / 2];
static __device__ uint32_t g_W2h[(size_t)CDIM * HID / 2];
static __device__ uint32_t g_W2l[(size_t)CDIM * HID / 2];
static __device__ float    g_pb [BQ * KTXT];
static __device__ float    g_wb2[CDIM];
static __device__ float    g_nb2[1];
static __device__ float    g_qn2[MTOT];

// ---------------------------------------------------------------------------
// Helpers
// ---------------------------------------------------------------------------
__device__ __forceinline__ uint32_t packh2(float x, float y) {
    __half2 h = __floats2half2_rn(x, y);
    return *reinterpret_cast<uint32_t*>(&h);
}

__device__ __forceinline__ void wsplit2(float x, float y,
                                        uint32_t& hi, uint32_t& lo) {
    float sx = x * WSCALE, sy = y * WSCALE;
    __half hx = __float2half_rn(sx);
    __half hy = __float2half_rn(sy);
    float rx = sx - __half2float(hx);
    float ry = sy - __half2float(hy);
    __half2 h2 = __halves2half2(hx, hy);
    __half2 l2 = __floats2half2_rn(rx, ry);
    hi = *reinterpret_cast<uint32_t*>(&h2);
    lo = *reinterpret_cast<uint32_t*>(&l2);
}

// activation split (unscaled): hi = fp16(x), lo = fp16(x - hi)
__device__ __forceinline__ void asplit2(float x, float y,
                                        uint32_t& hi, uint32_t& lo) {
    __half hx = __float2half_rn(x);
    __half hy = __float2half_rn(y);
    float rx = x - __half2float(hx);
    float ry = y - __half2float(hy);
    __half2 h2 = __halves2half2(hx, hy);
    __half2 l2 = __floats2half2_rn(rx, ry);
    hi = *reinterpret_cast<uint32_t*>(&h2);
    lo = *reinterpret_cast<uint32_t*>(&l2);
}

__device__ __forceinline__ void mma_f16(float* c, const uint32_t* a, const uint32_t* b) {
    asm volatile(
        "mma.sync.aligned.m16n8k16.row.col.f32.f16.f16.f32 "
        "{%0,%1,%2,%3}, {%4,%5,%6,%7}, {%8,%9}, {%0,%1,%2,%3};\n"
        : "+f"(c[0]), "+f"(c[1]), "+f"(c[2]), "+f"(c[3])
        : "r"(a[0]), "r"(a[1]), "r"(a[2]), "r"(a[3]), "r"(b[0]), "r"(b[1]));
}

__device__ __forceinline__ uint32_t smem_u32(const void* p) {
    uint32_t a;
    asm("{ .reg .u64 t; cvta.to.shared.u64 t, %1; cvt.u32.u64 %0, t; }"
        : "=r"(a) : "l"(p));
    return a;
}

__device__ __forceinline__ void ldsm_x4(uint32_t& r0, uint32_t& r1,
                                        uint32_t& r2, uint32_t& r3,
                                        uint32_t addr) {
    asm volatile(
        "ldmatrix.sync.aligned.m8n8.x4.shared.b16 {%0,%1,%2,%3}, [%4];"
        : "=r"(r0), "=r"(r1), "=r"(r2), "=r"(r3) : "r"(addr));
}

__device__ __forceinline__ void cp16(uint32_t* dst_smem, const uint32_t* src) {
    uint32_t s = (uint32_t)__cvta_generic_to_shared(dst_smem);
    asm volatile("cp.async.cg.shared.global [%0], [%1], 16;\n" :: "r"(s), "l"(src));
}
__device__ __forceinline__ void cp_commit() {
    asm volatile("cp.async.commit_group;\n");
}
__device__ __forceinline__ void cp_wait1() {
    asm volatile("cp.async.wait_group 1;\n");
}

// ---------------------------------------------------------------------------
// Kernel: text prep — keyt = l2norm(text), value = text @ Wv + bv
// ---------------------------------------------------------------------------
__global__ __launch_bounds__(256) void prep_text_kernel(
    const float* __restrict__ text, const float* __restrict__ Wv,
    const float* __restrict__ bv)
{
    __shared__ float ts[8][TDIM];
    int tid = threadIdx.x, lane = tid & 31, warp = tid >> 5;
    int b  = blockIdx.x >> 4;
    int kb = (blockIdx.x & 15) * 8;
    const float* tb = text + ((size_t)b * KTXT + kb) * TDIM;

    #pragma unroll
    for (int i = 0; i < 24; i++) {
        int lin = tid + 256 * i;
        int r = lin / TDIM, c = lin % TDIM;
        ts[r][c] = tb[(size_t)r * TDIM + c];
    }
    __syncthreads();

    {
        int r = warp;
        float s = 0.f;
        for (int i = lane; i < TDIM; i += 32) { float v = ts[r][i]; s += v * v; }
        #pragma unroll
        for (int o = 16; o; o >>= 1) s += __shfl_xor_sync(0xffffffffu, s, o);
        float inv = 1.0f / fmaxf(sqrtf(s), 1e-12f);
        float* kr = g_keyt + ((size_t)b * KTXT + kb + r) * TDIM;
        for (int i = lane; i < TDIM; i += 32) kr[i] = ts[r][i] * inv;
    }

    float acc[8][2];
    #pragma unroll
    for (int r = 0; r < 8; r++) { acc[r][0] = 0.f; acc[r][1] = 0.f; }
    int c0 = tid, c1 = tid + 256;
    for (int t = 0; t < TDIM; t++) {
        float w0 = Wv[(size_t)t * CDIM + c0];
        float w1 = Wv[(size_t)t * CDIM + c1];
        #pragma unroll
        for (int r = 0; r < 8; r++) {
            float tv = ts[r][t];
            acc[r][0] += tv * w0;
            acc[r][1] += tv * w1;
        }
    }
    float bb0 = bv[c0], bb1 = bv[c1];
    #pragma unroll
    for (int r = 0; r < 8; r++) {
        float* vr = g_value + ((size_t)b * KTXT + kb + r) * CDIM;
        vr[c0] = acc[r][0] + bb0;
        vr[c1] = acc[r][1] + bb1;
    }
}

// ---------------------------------------------------------------------------
// Kernel: small fp32 SGEMM  C[M,N] = A[M,K] @ B2[N,K]^T  (for P and G)
// ---------------------------------------------------------------------------
__global__ __launch_bounds__(256) void sgemm_tn_kernel(
    const float* __restrict__ A, const float* __restrict__ B2,
    float* __restrict__ C, int Kd, int N,
    size_t aStride, size_t bStride, size_t cStride)
{
    __shared__ float As[8][128];
    __shared__ float Bs[8][128];
    int tid = threadIdx.x;
    int tx = tid & 15, ty = tid >> 4;
    int bn = blockIdx.x, bm = blockIdx.y, bz = blockIdx.z;
    const float* Ab = A  + (size_t)bz * aStride + (size_t)bm * 128 * Kd;
    const float* Bb = B2 + (size_t)bz * bStride + (size_t)bn * 128 * Kd;
    int l_r = tid >> 1, l_k = (tid & 1) * 4;

    float acc[8][8];
    #pragma unroll
    for (int i = 0; i < 8; i++)
        #pragma unroll
        for (int j = 0; j < 8; j++) acc[i][j] = 0.f;

    for (int k0 = 0; k0 < Kd; k0 += 8) {
        float4 av = *(const float4*)(Ab + (size_t)l_r * Kd + k0 + l_k);
        As[l_k + 0][l_r] = av.x;
        As[l_k + 1][l_r] = av.y;
        As[l_k + 2][l_r] = av.z;
        As[l_k + 3][l_r] = av.w;
        float4 bv = *(const float4*)(Bb + (size_t)l_r * Kd + k0 + l_k);
        Bs[l_k + 0][l_r] = bv.x;
        Bs[l_k + 1][l_r] = bv.y;
        Bs[l_k + 2][l_r] = bv.z;
        Bs[l_k + 3][l_r] = bv.w;
        __syncthreads();
        #pragma unroll
        for (int k = 0; k < 8; k++) {
            float ar[8], br[8];
            #pragma unroll
            for (int i = 0; i < 4; i++) {
                ar[i]     = As[k][ty * 4 + i];
                ar[4 + i] = As[k][64 + ty * 4 + i];
                br[i]     = Bs[k][tx * 4 + i];
                br[4 + i] = Bs[k][64 + tx * 4 + i];
            }
            #pragma unroll
            for (int i = 0; i < 8; i++)
                #pragma unroll
                for (int j = 0; j < 8; j++) acc[i][j] += ar[i] * br[j];
        }
        __syncthreads();
    }

    float* Cb = C + (size_t)bz * cStride;
    #pragma unroll
    for (int gi = 0; gi < 2; gi++)
        #pragma unroll
        for (int ii = 0; ii < 4; ii++) {
            int r = bm * 128 + gi * 64 + ty * 4 + ii;
            #pragma unroll
            for (int gj = 0; gj < 2; gj++) {
                int cb = bn * 128 + gj * 64 + tx * 4;
                float4 o;
                o.x = acc[gi * 4 + ii][gj * 4 + 0];
                o.y = acc[gi * 4 + ii][gj * 4 + 1];
                o.z = acc[gi * 4 + ii][gj * 4 + 2];
                o.w = acc[gi * 4 + ii][gj * 4 + 3];
                *(float4*)(Cb + (size_t)r * N + cb) = o;
            }
        }
}

// ---------------------------------------------------------------------------
// Kernel: prep_small2 — warp-per-row dots
// ---------------------------------------------------------------------------
__global__ __launch_bounds__(256) void prep_small2_kernel(
    const float* __restrict__ Wq, const float* __restrict__ bq)
{
    int gw = blockIdx.x * 8 + (threadIdx.x >> 5);
    int lane = threadIdx.x & 31;
    if (gw > 1536) return;
    const float4* bp = (const float4*)bq;
    float s = 0.f;
    if (gw < 1024) {
        const float4* kr = (const float4*)(g_keyt + (size_t)gw * TDIM);
        #pragma unroll
        for (int i = 0; i < 6; i++) {
            float4 a = kr[lane + 32 * i], c = bp[lane + 32 * i];
            s += a.x * c.x + a.y * c.y + a.z * c.z + a.w * c.w;
        }
        #pragma unroll
        for (int o = 16; o; o >>= 1) s += __shfl_xor_sync(0xffffffffu, s, o);
        if (!lane) g_pb[gw] = s;
    } else if (gw < 1536) {
        int c = gw - 1024;
        const float4* wr = (const float4*)(Wq + (size_t)c * TDIM);
        #pragma unroll
        for (int i = 0; i < 6; i++) {
            float4 a = wr[lane + 32 * i], d = bp[lane + 32 * i];
            s += a.x * d.x + a.y * d.y + a.z * d.z + a.w * d.w;
        }
        #pragma unroll
        for (int o = 16; o; o >>= 1) s += __shfl_xor_sync(0xffffffffu, s, o);
        if (!lane) g_wb2[c] = 2.0f * s;
    } else {
        #pragma unroll
        for (int i = 0; i < 6; i++) {
            float4 a = bp[lane + 32 * i];
            s += a.x * a.x + a.y * a.y + a.z * a.z + a.w * a.w;
        }
        #pragma unroll
        for (int o = 16; o; o >>= 1) s += __shfl_xor_sync(0xffffffffu, s, o);
        if (!lane) g_nb2[0] = s;
    }
}

// ---------------------------------------------------------------------------
// Kernel: convert fp32 B [K][N] -> fp16 hi/lo planes [N][K/2], scaled x256
// (with optional batch strides via blockIdx.z)
// ---------------------------------------------------------------------------
__global__ __launch_bounds__(256) void convert_b_kernel(
    const float* __restrict__ in, uint32_t* __restrict__ oh,
    uint32_t* __restrict__ ol, int Kd, int N,
    size_t inStride, size_t outStride)
{
    __shared__ float t[64][65];
    int k0 = blockIdx.y * 64, n0 = blockIdx.x * 64;
    int bz = blockIdx.z;
    const float* inb = in + (size_t)bz * inStride;
    int tid = threadIdx.x;
    #pragma unroll
    for (int i = 0; i < 16; i++) {
        int lin = tid + 256 * i;
        int r = lin >> 6, c = lin & 63;
        t[r][c] = inb[(size_t)(k0 + r) * N + n0 + c];
    }
    __syncthreads();
    int K2 = Kd >> 1;
    #pragma unroll
    for (int i = 0; i < 8; i++) {
        int lin = tid + 256 * i;
        int n = lin >> 5, kp = lin & 31;
        uint32_t h, l;
        wsplit2(t[2 * kp][n], t[2 * kp + 1][n], h, l);
        size_t o = (size_t)bz * outStride + (size_t)(n0 + n) * K2 + (k0 >> 1) + kp;
        oh[o] = h;  ol[o] = l;
    }
}

// ---------------------------------------------------------------------------
// Kernel: LayerNorm -> fp32 + fp16 hi/lo planes
// ---------------------------------------------------------------------------
__global__ __launch_bounds__(256) void ln_kernel(
    const float* __restrict__ in, const float* __restrict__ g,
    const float* __restrict__ be, float* __restrict__ out,
    uint32_t* __restrict__ oh, uint32_t* __restrict__ ol)
{
    int warp = threadIdx.x >> 5, lane = threadIdx.x & 31;
    size_t row = (size_t)blockIdx.x * 8 + warp;
    const float4* p = (const float4*)(in + row * CDIM);
    float4 x[4];
    float s = 0.f, s2 = 0.f;
    #pragma unroll
    for (int i = 0; i < 4; i++) {
        x[i] = p[lane + 32 * i];
        s  += x[i].x + x[i].y + x[i].z + x[i].w;
        s2 += x[i].x * x[i].x + x[i].y * x[i].y + x[i].z * x[i].z + x[i].w * x[i].w;
    }
    #pragma unroll
    for (int o = 16; o; o >>= 1) {
        s  += __shfl_xor_sync(0xffffffffu, s, o);
        s2 += __shfl_xor_sync(0xffffffffu, s2, o);
    }
    float mu  = s * (1.0f / CDIM);
    float var = s2 * (1.0f / CDIM) - mu * mu;
    float rs  = rsqrtf(var + LN_EPS);
    float4* o4 = (float4*)(out + row * CDIM);
    const float4* gp = (const float4*)g;
    const float4* bp = (const float4*)be;
    #pragma unroll
    for (int i = 0; i < 4; i++) {
        int c4 = lane + 32 * i;
        float4 gv = gp[c4], bv = bp[c4], r;
        r.x = (x[i].x - mu) * rs * gv.x + bv.x;
        r.y = (x[i].y - mu) * rs * gv.y + bv.y;
        r.z = (x[i].z - mu) * rs * gv.z + bv.z;
        r.w = (x[i].w - mu) * rs * gv.w + bv.w;
        o4[c4] = r;
        uint2 h, l;
        asplit2(r.x, r.y, h.x, l.x);
        asplit2(r.z, r.w, h.y, l.y);
        *(uint2*)(oh + row * (CDIM / 2) + 2 * c4) = h;
        *(uint2*)(ol + row * (CDIM / 2) + 2 * c4) = l;
    }
}

// ---------------------------------------------------------------------------
// fp16 tensor-core GEMM, products: Ah*Bh [+ Ah*Bl if BP==2] [+ Al*Bh if AP==2]
// B pre-scaled x256. 256x128 block tile, 512 threads, warp tile 64x32.
// MODE 0: sim -> Out fp32 [M][128], per-batch B (batch = bm>>4)
// MODE 1: gelu(acc/256+bias) -> fp16 plane Oh
// MODE 2: acc/256+bias+Res -> Out fp32
// MODE 3: qn2[r] += sum_c (acc/256)*(2*Res - fp16(Res)) + bias*Res
// ---------------------------------------------------------------------------
#define A_PLANE 5120          // 256 rows * 20 u32
#define B_PLANE 2560          // 128 rows * 20 u32

template <int MODE, int AP, int BP>
__global__ __launch_bounds__(512) void tgemm4_kernel(
    const uint32_t* __restrict__ Ah, const uint32_t* __restrict__ Al,
    const uint32_t* __restrict__ Bh, const uint32_t* __restrict__ Bl,
    const float* __restrict__ bias, const float* __restrict__ Res,
    float* __restrict__ Out, uint32_t* __restrict__ Oh,
    int M, int N, int Kd)
{
    const int STG = AP * A_PLANE + BP * B_PLANE;
    extern __shared__ uint32_t sm[];
    uint32_t sbase = smem_u32(sm);
    int K2 = Kd >> 1;
    int tid = threadIdx.x, lane = tid & 31, warp = tid >> 5;
    int g  = lane >> 2, tg = lane & 3;
    int wm = warp >> 2, wn = warp & 3;
    int m0 = wm * 64,  n0 = wn * 32;
    int bn = blockIdx.x, bm = blockIdx.y;

    const uint32_t* AhB = Ah + (size_t)bm * 256 * K2;
    const uint32_t* AlB = (AP == 2) ? Al + (size_t)bm * 256 * K2 : nullptr;
    size_t bofs = (size_t)bn * 128 * K2;
    if (MODE == 0) bofs += (size_t)(bm >> 4) * KTXT * K2;   // per-batch B
    const uint32_t* BhB = Bh + bofs;
    const uint32_t* BlB = (BP == 2) ? Bl + bofs : nullptr;

    uint32_t a_ld = (uint32_t)((m0 + (lane & 7) + ((lane >> 3) & 1) * 8) * 20
                               + ((lane >> 4) & 1) * 4) * 4;
    uint32_t b_ld = (uint32_t)((n0 + (lane & 7) + ((lane >> 4) & 1) * 8) * 20
                               + ((lane >> 3) & 1) * 4) * 4;

    float acc[4][4][4];
    #pragma unroll
    for (int mi = 0; mi < 4; mi++)
        #pragma unroll
        for (int ni = 0; ni < 4; ni++)
            #pragma unroll
            for (int r = 0; r < 4; r++) acc[mi][ni][r] = 0.f;

    int nT = K2 / 16;
    const int AOFF = AP * A_PLANE;   // B planes start after A planes

    #pragma unroll
    for (int pf = 0; pf < 2; pf++) {
        uint32_t* st = sm + pf * STG;
        int kp0 = pf * 16;
        #pragma unroll
        for (int c = 0; c < 2; c++) {
            int idx = tid + 512 * c;
            int row = idx >> 2, kb = (idx & 3) * 4;
            size_t go = (size_t)row * K2 + kp0 + kb;
            cp16(st + row * 20 + kb, AhB + go);
            if (AP == 2) cp16(st + A_PLANE + row * 20 + kb, AlB + go);
        }
        {
            int row = tid >> 2, kb = (tid & 3) * 4;
            size_t go = (size_t)row * K2 + kp0 + kb;
            int so = row * 20 + kb;
            cp16(st + AOFF + so, BhB + go);
            if (BP == 2) cp16(st + AOFF + B_PLANE + so, BlB + go);
        }
        cp_commit();
    }

    for (int t = 0; t < nT; t++) {
        cp_wait1();
        __syncthreads();
        uint32_t stb = sbase + (uint32_t)((t & 1) * STG * 4);

        #pragma unroll
        for (int ks = 0; ks < 2; ks++) {
            uint32_t ksoff = (uint32_t)(ks * 32);
            uint32_t a[4][4], al[4][4], bh[4][2], bl[4][2];
            #pragma unroll
            for (int mi = 0; mi < 4; mi++) {
                uint32_t ao = stb + a_ld + ksoff + (uint32_t)(mi * 16 * 80);
                ldsm_x4(a[mi][0], a[mi][1], a[mi][2], a[mi][3], ao);
                if (AP == 2)
                    ldsm_x4(al[mi][0], al[mi][1], al[mi][2], al[mi][3],
                            ao + A_PLANE * 4);
            }
            #pragma unroll
            for (int p = 0; p < 2; p++) {
                uint32_t bo = stb + AOFF * 4 + b_ld + ksoff + (uint32_t)(p * 16 * 80);
                ldsm_x4(bh[2 * p][0], bh[2 * p][1], bh[2 * p + 1][0], bh[2 * p + 1][1], bo);
                if (BP == 2)
                    ldsm_x4(bl[2 * p][0], bl[2 * p][1], bl[2 * p + 1][0], bl[2 * p + 1][1],
                            bo + B_PLANE * 4);
            }
            #pragma unroll
            for (int mi = 0; mi < 4; mi++)
                #pragma unroll
                for (int ni = 0; ni < 4; ni++) {
                    mma_f16(acc[mi][ni], a[mi], bh[ni]);
                    if (BP == 2) mma_f16(acc[mi][ni], a[mi], bl[ni]);
                    if (AP == 2) mma_f16(acc[mi][ni], al[mi], bh[ni]);
                }
        }
        __syncthreads();
        if (t + 2 < nT) {
            uint32_t* dst = sm + (t & 1) * STG;
            int kp0 = (t + 2) * 16;
            #pragma unroll
            for (int c = 0; c < 2; c++) {
                int idx = tid + 512 * c;
                int row = idx >> 2, kb = (idx & 3) * 4;
                size_t go = (size_t)row * K2 + kp0 + kb;
                cp16(dst + row * 20 + kb, AhB + go);
                if (AP == 2) cp16(dst + A_PLANE + row * 20 + kb, AlB + go);
            }
            {
                int row = tid >> 2, kb = (tid & 3) * 4;
                size_t go = (size_t)row * K2 + kp0 + kb;
                int so = row * 20 + kb;
                cp16(dst + AOFF + so, BhB + go);
                if (BP == 2) cp16(dst + AOFF + B_PLANE + so, BlB + go);
            }
        }
        cp_commit();
    }

    if (MODE == 3) {
        #pragma unroll
        for (int mi = 0; mi < 4; mi++)
            #pragma unroll
            for (int half = 0; half < 2; half++) {
                int r = bm * 256 + m0 + mi * 16 + g + half * 8;
                float part = 0.f;
                #pragma unroll
                for (int ni = 0; ni < 4; ni++) {
                    int c = bn * 128 + n0 + ni * 8 + 2 * tg;
                    #pragma unroll
                    for (int jj = 0; jj < 2; jj++) {
                        float rv = Res[(size_t)r * N + c + jj];
                        float vh = __half2float(__float2half_rn(rv));
                        float z  = acc[mi][ni][half * 2 + jj] * WINV;
                        part += z * (2.0f * rv - vh) + bias[c + jj] * rv;
                    }
                }
                part += __shfl_xor_sync(0xffffffffu, part, 1);
                part += __shfl_xor_sync(0xffffffffu, part, 2);
                if (tg == 0) atomicAdd(&g_qn2[r], part);
            }
        return;
    }

    #pragma unroll
    for (int mi = 0; mi < 4; mi++)
        #pragma unroll
        for (int half = 0; half < 2; half++) {
            int r = bm * 256 + m0 + mi * 16 + g + half * 8;
            #pragma unroll
            for (int ni = 0; ni < 4; ni++) {
                int c = bn * 128 + n0 + ni * 8 + 2 * tg;
                float v0 = acc[mi][ni][half * 2 + 0] * WINV;
                float v1 = acc[mi][ni][half * 2 + 1] * WINV;
                if (MODE == 0) {
                    float2 ov = { v0, v1 };
                    *(float2*)(Out + (size_t)r * KTXT + c) = ov;
                } else if (MODE == 1) {
                    v0 += bias[c];  v1 += bias[c + 1];
                    v0 = v0 * normcdff(v0);
                    v1 = v1 * normcdff(v1);
                    Oh[(size_t)r * (N >> 1) + (c >> 1)] = packh2(v0, v1);
                } else {
                    v0 += bias[c]     + Res[(size_t)r * N + c];
                    v1 += bias[c + 1] + Res[(size_t)r * N + c + 1];
                    float2 ov = { v0, v1 };
                    *(float2*)(Out + (size_t)r * N + c) = ov;
                }
            }
        }
}

// ---------------------------------------------------------------------------
// Attention epilogue: read precomputed sim, topk/softmax/gather/LN2.
// 32 tokens/block, 256 threads (warp = 4 rows).
// ---------------------------------------------------------------------------
__global__ __launch_bounds__(256) void attn_kernel(
    const float* __restrict__ resid, const float* __restrict__ g2,
    const float* __restrict__ be2)
{
    __shared__ float invn[32];
    __shared__ float pb_s[KTXT];
    int tid = threadIdx.x, lane = tid & 31, warp = tid >> 5;
    int t0 = blockIdx.x * 32;
    int b  = t0 >> 12;

    if (tid < 32) {
        float qn2 = g_qn2[t0 + tid] + g_nb2[0];
        float n = sqrtf(fmaxf(qn2, 0.f));
        invn[tid] = 1.0f / fmaxf(n, 1e-12f);
    }
    if (tid < KTXT) pb_s[tid] = g_pb[b * KTXT + tid];
    __syncthreads();

    for (int rr = 0; rr < 4; rr++) {
        int row = warp * 4 + rr;
        float sc = invn[row];
        const float* sp = g_sim + (size_t)(t0 + row) * KTXT;
        float tv[4];
        #pragma unroll
        for (int j = 0; j < 4; j++) {
            int col = lane + 32 * j;
            tv[j] = (sp[col] + pb_s[col]) * sc;
        }

        float mval[TOPM]; int midx[TOPM];
        #pragma unroll
        for (int it = 0; it < TOPM; it++) {
            float lm = tv[0]; int lj = 0;
            #pragma unroll
            for (int j = 1; j < 4; j++) if (tv[j] > lm) { lm = tv[j]; lj = j; }
            int li = lane + 32 * lj;
            #pragma unroll
            for (int o = 16; o; o >>= 1) {
                float ov = __shfl_xor_sync(0xffffffffu, lm, o);
                int   oi = __shfl_xor_sync(0xffffffffu, li, o);
                if (ov > lm || (ov == lm && oi < li)) { lm = ov; li = oi; }
            }
            mval[it] = lm; midx[it] = li;
            if ((li & 31) == lane) tv[li >> 5] = -INFINITY;
        }

        float p[TOPM], psum = 0.f;
        #pragma unroll
        for (int it = 0; it < TOPM; it++) {
            p[it] = expf((mval[it] - mval[0]) * TEMP_INV);
            psum += p[it];
        }
        float rnorm = 1.0f / psum;

        float f[16];
        #pragma unroll
        for (int i = 0; i < 16; i++) f[i] = 0.f;
        const float* Vb = g_value + (size_t)b * KTXT * CDIM;
        #pragma unroll
        for (int it = 0; it < TOPM; it++) {
            const float4* vr = (const float4*)(Vb + (size_t)midx[it] * CDIM + lane * 16);
            float a_ = p[it] * rnorm;
            #pragma unroll
            for (int j = 0; j < 4; j++) {
                float4 v = vr[j];
                f[4 * j + 0] += a_ * v.x;
                f[4 * j + 1] += a_ * v.y;
                f[4 * j + 2] += a_ * v.z;
                f[4 * j + 3] += a_ * v.w;
            }
        }

        const float4* rp = (const float4*)(resid + (size_t)(t0 + row) * CDIM + lane * 16);
        float s = 0.f, s2 = 0.f;
        #pragma unroll
        for (int j = 0; j < 4; j++) {
            float4 v = rp[j];
            f[4 * j + 0] += v.x;  f[4 * j + 1] += v.y;
            f[4 * j + 2] += v.z;  f[4 * j + 3] += v.w;
        }
        #pragma unroll
        for (int i = 0; i < 16; i++) { s += f[i]; s2 += f[i] * f[i]; }
        #pragma unroll
        for (int o = 16; o; o >>= 1) {
            s  += __shfl_xor_sync(0xffffffffu, s, o);
            s2 += __shfl_xor_sync(0xffffffffu, s2, o);
        }
        float mu  = s * (1.0f / CDIM);
        float var = s2 * (1.0f / CDIM) - mu * mu;
        float rstd = rsqrtf(var + LN_EPS);

        size_t rbase = (size_t)(t0 + row);
        float*    xp = g_X  + rbase * CDIM + lane * 16;
        uint32_t* xh = g_Xh + rbase * (CDIM / 2) + lane * 8;
        #pragma unroll
        for (int j = 0; j < 4; j++) {
            int c = lane * 16 + 4 * j;
            float4 o;
            o.x = (f[4 * j + 0] - mu) * rstd * g2[c + 0] + be2[c + 0];
            o.y = (f[4 * j + 1] - mu) * rstd * g2[c + 1] + be2[c + 1];
            o.z = (f[4 * j + 2] - mu) * rstd * g2[c + 2] + be2[c + 2];
            o.w = (f[4 * j + 3] - mu) * rstd * g2[c + 3] + be2[c + 3];
            *(float4*)(xp + 4 * j) = o;
            uint2 h;
            h.x = packh2(o.x, o.y);
            h.y = packh2(o.z, o.w);
            *(uint2*)(xh + 2 * j) = h;
        }
    }
}

// ---------------------------------------------------------------------------
// Launch
// ---------------------------------------------------------------------------
extern "C" void kernel_launch(void* const* d_in, const int* in_sizes, int n_in,
                              void* d_out, int out_size)
{
    const float* vis  = (const float*)d_in[0];
    const float* text = (const float*)d_in[1];
    const float* Wq   = (const float*)d_in[2];
    const float* bq   = (const float*)d_in[3];
    const float* Wv   = (const float*)d_in[4];
    const float* bv   = (const float*)d_in[5];
    const float* W1   = (const float*)d_in[6];
    const float* b1   = (const float*)d_in[7];
    const float* W2   = (const float*)d_in[8];
    const float* b2   = (const float*)d_in[9];
    const float* g1   = (const float*)d_in[10];
    const float* be1  = (const float*)d_in[11];
    const float* g2   = (const float*)d_in[12];
    const float* be2  = (const float*)d_in[13];
    float* out = (float*)d_out;

    float *p_visln, *p_X, *p_P, *p_G, *p_keyt, *p_wb2, *p_qn2, *p_sim;
    uint32_t *p_vh, *p_vl, *p_Xh, *p_Hh;
    uint32_t *p_Gh, *p_Gl, *p_Ph, *p_Pl, *p_W1h, *p_W1l, *p_W2h, *p_W2l;
    cudaGetSymbolAddress((void**)&p_visln, g_visln);
    cudaGetSymbolAddress((void**)&p_X,     g_X);
    cudaGetSymbolAddress((void**)&p_P,     g_P);
    cudaGetSymbolAddress((void**)&p_G,     g_G);
    cudaGetSymbolAddress((void**)&p_keyt,  g_keyt);
    cudaGetSymbolAddress((void**)&p_wb2,   g_wb2);
    cudaGetSymbolAddress((void**)&p_qn2,   g_qn2);
    cudaGetSymbolAddress((void**)&p_sim,   g_sim);
    cudaGetSymbolAddress((void**)&p_vh,    g_vh);
    cudaGetSymbolAddress((void**)&p_vl,    g_vl);
    cudaGetSymbolAddress((void**)&p_Xh,    g_Xh);
    cudaGetSymbolAddress((void**)&p_Hh,    g_Hh);
    cudaGetSymbolAddress((void**)&p_Gh,    g_Gh);
    cudaGetSymbolAddress((void**)&p_Gl,    g_Gl);
    cudaGetSymbolAddress((void**)&p_Ph,    g_Ph);
    cudaGetSymbolAddress((void**)&p_Pl,    g_Pl);
    cudaGetSymbolAddress((void**)&p_W1h,   g_W1h);
    cudaGetSymbolAddress((void**)&p_W1l,   g_W1l);
    cudaGetSymbolAddress((void**)&p_W2h,   g_W2h);
    cudaGetSymbolAddress((void**)&p_W2l,   g_W2l);

    const int SMEM_1P  = 2 * (1 * A_PLANE + 1 * B_PLANE) * 4;   // 61440
    const int SMEM_Q   = 2 * (1 * A_PLANE + 2 * B_PLANE) * 4;   // 81920
    const int SMEM_SIM = 2 * (2 * A_PLANE + 2 * B_PLANE) * 4;   // 122880
    cudaFuncSetAttribute((const void*)tgemm4_kernel<0, 2, 2>,
                         cudaFuncAttributeMaxDynamicSharedMemorySize, SMEM_SIM);
    cudaFuncSetAttribute((const void*)tgemm4_kernel<1, 1, 1>,
                         cudaFuncAttributeMaxDynamicSharedMemorySize, SMEM_1P);
    cudaFuncSetAttribute((const void*)tgemm4_kernel<2, 1, 1>,
                         cudaFuncAttributeMaxDynamicSharedMemorySize, SMEM_1P);
    cudaFuncSetAttribute((const void*)tgemm4_kernel<3, 1, 2>,
                         cudaFuncAttributeMaxDynamicSharedMemorySize, SMEM_Q);

    // 1) text prep (keyt, value)
    prep_text_kernel<<<(BQ * KTXT) / 8, 256>>>(text, Wv, bv);
    // 2) P_b = Wq @ keyt_b^T per batch (fp32)
    sgemm_tn_kernel<<<dim3(1, CDIM / 128, BQ), 256>>>(
        Wq, p_keyt, p_P, TDIM, KTXT,
        0, (size_t)KTXT * TDIM, (size_t)CDIM * KTXT);
    // 3) G = Wq @ Wq^T (fp32)
    sgemm_tn_kernel<<<dim3(CDIM / 128, CDIM / 128, 1), 256>>>(
        Wq, Wq, p_G, TDIM, CDIM, 0, 0, 0);
    // 4) pb, wb2, nb2
    prep_small2_kernel<<<193, 256>>>(Wq, bq);
    // 5) convert weights to fp16 hi/lo planes (x256)
    convert_b_kernel<<<dim3(CDIM / 64, CDIM / 64), 256>>>(
        p_G, p_Gh, p_Gl, CDIM, CDIM, 0, 0);
    convert_b_kernel<<<dim3(HID / 64, CDIM / 64), 256>>>(
        W1, p_W1h, p_W1l, CDIM, HID, 0, 0);
    convert_b_kernel<<<dim3(CDIM / 64, HID / 64), 256>>>(
        W2, p_W2h, p_W2l, HID, CDIM, 0, 0);
    //    P per-batch: [CDIM][KTXT] -> [KTXT][CDIM/2] planes
    convert_b_kernel<<<dim3(KTXT / 64, CDIM / 64, BQ), 256>>>(
        p_P, p_Ph, p_Pl, CDIM, KTXT,
        (size_t)CDIM * KTXT, (size_t)KTXT * CDIM / 2);
    // 6) LN1 -> visln fp32 + vh/vl fp16 planes
    ln_kernel<<<MTOT / 8, 256>>>(vis, g1, be1, p_visln, p_vh, p_vl);
    // 7) qn2 (AP=1, BP=2)
    cudaMemsetAsync(p_qn2, 0, MTOT * sizeof(float));
    tgemm4_kernel<3, 1, 2><<<dim3(CDIM / 128, MTOT / 256), 512, SMEM_Q>>>(
        p_vh, nullptr, p_Gh, p_Gl, p_wb2, p_visln, nullptr, nullptr,
        MTOT, CDIM, CDIM);
    // 8) sim = (vh+vl) @ P_b planes (3 products) -> g_sim fp32
    tgemm4_kernel<0, 2, 2><<<dim3(1, MTOT / 256), 512, SMEM_SIM>>>(
        p_vh, p_vl, p_Ph, p_Pl, nullptr, nullptr, p_sim, nullptr,
        MTOT, KTXT, CDIM);
    // 9) attention epilogue + residual + LN2 -> X fp32 + Xh fp16
    attn_kernel<<<MTOT / 32, 256>>>(vis, g2, be2);
    // 10) H = gelu(X @ W1 + b1) -> fp16 plane Hh
    tgemm4_kernel<1, 1, 1><<<dim3(HID / 128, MTOT / 256), 512, SMEM_1P>>>(
        p_Xh, nullptr, p_W1h, p_W1l, b1, nullptr, nullptr, p_Hh,
        MTOT, HID, CDIM);
    // 11) out = X + H @ W2 + b2
    tgemm4_kernel<2, 1, 1><<<dim3(CDIM / 128, MTOT / 256), 512, SMEM_1P>>>(
        p_Hh, nullptr, p_W2h, p_W2l, b2, p_X, out, nullptr,
        MTOT, CDIM, HID);
}

// round 13
// speedup vs baseline: 1.9744x; 1.0406x over previous
#include <cuda_runtime.h>
#include <cuda_fp16.h>
#include <math.h>
#include <stdint.h>

// ---------------------------------------------------------------------------
// Problem constants
// ---------------------------------------------------------------------------
#define BQ    8
#define MTOT  32768
#define CDIM  512
#define TDIM  768
#define KTXT  128
#define HID   2048
#define TOPM  5
#define TEMP_INV (1.0f/0.07f)
#define LN_EPS 1e-5f
#define WSCALE 256.0f
#define WINV   (1.0f/256.0f)

// ---------------------------------------------------------------------------
// Scratch (device globals)
// ---------------------------------------------------------------------------
static __device__ uint32_t g_vh[MTOT * CDIM / 2];
static __device__ uint32_t g_vl[MTOT * CDIM / 2];
static __device__ float    g_X [MTOT * CDIM];
static __device__ uint32_t g_Xh[MTOT * CDIM / 2];
static __device__ uint32_t g_Hh[(size_t)MTOT * HID / 2];
static __device__ float    g_sim[(size_t)MTOT * KTXT];      // raw sim (16 MB)
static __device__ float    g_keyt [BQ * KTXT * TDIM];
static __device__ float    g_value[BQ * KTXT * CDIM];
static __device__ float    g_P [BQ * CDIM * KTXT];
static __device__ float    g_G [CDIM * CDIM];
static __device__ uint32_t g_Gh [CDIM * CDIM / 2];
static __device__ uint32_t g_Gl [CDIM * CDIM / 2];
static __device__ uint32_t g_Ph [BQ * KTXT * CDIM / 2];     // per-batch P planes
static __device__ uint32_t g_Pl [BQ * KTXT * CDIM / 2];
static __device__ uint32_t g_W1h[(size_t)HID * CDIM / 2];
static __device__ uint32_t g_W1l[(size_t)HID * CDIM / 2];
static __device__ uint32_t g_W2h[(size_t)CDIM * HID / 2];
static __device__ uint32_t g_W2l[(size_t)CDIM * HID / 2];
static __device__ float    g_pb [BQ * KTXT];
static __device__ float    g_wb2[CDIM];
static __device__ float    g_nb2[1];
static __device__ float    g_qn2[MTOT];

// ---------------------------------------------------------------------------
// Helpers
// ---------------------------------------------------------------------------
__device__ __forceinline__ uint32_t packh2(float x, float y) {
    __half2 h = __floats2half2_rn(x, y);
    return *reinterpret_cast<uint32_t*>(&h);
}

__device__ __forceinline__ void wsplit2(float x, float y,
                                        uint32_t& hi, uint32_t& lo) {
    float sx = x * WSCALE, sy = y * WSCALE;
    __half hx = __float2half_rn(sx);
    __half hy = __float2half_rn(sy);
    float rx = sx - __half2float(hx);
    float ry = sy - __half2float(hy);
    __half2 h2 = __halves2half2(hx, hy);
    __half2 l2 = __floats2half2_rn(rx, ry);
    hi = *reinterpret_cast<uint32_t*>(&h2);
    lo = *reinterpret_cast<uint32_t*>(&l2);
}

// activation split (unscaled): hi = fp16(x), lo = fp16(x - hi)
__device__ __forceinline__ void asplit2(float x, float y,
                                        uint32_t& hi, uint32_t& lo) {
    __half hx = __float2half_rn(x);
    __half hy = __float2half_rn(y);
    float rx = x - __half2float(hx);
    float ry = y - __half2float(hy);
    __half2 h2 = __halves2half2(hx, hy);
    __half2 l2 = __floats2half2_rn(rx, ry);
    hi = *reinterpret_cast<uint32_t*>(&h2);
    lo = *reinterpret_cast<uint32_t*>(&l2);
}

__device__ __forceinline__ void mma_f16(float* c, const uint32_t* a, const uint32_t* b) {
    asm volatile(
        "mma.sync.aligned.m16n8k16.row.col.f32.f16.f16.f32 "
        "{%0,%1,%2,%3}, {%4,%5,%6,%7}, {%8,%9}, {%0,%1,%2,%3};\n"
        : "+f"(c[0]), "+f"(c[1]), "+f"(c[2]), "+f"(c[3])
        : "r"(a[0]), "r"(a[1]), "r"(a[2]), "r"(a[3]), "r"(b[0]), "r"(b[1]));
}

__device__ __forceinline__ uint32_t smem_u32(const void* p) {
    uint32_t a;
    asm("{ .reg .u64 t; cvta.to.shared.u64 t, %1; cvt.u32.u64 %0, t; }"
        : "=r"(a) : "l"(p));
    return a;
}

__device__ __forceinline__ void ldsm_x4(uint32_t& r0, uint32_t& r1,
                                        uint32_t& r2, uint32_t& r3,
                                        uint32_t addr) {
    asm volatile(
        "ldmatrix.sync.aligned.m8n8.x4.shared.b16 {%0,%1,%2,%3}, [%4];"
        : "=r"(r0), "=r"(r1), "=r"(r2), "=r"(r3) : "r"(addr));
}

__device__ __forceinline__ void cp16(uint32_t* dst_smem, const uint32_t* src) {
    uint32_t s = (uint32_t)__cvta_generic_to_shared(dst_smem);
    asm volatile("cp.async.cg.shared.global [%0], [%1], 16;\n" :: "r"(s), "l"(src));
}
__device__ __forceinline__ void cp_commit() {
    asm volatile("cp.async.commit_group;\n");
}
__device__ __forceinline__ void cp_wait1() {
    asm volatile("cp.async.wait_group 1;\n");
}

// ---------------------------------------------------------------------------
// Kernel: text prep — keyt = l2norm(text), value = text @ Wv + bv
// ---------------------------------------------------------------------------
__global__ __launch_bounds__(256) void prep_text_kernel(
    const float* __restrict__ text, const float* __restrict__ Wv,
    const float* __restrict__ bv)
{
    __shared__ float ts[8][TDIM];
    int tid = threadIdx.x, lane = tid & 31, warp = tid >> 5;
    int b  = blockIdx.x >> 4;
    int kb = (blockIdx.x & 15) * 8;
    const float* tb = text + ((size_t)b * KTXT + kb) * TDIM;

    #pragma unroll
    for (int i = 0; i < 24; i++) {
        int lin = tid + 256 * i;
        int r = lin / TDIM, c = lin % TDIM;
        ts[r][c] = tb[(size_t)r * TDIM + c];
    }
    __syncthreads();

    {
        int r = warp;
        float s = 0.f;
        for (int i = lane; i < TDIM; i += 32) { float v = ts[r][i]; s += v * v; }
        #pragma unroll
        for (int o = 16; o; o >>= 1) s += __shfl_xor_sync(0xffffffffu, s, o);
        float inv = 1.0f / fmaxf(sqrtf(s), 1e-12f);
        float* kr = g_keyt + ((size_t)b * KTXT + kb + r) * TDIM;
        for (int i = lane; i < TDIM; i += 32) kr[i] = ts[r][i] * inv;
    }

    float acc[8][2];
    #pragma unroll
    for (int r = 0; r < 8; r++) { acc[r][0] = 0.f; acc[r][1] = 0.f; }
    int c0 = tid, c1 = tid + 256;
    for (int t = 0; t < TDIM; t++) {
        float w0 = Wv[(size_t)t * CDIM + c0];
        float w1 = Wv[(size_t)t * CDIM + c1];
        #pragma unroll
        for (int r = 0; r < 8; r++) {
            float tv = ts[r][t];
            acc[r][0] += tv * w0;
            acc[r][1] += tv * w1;
        }
    }
    float bb0 = bv[c0], bb1 = bv[c1];
    #pragma unroll
    for (int r = 0; r < 8; r++) {
        float* vr = g_value + ((size_t)b * KTXT + kb + r) * CDIM;
        vr[c0] = acc[r][0] + bb0;
        vr[c1] = acc[r][1] + bb1;
    }
}

// ---------------------------------------------------------------------------
// Kernel: small fp32 SGEMM  C[M,N] = A[M,K] @ B2[N,K]^T  (for P and G)
// ---------------------------------------------------------------------------
__global__ __launch_bounds__(256) void sgemm_tn_kernel(
    const float* __restrict__ A, const float* __restrict__ B2,
    float* __restrict__ C, int Kd, int N,
    size_t aStride, size_t bStride, size_t cStride)
{
    __shared__ float As[8][128];
    __shared__ float Bs[8][128];
    int tid = threadIdx.x;
    int tx = tid & 15, ty = tid >> 4;
    int bn = blockIdx.x, bm = blockIdx.y, bz = blockIdx.z;
    const float* Ab = A  + (size_t)bz * aStride + (size_t)bm * 128 * Kd;
    const float* Bb = B2 + (size_t)bz * bStride + (size_t)bn * 128 * Kd;
    int l_r = tid >> 1, l_k = (tid & 1) * 4;

    float acc[8][8];
    #pragma unroll
    for (int i = 0; i < 8; i++)
        #pragma unroll
        for (int j = 0; j < 8; j++) acc[i][j] = 0.f;

    for (int k0 = 0; k0 < Kd; k0 += 8) {
        float4 av = *(const float4*)(Ab + (size_t)l_r * Kd + k0 + l_k);
        As[l_k + 0][l_r] = av.x;
        As[l_k + 1][l_r] = av.y;
        As[l_k + 2][l_r] = av.z;
        As[l_k + 3][l_r] = av.w;
        float4 bv = *(const float4*)(Bb + (size_t)l_r * Kd + k0 + l_k);
        Bs[l_k + 0][l_r] = bv.x;
        Bs[l_k + 1][l_r] = bv.y;
        Bs[l_k + 2][l_r] = bv.z;
        Bs[l_k + 3][l_r] = bv.w;
        __syncthreads();
        #pragma unroll
        for (int k = 0; k < 8; k++) {
            float ar[8], br[8];
            #pragma unroll
            for (int i = 0; i < 4; i++) {
                ar[i]     = As[k][ty * 4 + i];
                ar[4 + i] = As[k][64 + ty * 4 + i];
                br[i]     = Bs[k][tx * 4 + i];
                br[4 + i] = Bs[k][64 + tx * 4 + i];
            }
            #pragma unroll
            for (int i = 0; i < 8; i++)
                #pragma unroll
                for (int j = 0; j < 8; j++) acc[i][j] += ar[i] * br[j];
        }
        __syncthreads();
    }

    float* Cb = C + (size_t)bz * cStride;
    #pragma unroll
    for (int gi = 0; gi < 2; gi++)
        #pragma unroll
        for (int ii = 0; ii < 4; ii++) {
            int r = bm * 128 + gi * 64 + ty * 4 + ii;
            #pragma unroll
            for (int gj = 0; gj < 2; gj++) {
                int cb = bn * 128 + gj * 64 + tx * 4;
                float4 o;
                o.x = acc[gi * 4 + ii][gj * 4 + 0];
                o.y = acc[gi * 4 + ii][gj * 4 + 1];
                o.z = acc[gi * 4 + ii][gj * 4 + 2];
                o.w = acc[gi * 4 + ii][gj * 4 + 3];
                *(float4*)(Cb + (size_t)r * N + cb) = o;
            }
        }
}

// ---------------------------------------------------------------------------
// Kernel: prep_small2 — warp-per-row dots
// ---------------------------------------------------------------------------
__global__ __launch_bounds__(256) void prep_small2_kernel(
    const float* __restrict__ Wq, const float* __restrict__ bq)
{
    int gw = blockIdx.x * 8 + (threadIdx.x >> 5);
    int lane = threadIdx.x & 31;
    if (gw > 1536) return;
    const float4* bp = (const float4*)bq;
    float s = 0.f;
    if (gw < 1024) {
        const float4* kr = (const float4*)(g_keyt + (size_t)gw * TDIM);
        #pragma unroll
        for (int i = 0; i < 6; i++) {
            float4 a = kr[lane + 32 * i], c = bp[lane + 32 * i];
            s += a.x * c.x + a.y * c.y + a.z * c.z + a.w * c.w;
        }
        #pragma unroll
        for (int o = 16; o; o >>= 1) s += __shfl_xor_sync(0xffffffffu, s, o);
        if (!lane) g_pb[gw] = s;
    } else if (gw < 1536) {
        int c = gw - 1024;
        const float4* wr = (const float4*)(Wq + (size_t)c * TDIM);
        #pragma unroll
        for (int i = 0; i < 6; i++) {
            float4 a = wr[lane + 32 * i], d = bp[lane + 32 * i];
            s += a.x * d.x + a.y * d.y + a.z * d.z + a.w * d.w;
        }
        #pragma unroll
        for (int o = 16; o; o >>= 1) s += __shfl_xor_sync(0xffffffffu, s, o);
        if (!lane) g_wb2[c] = 2.0f * s;
    } else {
        #pragma unroll
        for (int i = 0; i < 6; i++) {
            float4 a = bp[lane + 32 * i];
            s += a.x * a.x + a.y * a.y + a.z * a.z + a.w * a.w;
        }
        #pragma unroll
        for (int o = 16; o; o >>= 1) s += __shfl_xor_sync(0xffffffffu, s, o);
        if (!lane) g_nb2[0] = s;
    }
}

// ---------------------------------------------------------------------------
// Kernel: convert fp32 B [K][N] -> fp16 hi/lo planes [N][K/2], scaled x256
// ---------------------------------------------------------------------------
__global__ __launch_bounds__(256) void convert_b_kernel(
    const float* __restrict__ in, uint32_t* __restrict__ oh,
    uint32_t* __restrict__ ol, int Kd, int N,
    size_t inStride, size_t outStride)
{
    __shared__ float t[64][65];
    int k0 = blockIdx.y * 64, n0 = blockIdx.x * 64;
    int bz = blockIdx.z;
    const float* inb = in + (size_t)bz * inStride;
    int tid = threadIdx.x;
    #pragma unroll
    for (int i = 0; i < 16; i++) {
        int lin = tid + 256 * i;
        int r = lin >> 6, c = lin & 63;
        t[r][c] = inb[(size_t)(k0 + r) * N + n0 + c];
    }
    __syncthreads();
    int K2 = Kd >> 1;
    #pragma unroll
    for (int i = 0; i < 8; i++) {
        int lin = tid + 256 * i;
        int n = lin >> 5, kp = lin & 31;
        uint32_t h, l;
        wsplit2(t[2 * kp][n], t[2 * kp + 1][n], h, l);
        size_t o = (size_t)bz * outStride + (size_t)(n0 + n) * K2 + (k0 >> 1) + kp;
        oh[o] = h;  ol[o] = l;
    }
}

// ---------------------------------------------------------------------------
// Kernel: LayerNorm -> fp16 hi/lo planes only (no fp32 output)
// ---------------------------------------------------------------------------
__global__ __launch_bounds__(256) void ln_kernel(
    const float* __restrict__ in, const float* __restrict__ g,
    const float* __restrict__ be,
    uint32_t* __restrict__ oh, uint32_t* __restrict__ ol)
{
    int warp = threadIdx.x >> 5, lane = threadIdx.x & 31;
    size_t row = (size_t)blockIdx.x * 8 + warp;
    const float4* p = (const float4*)(in + row * CDIM);
    float4 x[4];
    float s = 0.f, s2 = 0.f;
    #pragma unroll
    for (int i = 0; i < 4; i++) {
        x[i] = p[lane + 32 * i];
        s  += x[i].x + x[i].y + x[i].z + x[i].w;
        s2 += x[i].x * x[i].x + x[i].y * x[i].y + x[i].z * x[i].z + x[i].w * x[i].w;
    }
    #pragma unroll
    for (int o = 16; o; o >>= 1) {
        s  += __shfl_xor_sync(0xffffffffu, s, o);
        s2 += __shfl_xor_sync(0xffffffffu, s2, o);
    }
    float mu  = s * (1.0f / CDIM);
    float var = s2 * (1.0f / CDIM) - mu * mu;
    float rs  = rsqrtf(var + LN_EPS);
    const float4* gp = (const float4*)g;
    const float4* bp = (const float4*)be;
    #pragma unroll
    for (int i = 0; i < 4; i++) {
        int c4 = lane + 32 * i;
        float4 gv = gp[c4], bv = bp[c4], r;
        r.x = (x[i].x - mu) * rs * gv.x + bv.x;
        r.y = (x[i].y - mu) * rs * gv.y + bv.y;
        r.z = (x[i].z - mu) * rs * gv.z + bv.z;
        r.w = (x[i].w - mu) * rs * gv.w + bv.w;
        uint2 h, l;
        asplit2(r.x, r.y, h.x, l.x);
        asplit2(r.z, r.w, h.y, l.y);
        *(uint2*)(oh + row * (CDIM / 2) + 2 * c4) = h;
        *(uint2*)(ol + row * (CDIM / 2) + 2 * c4) = l;
    }
}

// ---------------------------------------------------------------------------
// fp16 tensor-core GEMM, products: Ah*Bh [+ Ah*Bl if BP==2] [+ Al*Bh if AP==2]
// B pre-scaled x256. 256x128 block tile, 512 threads, warp tile 64x32.
// MODE 0: sim -> Out fp32 [M][128], per-batch B (batch = bm>>4)
// MODE 1: gelu(acc/256+bias) -> fp16 plane Oh
// MODE 2: acc/256+bias+Res -> Out fp32
// MODE 3: qn2[r] += sum_c (acc/256)*(h+2l) + bias*(h+l),  h/l from Ah/Al planes
// ---------------------------------------------------------------------------
#define A_PLANE 5120          // 256 rows * 20 u32
#define B_PLANE 2560          // 128 rows * 20 u32

template <int MODE, int AP, int BP>
__global__ __launch_bounds__(512) void tgemm4_kernel(
    const uint32_t* __restrict__ Ah, const uint32_t* __restrict__ Al,
    const uint32_t* __restrict__ Bh, const uint32_t* __restrict__ Bl,
    const float* __restrict__ bias, const float* __restrict__ Res,
    float* __restrict__ Out, uint32_t* __restrict__ Oh,
    int M, int N, int Kd)
{
    const int STG = AP * A_PLANE + BP * B_PLANE;
    extern __shared__ uint32_t sm[];
    uint32_t sbase = smem_u32(sm);
    int K2 = Kd >> 1;
    int tid = threadIdx.x, lane = tid & 31, warp = tid >> 5;
    int g  = lane >> 2, tg = lane & 3;
    int wm = warp >> 2, wn = warp & 3;
    int m0 = wm * 64,  n0 = wn * 32;
    int bn = blockIdx.x, bm = blockIdx.y;

    const uint32_t* AhB = Ah + (size_t)bm * 256 * K2;
    const uint32_t* AlB = (AP == 2) ? Al + (size_t)bm * 256 * K2 : nullptr;
    size_t bofs = (size_t)bn * 128 * K2;
    if (MODE == 0) bofs += (size_t)(bm >> 4) * KTXT * K2;   // per-batch B
    const uint32_t* BhB = Bh + bofs;
    const uint32_t* BlB = (BP == 2) ? Bl + bofs : nullptr;

    uint32_t a_ld = (uint32_t)((m0 + (lane & 7) + ((lane >> 3) & 1) * 8) * 20
                               + ((lane >> 4) & 1) * 4) * 4;
    uint32_t b_ld = (uint32_t)((n0 + (lane & 7) + ((lane >> 4) & 1) * 8) * 20
                               + ((lane >> 3) & 1) * 4) * 4;

    float acc[4][4][4];
    #pragma unroll
    for (int mi = 0; mi < 4; mi++)
        #pragma unroll
        for (int ni = 0; ni < 4; ni++)
            #pragma unroll
            for (int r = 0; r < 4; r++) acc[mi][ni][r] = 0.f;

    int nT = K2 / 16;
    const int AOFF = AP * A_PLANE;

    #pragma unroll
    for (int pf = 0; pf < 2; pf++) {
        uint32_t* st = sm + pf * STG;
        int kp0 = pf * 16;
        #pragma unroll
        for (int c = 0; c < 2; c++) {
            int idx = tid + 512 * c;
            int row = idx >> 2, kb = (idx & 3) * 4;
            size_t go = (size_t)row * K2 + kp0 + kb;
            cp16(st + row * 20 + kb, AhB + go);
            if (AP == 2) cp16(st + A_PLANE + row * 20 + kb, AlB + go);
        }
        {
            int row = tid >> 2, kb = (tid & 3) * 4;
            size_t go = (size_t)row * K2 + kp0 + kb;
            int so = row * 20 + kb;
            cp16(st + AOFF + so, BhB + go);
            if (BP == 2) cp16(st + AOFF + B_PLANE + so, BlB + go);
        }
        cp_commit();
    }

    for (int t = 0; t < nT; t++) {
        cp_wait1();
        __syncthreads();
        uint32_t stb = sbase + (uint32_t)((t & 1) * STG * 4);

        #pragma unroll
        for (int ks = 0; ks < 2; ks++) {
            uint32_t ksoff = (uint32_t)(ks * 32);
            uint32_t a[4][4], al[4][4], bh[4][2], bl[4][2];
            #pragma unroll
            for (int mi = 0; mi < 4; mi++) {
                uint32_t ao = stb + a_ld + ksoff + (uint32_t)(mi * 16 * 80);
                ldsm_x4(a[mi][0], a[mi][1], a[mi][2], a[mi][3], ao);
                if (AP == 2)
                    ldsm_x4(al[mi][0], al[mi][1], al[mi][2], al[mi][3],
                            ao + A_PLANE * 4);
            }
            #pragma unroll
            for (int p = 0; p < 2; p++) {
                uint32_t bo = stb + AOFF * 4 + b_ld + ksoff + (uint32_t)(p * 16 * 80);
                ldsm_x4(bh[2 * p][0], bh[2 * p][1], bh[2 * p + 1][0], bh[2 * p + 1][1], bo);
                if (BP == 2)
                    ldsm_x4(bl[2 * p][0], bl[2 * p][1], bl[2 * p + 1][0], bl[2 * p + 1][1],
                            bo + B_PLANE * 4);
            }
            #pragma unroll
            for (int mi = 0; mi < 4; mi++)
                #pragma unroll
                for (int ni = 0; ni < 4; ni++) {
                    mma_f16(acc[mi][ni], a[mi], bh[ni]);
                    if (BP == 2) mma_f16(acc[mi][ni], a[mi], bl[ni]);
                    if (AP == 2) mma_f16(acc[mi][ni], al[mi], bh[ni]);
                }
        }
        __syncthreads();
        if (t + 2 < nT) {
            uint32_t* dst = sm + (t & 1) * STG;
            int kp0 = (t + 2) * 16;
            #pragma unroll
            for (int c = 0; c < 2; c++) {
                int idx = tid + 512 * c;
                int row = idx >> 2, kb = (idx & 3) * 4;
                size_t go = (size_t)row * K2 + kp0 + kb;
                cp16(dst + row * 20 + kb, AhB + go);
                if (AP == 2) cp16(dst + A_PLANE + row * 20 + kb, AlB + go);
            }
            {
                int row = tid >> 2, kb = (tid & 3) * 4;
                size_t go = (size_t)row * K2 + kp0 + kb;
                int so = row * 20 + kb;
                cp16(dst + AOFF + so, BhB + go);
                if (BP == 2) cp16(dst + AOFF + B_PLANE + so, BlB + go);
            }
        }
        cp_commit();
    }

    if (MODE == 3) {
        // qn2[r] += sum_c z*(h+2l) + bias*(h+l), where v = h + l (fp16 planes)
        #pragma unroll
        for (int mi = 0; mi < 4; mi++)
            #pragma unroll
            for (int half = 0; half < 2; half++) {
                int r = bm * 256 + m0 + mi * 16 + g + half * 8;
                float part = 0.f;
                #pragma unroll
                for (int ni = 0; ni < 4; ni++) {
                    int c = bn * 128 + n0 + ni * 8 + 2 * tg;
                    uint32_t hu = Ah[(size_t)r * (N >> 1) + (c >> 1)];
                    uint32_t lu = Al[(size_t)r * (N >> 1) + (c >> 1)];
                    __half2 h2 = *reinterpret_cast<__half2*>(&hu);
                    __half2 l2 = *reinterpret_cast<__half2*>(&lu);
                    float h0 = __half2float(__low2half(h2));
                    float h1 = __half2float(__high2half(h2));
                    float l0 = __half2float(__low2half(l2));
                    float l1 = __half2float(__high2half(l2));
                    float z0 = acc[mi][ni][half * 2 + 0] * WINV;
                    float z1 = acc[mi][ni][half * 2 + 1] * WINV;
                    part += z0 * (h0 + 2.0f * l0) + bias[c]     * (h0 + l0);
                    part += z1 * (h1 + 2.0f * l1) + bias[c + 1] * (h1 + l1);
                }
                part += __shfl_xor_sync(0xffffffffu, part, 1);
                part += __shfl_xor_sync(0xffffffffu, part, 2);
                if (tg == 0) atomicAdd(&g_qn2[r], part);
            }
        return;
    }

    #pragma unroll
    for (int mi = 0; mi < 4; mi++)
        #pragma unroll
        for (int half = 0; half < 2; half++) {
            int r = bm * 256 + m0 + mi * 16 + g + half * 8;
            #pragma unroll
            for (int ni = 0; ni < 4; ni++) {
                int c = bn * 128 + n0 + ni * 8 + 2 * tg;
                float v0 = acc[mi][ni][half * 2 + 0] * WINV;
                float v1 = acc[mi][ni][half * 2 + 1] * WINV;
                if (MODE == 0) {
                    float2 ov = { v0, v1 };
                    *(float2*)(Out + (size_t)r * KTXT + c) = ov;
                } else if (MODE == 1) {
                    v0 += bias[c];  v1 += bias[c + 1];
                    v0 = v0 * normcdff(v0);
                    v1 = v1 * normcdff(v1);
                    Oh[(size_t)r * (N >> 1) + (c >> 1)] = packh2(v0, v1);
                } else {
                    v0 += bias[c]     + Res[(size_t)r * N + c];
                    v1 += bias[c + 1] + Res[(size_t)r * N + c + 1];
                    float2 ov = { v0, v1 };
                    *(float2*)(Out + (size_t)r * N + c) = ov;
                }
            }
        }
}

// ---------------------------------------------------------------------------
// Attention epilogue: read precomputed sim, topk/softmax/gather/LN2.
// ---------------------------------------------------------------------------
__global__ __launch_bounds__(256) void attn_kernel(
    const float* __restrict__ resid, const float* __restrict__ g2,
    const float* __restrict__ be2)
{
    __shared__ float invn[32];
    __shared__ float pb_s[KTXT];
    int tid = threadIdx.x, lane = tid & 31, warp = tid >> 5;
    int t0 = blockIdx.x * 32;
    int b  = t0 >> 12;

    if (tid < 32) {
        float qn2 = g_qn2[t0 + tid] + g_nb2[0];
        float n = sqrtf(fmaxf(qn2, 0.f));
        invn[tid] = 1.0f / fmaxf(n, 1e-12f);
    }
    if (tid < KTXT) pb_s[tid] = g_pb[b * KTXT + tid];
    __syncthreads();

    for (int rr = 0; rr < 4; rr++) {
        int row = warp * 4 + rr;
        float sc = invn[row];
        const float* sp = g_sim + (size_t)(t0 + row) * KTXT;
        float tv[4];
        #pragma unroll
        for (int j = 0; j < 4; j++) {
            int col = lane + 32 * j;
            tv[j] = (sp[col] + pb_s[col]) * sc;
        }

        float mval[TOPM]; int midx[TOPM];
        #pragma unroll
        for (int it = 0; it < TOPM; it++) {
            float lm = tv[0]; int lj = 0;
            #pragma unroll
            for (int j = 1; j < 4; j++) if (tv[j] > lm) { lm = tv[j]; lj = j; }
            int li = lane + 32 * lj;
            #pragma unroll
            for (int o = 16; o; o >>= 1) {
                float ov = __shfl_xor_sync(0xffffffffu, lm, o);
                int   oi = __shfl_xor_sync(0xffffffffu, li, o);
                if (ov > lm || (ov == lm && oi < li)) { lm = ov; li = oi; }
            }
            mval[it] = lm; midx[it] = li;
            if ((li & 31) == lane) tv[li >> 5] = -INFINITY;
        }

        float p[TOPM], psum = 0.f;
        #pragma unroll
        for (int it = 0; it < TOPM; it++) {
            p[it] = expf((mval[it] - mval[0]) * TEMP_INV);
            psum += p[it];
        }
        float rnorm = 1.0f / psum;

        float f[16];
        #pragma unroll
        for (int i = 0; i < 16; i++) f[i] = 0.f;
        const float* Vb = g_value + (size_t)b * KTXT * CDIM;
        #pragma unroll
        for (int it = 0; it < TOPM; it++) {
            const float4* vr = (const float4*)(Vb + (size_t)midx[it] * CDIM + lane * 16);
            float a_ = p[it] * rnorm;
            #pragma unroll
            for (int j = 0; j < 4; j++) {
                float4 v = vr[j];
                f[4 * j + 0] += a_ * v.x;
                f[4 * j + 1] += a_ * v.y;
                f[4 * j + 2] += a_ * v.z;
                f[4 * j + 3] += a_ * v.w;
            }
        }

        const float4* rp = (const float4*)(resid + (size_t)(t0 + row) * CDIM + lane * 16);
        float s = 0.f, s2 = 0.f;
        #pragma unroll
        for (int j = 0; j < 4; j++) {
            float4 v = rp[j];
            f[4 * j + 0] += v.x;  f[4 * j + 1] += v.y;
            f[4 * j + 2] += v.z;  f[4 * j + 3] += v.w;
        }
        #pragma unroll
        for (int i = 0; i < 16; i++) { s += f[i]; s2 += f[i] * f[i]; }
        #pragma unroll
        for (int o = 16; o; o >>= 1) {
            s  += __shfl_xor_sync(0xffffffffu, s, o);
            s2 += __shfl_xor_sync(0xffffffffu, s2, o);
        }
        float mu  = s * (1.0f / CDIM);
        float var = s2 * (1.0f / CDIM) - mu * mu;
        float rstd = rsqrtf(var + LN_EPS);

        size_t rbase = (size_t)(t0 + row);
        float*    xp = g_X  + rbase * CDIM + lane * 16;
        uint32_t* xh = g_Xh + rbase * (CDIM / 2) + lane * 8;
        #pragma unroll
        for (int j = 0; j < 4; j++) {
            int c = lane * 16 + 4 * j;
            float4 o;
            o.x = (f[4 * j + 0] - mu) * rstd * g2[c + 0] + be2[c + 0];
            o.y = (f[4 * j + 1] - mu) * rstd * g2[c + 1] + be2[c + 1];
            o.z = (f[4 * j + 2] - mu) * rstd * g2[c + 2] + be2[c + 2];
            o.w = (f[4 * j + 3] - mu) * rstd * g2[c + 3] + be2[c + 3];
            *(float4*)(xp + 4 * j) = o;
            uint2 h;
            h.x = packh2(o.x, o.y);
            h.y = packh2(o.z, o.w);
            *(uint2*)(xh + 2 * j) = h;
        }
    }
}

// ---------------------------------------------------------------------------
// Launch
// ---------------------------------------------------------------------------
extern "C" void kernel_launch(void* const* d_in, const int* in_sizes, int n_in,
                              void* d_out, int out_size)
{
    const float* vis  = (const float*)d_in[0];
    const float* text = (const float*)d_in[1];
    const float* Wq   = (const float*)d_in[2];
    const float* bq   = (const float*)d_in[3];
    const float* Wv   = (const float*)d_in[4];
    const float* bv   = (const float*)d_in[5];
    const float* W1   = (const float*)d_in[6];
    const float* b1   = (const float*)d_in[7];
    const float* W2   = (const float*)d_in[8];
    const float* b2   = (const float*)d_in[9];
    const float* g1   = (const float*)d_in[10];
    const float* be1  = (const float*)d_in[11];
    const float* g2   = (const float*)d_in[12];
    const float* be2  = (const float*)d_in[13];
    float* out = (float*)d_out;

    float *p_X, *p_P, *p_G, *p_keyt, *p_wb2, *p_qn2, *p_sim;
    uint32_t *p_vh, *p_vl, *p_Xh, *p_Hh;
    uint32_t *p_Gh, *p_Gl, *p_Ph, *p_Pl, *p_W1h, *p_W1l, *p_W2h, *p_W2l;
    cudaGetSymbolAddress((void**)&p_X,     g_X);
    cudaGetSymbolAddress((void**)&p_P,     g_P);
    cudaGetSymbolAddress((void**)&p_G,     g_G);
    cudaGetSymbolAddress((void**)&p_keyt,  g_keyt);
    cudaGetSymbolAddress((void**)&p_wb2,   g_wb2);
    cudaGetSymbolAddress((void**)&p_qn2,   g_qn2);
    cudaGetSymbolAddress((void**)&p_sim,   g_sim);
    cudaGetSymbolAddress((void**)&p_vh,    g_vh);
    cudaGetSymbolAddress((void**)&p_vl,    g_vl);
    cudaGetSymbolAddress((void**)&p_Xh,    g_Xh);
    cudaGetSymbolAddress((void**)&p_Hh,    g_Hh);
    cudaGetSymbolAddress((void**)&p_Gh,    g_Gh);
    cudaGetSymbolAddress((void**)&p_Gl,    g_Gl);
    cudaGetSymbolAddress((void**)&p_Ph,    g_Ph);
    cudaGetSymbolAddress((void**)&p_Pl,    g_Pl);
    cudaGetSymbolAddress((void**)&p_W1h,   g_W1h);
    cudaGetSymbolAddress((void**)&p_W1l,   g_W1l);
    cudaGetSymbolAddress((void**)&p_W2h,   g_W2h);
    cudaGetSymbolAddress((void**)&p_W2l,   g_W2l);

    const int SMEM_1P  = 2 * (1 * A_PLANE + 1 * B_PLANE) * 4;   // 61440
    const int SMEM_SIM = 2 * (2 * A_PLANE + 2 * B_PLANE) * 4;   // 122880
    cudaFuncSetAttribute((const void*)tgemm4_kernel<0, 2, 2>,
                         cudaFuncAttributeMaxDynamicSharedMemorySize, SMEM_SIM);
    cudaFuncSetAttribute((const void*)tgemm4_kernel<1, 1, 1>,
                         cudaFuncAttributeMaxDynamicSharedMemorySize, SMEM_1P);
    cudaFuncSetAttribute((const void*)tgemm4_kernel<2, 1, 1>,
                         cudaFuncAttributeMaxDynamicSharedMemorySize, SMEM_1P);
    cudaFuncSetAttribute((const void*)tgemm4_kernel<3, 1, 1>,
                         cudaFuncAttributeMaxDynamicSharedMemorySize, SMEM_1P);

    // 1) text prep (keyt, value)
    prep_text_kernel<<<(BQ * KTXT) / 8, 256>>>(text, Wv, bv);
    // 2) P_b = Wq @ keyt_b^T per batch (fp32)
    sgemm_tn_kernel<<<dim3(1, CDIM / 128, BQ), 256>>>(
        Wq, p_keyt, p_P, TDIM, KTXT,
        0, (size_t)KTXT * TDIM, (size_t)CDIM * KTXT);
    // 3) G = Wq @ Wq^T (fp32)
    sgemm_tn_kernel<<<dim3(CDIM / 128, CDIM / 128, 1), 256>>>(
        Wq, Wq, p_G, TDIM, CDIM, 0, 0, 0);
    // 4) pb, wb2, nb2
    prep_small2_kernel<<<193, 256>>>(Wq, bq);
    // 5) convert weights to fp16 hi/lo planes (x256)
    convert_b_kernel<<<dim3(CDIM / 64, CDIM / 64), 256>>>(
        p_G, p_Gh, p_Gl, CDIM, CDIM, 0, 0);
    convert_b_kernel<<<dim3(HID / 64, CDIM / 64), 256>>>(
        W1, p_W1h, p_W1l, CDIM, HID, 0, 0);
    convert_b_kernel<<<dim3(CDIM / 64, HID / 64), 256>>>(
        W2, p_W2h, p_W2l, HID, CDIM, 0, 0);
    convert_b_kernel<<<dim3(KTXT / 64, CDIM / 64, BQ), 256>>>(
        p_P, p_Ph, p_Pl, CDIM, KTXT,
        (size_t)CDIM * KTXT, (size_t)KTXT * CDIM / 2);
    // 6) LN1 -> vh/vl fp16 planes (no fp32)
    ln_kernel<<<MTOT / 8, 256>>>(vis, g1, be1, p_vh, p_vl);
    // 7) qn2 (1 product; missing v^T Gl v term is ~5e-6 relative and
    //    ranking-invariant; activation lo corrected via (h+2l) epilogue)
    cudaMemsetAsync(p_qn2, 0, MTOT * sizeof(float));
    tgemm4_kernel<3, 1, 1><<<dim3(CDIM / 128, MTOT / 256), 512, SMEM_1P>>>(
        p_vh, p_vl, p_Gh, nullptr, p_wb2, nullptr, nullptr, nullptr,
        MTOT, CDIM, CDIM);
    // 8) sim = (vh+vl) @ P_b planes (3 products) -> g_sim fp32
    tgemm4_kernel<0, 2, 2><<<dim3(1, MTOT / 256), 512, SMEM_SIM>>>(
        p_vh, p_vl, p_Ph, p_Pl, nullptr, nullptr, p_sim, nullptr,
        MTOT, KTXT, CDIM);
    // 9) attention epilogue + residual + LN2 -> X fp32 + Xh fp16
    attn_kernel<<<MTOT / 32, 256>>>(vis, g2, be2);
    // 10) H = gelu(X @ W1 + b1) -> fp16 plane Hh
    tgemm4_kernel<1, 1, 1><<<dim3(HID / 128, MTOT / 256), 512, SMEM_1P>>>(
        p_Xh, nullptr, p_W1h, p_W1l, b1, nullptr, nullptr, p_Hh,
        MTOT, HID, CDIM);
    // 11) out = X + H @ W2 + b2
    tgemm4_kernel<2, 1, 1><<<dim3(CDIM / 128, MTOT / 256), 512, SMEM_1P>>>(
        p_Hh, nullptr, p_W2h, p_W2l, b2, p_X, out, nullptr,
        MTOT, CDIM, HID);
}

// round 14
// speedup vs baseline: 2.1641x; 1.0960x over previous
#include <cuda_runtime.h>
#include <cuda_fp16.h>
#include <math.h>
#include <stdint.h>

// ---------------------------------------------------------------------------
// Problem constants
// ---------------------------------------------------------------------------
#define BQ    8
#define MTOT  32768
#define CDIM  512
#define TDIM  768
#define KTXT  128
#define HID   2048
#define TOPM  5
#define TEMP_INV (1.0f/0.07f)
#define LN_EPS 1e-5f
#define WSCALE 256.0f
#define WINV   (1.0f/256.0f)

// ---------------------------------------------------------------------------
// Scratch (device globals)
// ---------------------------------------------------------------------------
static __device__ uint32_t g_vh[MTOT * CDIM / 2];
static __device__ uint32_t g_vl[MTOT * CDIM / 2];
static __device__ float    g_X [MTOT * CDIM];
static __device__ uint32_t g_Xh[MTOT * CDIM / 2];
static __device__ uint32_t g_Hh[(size_t)MTOT * HID / 2];
static __device__ float    g_sim[(size_t)MTOT * KTXT];
static __device__ float    g_keyt [BQ * KTXT * TDIM];
static __device__ float    g_value[BQ * KTXT * CDIM];
static __device__ float    g_P [BQ * CDIM * KTXT];
static __device__ float    g_G [CDIM * CDIM];
static __device__ uint32_t g_Gh [CDIM * CDIM / 2];
static __device__ uint32_t g_Gl [CDIM * CDIM / 2];
static __device__ uint32_t g_Ph [BQ * KTXT * CDIM / 2];
static __device__ uint32_t g_Pl [BQ * KTXT * CDIM / 2];
static __device__ uint32_t g_W1h[(size_t)HID * CDIM / 2];
static __device__ uint32_t g_W1l[(size_t)HID * CDIM / 2];
static __device__ uint32_t g_W2h[(size_t)CDIM * HID / 2];
static __device__ uint32_t g_W2l[(size_t)CDIM * HID / 2];
static __device__ float    g_pb [BQ * KTXT];
static __device__ float    g_wb2[CDIM];
static __device__ float    g_nb2[1];
static __device__ float    g_qn2[MTOT];

// ---------------------------------------------------------------------------
// Helpers
// ---------------------------------------------------------------------------
__device__ __forceinline__ uint32_t packh2(float x, float y) {
    __half2 h = __floats2half2_rn(x, y);
    return *reinterpret_cast<uint32_t*>(&h);
}

__device__ __forceinline__ void wsplit2(float x, float y,
                                        uint32_t& hi, uint32_t& lo) {
    float sx = x * WSCALE, sy = y * WSCALE;
    __half hx = __float2half_rn(sx);
    __half hy = __float2half_rn(sy);
    float rx = sx - __half2float(hx);
    float ry = sy - __half2float(hy);
    __half2 h2 = __halves2half2(hx, hy);
    __half2 l2 = __floats2half2_rn(rx, ry);
    hi = *reinterpret_cast<uint32_t*>(&h2);
    lo = *reinterpret_cast<uint32_t*>(&l2);
}

__device__ __forceinline__ void asplit2(float x, float y,
                                        uint32_t& hi, uint32_t& lo) {
    __half hx = __float2half_rn(x);
    __half hy = __float2half_rn(y);
    float rx = x - __half2float(hx);
    float ry = y - __half2float(hy);
    __half2 h2 = __halves2half2(hx, hy);
    __half2 l2 = __floats2half2_rn(rx, ry);
    hi = *reinterpret_cast<uint32_t*>(&h2);
    lo = *reinterpret_cast<uint32_t*>(&l2);
}

__device__ __forceinline__ void mma_f16(float* c, const uint32_t* a, const uint32_t* b) {
    asm volatile(
        "mma.sync.aligned.m16n8k16.row.col.f32.f16.f16.f32 "
        "{%0,%1,%2,%3}, {%4,%5,%6,%7}, {%8,%9}, {%0,%1,%2,%3};\n"
        : "+f"(c[0]), "+f"(c[1]), "+f"(c[2]), "+f"(c[3])
        : "r"(a[0]), "r"(a[1]), "r"(a[2]), "r"(a[3]), "r"(b[0]), "r"(b[1]));
}

__device__ __forceinline__ uint32_t smem_u32(const void* p) {
    uint32_t a;
    asm("{ .reg .u64 t; cvta.to.shared.u64 t, %1; cvt.u32.u64 %0, t; }"
        : "=r"(a) : "l"(p));
    return a;
}

__device__ __forceinline__ void ldsm_x4(uint32_t& r0, uint32_t& r1,
                                        uint32_t& r2, uint32_t& r3,
                                        uint32_t addr) {
    asm volatile(
        "ldmatrix.sync.aligned.m8n8.x4.shared.b16 {%0,%1,%2,%3}, [%4];"
        : "=r"(r0), "=r"(r1), "=r"(r2), "=r"(r3) : "r"(addr));
}

__device__ __forceinline__ void cp16(uint32_t* dst_smem, const uint32_t* src) {
    uint32_t s = (uint32_t)__cvta_generic_to_shared(dst_smem);
    asm volatile("cp.async.cg.shared.global [%0], [%1], 16;\n" :: "r"(s), "l"(src));
}
__device__ __forceinline__ void cp_commit() {
    asm volatile("cp.async.commit_group;\n");
}
__device__ __forceinline__ void cp_wait1() {
    asm volatile("cp.async.wait_group 1;\n");
}

// ---------------------------------------------------------------------------
// Device bodies (math identical to R13 kernels)
// ---------------------------------------------------------------------------
__device__ void ln_body(const float* __restrict__ in, const float* __restrict__ g,
                        const float* __restrict__ be,
                        uint32_t* __restrict__ oh, uint32_t* __restrict__ ol, int blk)
{
    int warp = threadIdx.x >> 5, lane = threadIdx.x & 31;
    size_t row = (size_t)blk * 8 + warp;
    const float4* p = (const float4*)(in + row * CDIM);
    float4 x[4];
    float s = 0.f, s2 = 0.f;
    #pragma unroll
    for (int i = 0; i < 4; i++) {
        x[i] = p[lane + 32 * i];
        s  += x[i].x + x[i].y + x[i].z + x[i].w;
        s2 += x[i].x * x[i].x + x[i].y * x[i].y + x[i].z * x[i].z + x[i].w * x[i].w;
    }
    #pragma unroll
    for (int o = 16; o; o >>= 1) {
        s  += __shfl_xor_sync(0xffffffffu, s, o);
        s2 += __shfl_xor_sync(0xffffffffu, s2, o);
    }
    float mu  = s * (1.0f / CDIM);
    float var = s2 * (1.0f / CDIM) - mu * mu;
    float rs  = rsqrtf(var + LN_EPS);
    const float4* gp = (const float4*)g;
    const float4* bp = (const float4*)be;
    #pragma unroll
    for (int i = 0; i < 4; i++) {
        int c4 = lane + 32 * i;
        float4 gv = gp[c4], bv = bp[c4], r;
        r.x = (x[i].x - mu) * rs * gv.x + bv.x;
        r.y = (x[i].y - mu) * rs * gv.y + bv.y;
        r.z = (x[i].z - mu) * rs * gv.z + bv.z;
        r.w = (x[i].w - mu) * rs * gv.w + bv.w;
        uint2 h, l;
        asplit2(r.x, r.y, h.x, l.x);
        asplit2(r.z, r.w, h.y, l.y);
        *(uint2*)(oh + row * (CDIM / 2) + 2 * c4) = h;
        *(uint2*)(ol + row * (CDIM / 2) + 2 * c4) = l;
    }
}

__device__ void prep_text_body(const float* __restrict__ text,
                               const float* __restrict__ Wv,
                               const float* __restrict__ bv,
                               float (*ts)[TDIM], int blk)
{
    int tid = threadIdx.x, lane = tid & 31, warp = tid >> 5;
    int b  = blk >> 4;
    int kb = (blk & 15) * 8;
    const float* tb = text + ((size_t)b * KTXT + kb) * TDIM;

    #pragma unroll
    for (int i = 0; i < 24; i++) {
        int lin = tid + 256 * i;
        int r = lin / TDIM, c = lin % TDIM;
        ts[r][c] = tb[(size_t)r * TDIM + c];
    }
    __syncthreads();

    {
        int r = warp;
        float s = 0.f;
        for (int i = lane; i < TDIM; i += 32) { float v = ts[r][i]; s += v * v; }
        #pragma unroll
        for (int o = 16; o; o >>= 1) s += __shfl_xor_sync(0xffffffffu, s, o);
        float inv = 1.0f / fmaxf(sqrtf(s), 1e-12f);
        float* kr = g_keyt + ((size_t)b * KTXT + kb + r) * TDIM;
        for (int i = lane; i < TDIM; i += 32) kr[i] = ts[r][i] * inv;
    }

    float acc[8][2];
    #pragma unroll
    for (int r = 0; r < 8; r++) { acc[r][0] = 0.f; acc[r][1] = 0.f; }
    int c0 = tid, c1 = tid + 256;
    for (int t = 0; t < TDIM; t++) {
        float w0 = Wv[(size_t)t * CDIM + c0];
        float w1 = Wv[(size_t)t * CDIM + c1];
        #pragma unroll
        for (int r = 0; r < 8; r++) {
            float tv = ts[r][t];
            acc[r][0] += tv * w0;
            acc[r][1] += tv * w1;
        }
    }
    float bb0 = bv[c0], bb1 = bv[c1];
    #pragma unroll
    for (int r = 0; r < 8; r++) {
        float* vr = g_value + ((size_t)b * KTXT + kb + r) * CDIM;
        vr[c0] = acc[r][0] + bb0;
        vr[c1] = acc[r][1] + bb1;
    }
}

__device__ void convert_body(const float* __restrict__ in,
                             uint32_t* __restrict__ oh, uint32_t* __restrict__ ol,
                             int Kd, int N, int bx, int by, int bz,
                             size_t inStride, size_t outStride, float (*t)[65])
{
    int k0 = by * 64, n0 = bx * 64;
    const float* inb = in + (size_t)bz * inStride;
    int tid = threadIdx.x;
    #pragma unroll
    for (int i = 0; i < 16; i++) {
        int lin = tid + 256 * i;
        int r = lin >> 6, c = lin & 63;
        t[r][c] = inb[(size_t)(k0 + r) * N + n0 + c];
    }
    __syncthreads();
    int K2 = Kd >> 1;
    #pragma unroll
    for (int i = 0; i < 8; i++) {
        int lin = tid + 256 * i;
        int n = lin >> 5, kp = lin & 31;
        uint32_t h, l;
        wsplit2(t[2 * kp][n], t[2 * kp + 1][n], h, l);
        size_t o = (size_t)bz * outStride + (size_t)(n0 + n) * K2 + (k0 >> 1) + kp;
        oh[o] = h;  ol[o] = l;
    }
}

__device__ void wb2_body(const float* __restrict__ Wq,
                         const float* __restrict__ bq, int gw2)
{
    if (gw2 > 512) return;
    int lane = threadIdx.x & 31;
    const float4* bp = (const float4*)bq;
    float s = 0.f;
    if (gw2 < 512) {
        const float4* wr = (const float4*)(Wq + (size_t)gw2 * TDIM);
        #pragma unroll
        for (int i = 0; i < 6; i++) {
            float4 a = wr[lane + 32 * i], d = bp[lane + 32 * i];
            s += a.x * d.x + a.y * d.y + a.z * d.z + a.w * d.w;
        }
        #pragma unroll
        for (int o = 16; o; o >>= 1) s += __shfl_xor_sync(0xffffffffu, s, o);
        if (!lane) g_wb2[gw2] = 2.0f * s;
    } else {
        #pragma unroll
        for (int i = 0; i < 6; i++) {
            float4 a = bp[lane + 32 * i];
            s += a.x * a.x + a.y * a.y + a.z * a.z + a.w * a.w;
        }
        #pragma unroll
        for (int o = 16; o; o >>= 1) s += __shfl_xor_sync(0xffffffffu, s, o);
        if (!lane) g_nb2[0] = s;
    }
}

__device__ void pb_body(const float* __restrict__ bq, int gw)
{
    if (gw >= 1024) return;
    int lane = threadIdx.x & 31;
    const float4* bp = (const float4*)bq;
    const float4* kr = (const float4*)(g_keyt + (size_t)gw * TDIM);
    float s = 0.f;
    #pragma unroll
    for (int i = 0; i < 6; i++) {
        float4 a = kr[lane + 32 * i], c = bp[lane + 32 * i];
        s += a.x * c.x + a.y * c.y + a.z * c.z + a.w * c.w;
    }
    #pragma unroll
    for (int o = 16; o; o >>= 1) s += __shfl_xor_sync(0xffffffffu, s, o);
    if (!lane) g_pb[gw] = s;
}

__device__ void sgemm_body(const float* __restrict__ A, const float* __restrict__ B2,
                           float* __restrict__ C, int Kd, int N, int bn, int bm,
                           float (*As)[128], float (*Bs)[128])
{
    int tid = threadIdx.x;
    int tx = tid & 15, ty = tid >> 4;
    const float* Ab = A  + (size_t)bm * 128 * Kd;
    const float* Bb = B2 + (size_t)bn * 128 * Kd;
    int l_r = tid >> 1, l_k = (tid & 1) * 4;

    float acc[8][8];
    #pragma unroll
    for (int i = 0; i < 8; i++)
        #pragma unroll
        for (int j = 0; j < 8; j++) acc[i][j] = 0.f;

    for (int k0 = 0; k0 < Kd; k0 += 8) {
        float4 av = *(const float4*)(Ab + (size_t)l_r * Kd + k0 + l_k);
        As[l_k + 0][l_r] = av.x;
        As[l_k + 1][l_r] = av.y;
        As[l_k + 2][l_r] = av.z;
        As[l_k + 3][l_r] = av.w;
        float4 bv = *(const float4*)(Bb + (size_t)l_r * Kd + k0 + l_k);
        Bs[l_k + 0][l_r] = bv.x;
        Bs[l_k + 1][l_r] = bv.y;
        Bs[l_k + 2][l_r] = bv.z;
        Bs[l_k + 3][l_r] = bv.w;
        __syncthreads();
        #pragma unroll
        for (int k = 0; k < 8; k++) {
            float ar[8], br[8];
            #pragma unroll
            for (int i = 0; i < 4; i++) {
                ar[i]     = As[k][ty * 4 + i];
                ar[4 + i] = As[k][64 + ty * 4 + i];
                br[i]     = Bs[k][tx * 4 + i];
                br[4 + i] = Bs[k][64 + tx * 4 + i];
            }
            #pragma unroll
            for (int i = 0; i < 8; i++)
                #pragma unroll
                for (int j = 0; j < 8; j++) acc[i][j] += ar[i] * br[j];
        }
        __syncthreads();
    }

    #pragma unroll
    for (int gi = 0; gi < 2; gi++)
        #pragma unroll
        for (int ii = 0; ii < 4; ii++) {
            int r = bm * 128 + gi * 64 + ty * 4 + ii;
            #pragma unroll
            for (int gj = 0; gj < 2; gj++) {
                int cb = bn * 128 + gj * 64 + tx * 4;
                float4 o;
                o.x = acc[gi * 4 + ii][gj * 4 + 0];
                o.y = acc[gi * 4 + ii][gj * 4 + 1];
                o.z = acc[gi * 4 + ii][gj * 4 + 2];
                o.w = acc[gi * 4 + ii][gj * 4 + 3];
                *(float4*)(C + (size_t)r * N + cb) = o;
            }
        }
}

// ---------------------------------------------------------------------------
// Fused prep launch A: LN1 | prep_text | convert W1 | convert W2 | wb2/nb2
// blocks: [0,4096) ln | [4096,4224) text | [4224,4480) W1 | [4480,4736) W2
//         | [4736,4801) wb2/nb2
// ---------------------------------------------------------------------------
__global__ __launch_bounds__(256) void fused_prepA_kernel(
    const float* __restrict__ vis, const float* __restrict__ g1,
    const float* __restrict__ be1,
    const float* __restrict__ text, const float* __restrict__ Wv,
    const float* __restrict__ bv,
    const float* __restrict__ W1, const float* __restrict__ W2,
    const float* __restrict__ Wq, const float* __restrict__ bq)
{
    __shared__ __align__(16) char sbuf[24576];
    int j = blockIdx.x;
    if (j < 4096) {
        ln_body(vis, g1, be1, g_vh, g_vl, j);
    } else if (j < 4224) {
        prep_text_body(text, Wv, bv, (float(*)[TDIM])sbuf, j - 4096);
    } else if (j < 4480) {
        int jj = j - 4224;   // W1 grid (32, 8)
        convert_body(W1, g_W1h, g_W1l, CDIM, HID, jj & 31, jj >> 5, 0, 0, 0,
                     (float(*)[65])sbuf);
    } else if (j < 4736) {
        int jj = j - 4480;   // W2 grid (8, 32)
        convert_body(W2, g_W2h, g_W2l, HID, CDIM, jj & 7, jj >> 3, 0, 0, 0,
                     (float(*)[65])sbuf);
    } else {
        int gw2 = (j - 4736) * 8 + (threadIdx.x >> 5);
        wb2_body(Wq, bq, gw2);
    }
}

// ---------------------------------------------------------------------------
// Fused prep launch B: G gemm | P gemms | pb
// blocks: [0,16) G | [16,48) P | [48,176) pb
// ---------------------------------------------------------------------------
__global__ __launch_bounds__(256) void fused_prepB_kernel(
    const float* __restrict__ Wq, const float* __restrict__ bq)
{
    __shared__ __align__(16) float As[8][128];
    __shared__ float Bs[8][128];
    int j = blockIdx.x;
    if (j < 16) {
        sgemm_body(Wq, Wq, g_G, TDIM, CDIM, j & 3, j >> 2, As, Bs);
    } else if (j < 48) {
        int jj = j - 16;
        int bz = jj >> 2, bm = jj & 3;
        sgemm_body(Wq, g_keyt + (size_t)bz * KTXT * TDIM,
                   g_P + (size_t)bz * CDIM * KTXT,
                   TDIM, KTXT, 0, bm, As, Bs);
    } else {
        int gw = (j - 48) * 8 + (threadIdx.x >> 5);
        pb_body(bq, gw);
    }
}

// ---------------------------------------------------------------------------
// Fused prep launch C: convert G | convert P
// blocks: [0,64) G (grid 8x8) | [64,192) P (grid 2x8x8)
// ---------------------------------------------------------------------------
__global__ __launch_bounds__(256) void fused_prepC_kernel()
{
    __shared__ __align__(16) float t[64][65];
    int j = blockIdx.x;
    if (j < 64) {
        convert_body(g_G, g_Gh, g_Gl, CDIM, CDIM, j & 7, j >> 3, 0, 0, 0, t);
    } else {
        int jj = j - 64;
        convert_body(g_P, g_Ph, g_Pl, CDIM, KTXT, jj & 1, (jj >> 1) & 7, jj >> 4,
                     (size_t)CDIM * KTXT, (size_t)KTXT * CDIM / 2, t);
    }
}

// ---------------------------------------------------------------------------
// fp16 tensor-core GEMM (unchanged from R13)
// ---------------------------------------------------------------------------
#define A_PLANE 5120
#define B_PLANE 2560

template <int MODE, int AP, int BP>
__global__ __launch_bounds__(512) void tgemm4_kernel(
    const uint32_t* __restrict__ Ah, const uint32_t* __restrict__ Al,
    const uint32_t* __restrict__ Bh, const uint32_t* __restrict__ Bl,
    const float* __restrict__ bias, const float* __restrict__ Res,
    float* __restrict__ Out, uint32_t* __restrict__ Oh,
    int M, int N, int Kd)
{
    const int STG = AP * A_PLANE + BP * B_PLANE;
    extern __shared__ uint32_t sm[];
    uint32_t sbase = smem_u32(sm);
    int K2 = Kd >> 1;
    int tid = threadIdx.x, lane = tid & 31, warp = tid >> 5;
    int g  = lane >> 2, tg = lane & 3;
    int wm = warp >> 2, wn = warp & 3;
    int m0 = wm * 64,  n0 = wn * 32;
    int bn = blockIdx.x, bm = blockIdx.y;

    const uint32_t* AhB = Ah + (size_t)bm * 256 * K2;
    const uint32_t* AlB = (AP == 2) ? Al + (size_t)bm * 256 * K2 : nullptr;
    size_t bofs = (size_t)bn * 128 * K2;
    if (MODE == 0) bofs += (size_t)(bm >> 4) * KTXT * K2;
    const uint32_t* BhB = Bh + bofs;
    const uint32_t* BlB = (BP == 2) ? Bl + bofs : nullptr;

    uint32_t a_ld = (uint32_t)((m0 + (lane & 7) + ((lane >> 3) & 1) * 8) * 20
                               + ((lane >> 4) & 1) * 4) * 4;
    uint32_t b_ld = (uint32_t)((n0 + (lane & 7) + ((lane >> 4) & 1) * 8) * 20
                               + ((lane >> 3) & 1) * 4) * 4;

    float acc[4][4][4];
    #pragma unroll
    for (int mi = 0; mi < 4; mi++)
        #pragma unroll
        for (int ni = 0; ni < 4; ni++)
            #pragma unroll
            for (int r = 0; r < 4; r++) acc[mi][ni][r] = 0.f;

    int nT = K2 / 16;
    const int AOFF = AP * A_PLANE;

    #pragma unroll
    for (int pf = 0; pf < 2; pf++) {
        uint32_t* st = sm + pf * STG;
        int kp0 = pf * 16;
        #pragma unroll
        for (int c = 0; c < 2; c++) {
            int idx = tid + 512 * c;
            int row = idx >> 2, kb = (idx & 3) * 4;
            size_t go = (size_t)row * K2 + kp0 + kb;
            cp16(st + row * 20 + kb, AhB + go);
            if (AP == 2) cp16(st + A_PLANE + row * 20 + kb, AlB + go);
        }
        {
            int row = tid >> 2, kb = (tid & 3) * 4;
            size_t go = (size_t)row * K2 + kp0 + kb;
            int so = row * 20 + kb;
            cp16(st + AOFF + so, BhB + go);
            if (BP == 2) cp16(st + AOFF + B_PLANE + so, BlB + go);
        }
        cp_commit();
    }

    for (int t = 0; t < nT; t++) {
        cp_wait1();
        __syncthreads();
        uint32_t stb = sbase + (uint32_t)((t & 1) * STG * 4);

        #pragma unroll
        for (int ks = 0; ks < 2; ks++) {
            uint32_t ksoff = (uint32_t)(ks * 32);
            uint32_t a[4][4], al[4][4], bh[4][2], bl[4][2];
            #pragma unroll
            for (int mi = 0; mi < 4; mi++) {
                uint32_t ao = stb + a_ld + ksoff + (uint32_t)(mi * 16 * 80);
                ldsm_x4(a[mi][0], a[mi][1], a[mi][2], a[mi][3], ao);
                if (AP == 2)
                    ldsm_x4(al[mi][0], al[mi][1], al[mi][2], al[mi][3],
                            ao + A_PLANE * 4);
            }
            #pragma unroll
            for (int p = 0; p < 2; p++) {
                uint32_t bo = stb + AOFF * 4 + b_ld + ksoff + (uint32_t)(p * 16 * 80);
                ldsm_x4(bh[2 * p][0], bh[2 * p][1], bh[2 * p + 1][0], bh[2 * p + 1][1], bo);
                if (BP == 2)
                    ldsm_x4(bl[2 * p][0], bl[2 * p][1], bl[2 * p + 1][0], bl[2 * p + 1][1],
                            bo + B_PLANE * 4);
            }
            #pragma unroll
            for (int mi = 0; mi < 4; mi++)
                #pragma unroll
                for (int ni = 0; ni < 4; ni++) {
                    mma_f16(acc[mi][ni], a[mi], bh[ni]);
                    if (BP == 2) mma_f16(acc[mi][ni], a[mi], bl[ni]);
                    if (AP == 2) mma_f16(acc[mi][ni], al[mi], bh[ni]);
                }
        }
        __syncthreads();
        if (t + 2 < nT) {
            uint32_t* dst = sm + (t & 1) * STG;
            int kp0 = (t + 2) * 16;
            #pragma unroll
            for (int c = 0; c < 2; c++) {
                int idx = tid + 512 * c;
                int row = idx >> 2, kb = (idx & 3) * 4;
                size_t go = (size_t)row * K2 + kp0 + kb;
                cp16(dst + row * 20 + kb, AhB + go);
                if (AP == 2) cp16(dst + A_PLANE + row * 20 + kb, AlB + go);
            }
            {
                int row = tid >> 2, kb = (tid & 3) * 4;
                size_t go = (size_t)row * K2 + kp0 + kb;
                int so = row * 20 + kb;
                cp16(dst + AOFF + so, BhB + go);
                if (BP == 2) cp16(dst + AOFF + B_PLANE + so, BlB + go);
            }
        }
        cp_commit();
    }

    if (MODE == 3) {
        #pragma unroll
        for (int mi = 0; mi < 4; mi++)
            #pragma unroll
            for (int half = 0; half < 2; half++) {
                int r = bm * 256 + m0 + mi * 16 + g + half * 8;
                float part = 0.f;
                #pragma unroll
                for (int ni = 0; ni < 4; ni++) {
                    int c = bn * 128 + n0 + ni * 8 + 2 * tg;
                    uint32_t hu = Ah[(size_t)r * (N >> 1) + (c >> 1)];
                    uint32_t lu = Al[(size_t)r * (N >> 1) + (c >> 1)];
                    __half2 h2 = *reinterpret_cast<__half2*>(&hu);
                    __half2 l2 = *reinterpret_cast<__half2*>(&lu);
                    float h0 = __half2float(__low2half(h2));
                    float h1 = __half2float(__high2half(h2));
                    float l0 = __half2float(__low2half(l2));
                    float l1 = __half2float(__high2half(l2));
                    float z0 = acc[mi][ni][half * 2 + 0] * WINV;
                    float z1 = acc[mi][ni][half * 2 + 1] * WINV;
                    part += z0 * (h0 + 2.0f * l0) + bias[c]     * (h0 + l0);
                    part += z1 * (h1 + 2.0f * l1) + bias[c + 1] * (h1 + l1);
                }
                part += __shfl_xor_sync(0xffffffffu, part, 1);
                part += __shfl_xor_sync(0xffffffffu, part, 2);
                if (tg == 0) atomicAdd(&g_qn2[r], part);
            }
        return;
    }

    #pragma unroll
    for (int mi = 0; mi < 4; mi++)
        #pragma unroll
        for (int half = 0; half < 2; half++) {
            int r = bm * 256 + m0 + mi * 16 + g + half * 8;
            #pragma unroll
            for (int ni = 0; ni < 4; ni++) {
                int c = bn * 128 + n0 + ni * 8 + 2 * tg;
                float v0 = acc[mi][ni][half * 2 + 0] * WINV;
                float v1 = acc[mi][ni][half * 2 + 1] * WINV;
                if (MODE == 0) {
                    float2 ov = { v0, v1 };
                    *(float2*)(Out + (size_t)r * KTXT + c) = ov;
                } else if (MODE == 1) {
                    v0 += bias[c];  v1 += bias[c + 1];
                    v0 = v0 * normcdff(v0);
                    v1 = v1 * normcdff(v1);
                    Oh[(size_t)r * (N >> 1) + (c >> 1)] = packh2(v0, v1);
                } else {
                    v0 += bias[c]     + Res[(size_t)r * N + c];
                    v1 += bias[c + 1] + Res[(size_t)r * N + c + 1];
                    float2 ov = { v0, v1 };
                    *(float2*)(Out + (size_t)r * N + c) = ov;
                }
            }
        }
}

// ---------------------------------------------------------------------------
// Attention epilogue (unchanged from R13)
// ---------------------------------------------------------------------------
__global__ __launch_bounds__(256) void attn_kernel(
    const float* __restrict__ resid, const float* __restrict__ g2,
    const float* __restrict__ be2)
{
    __shared__ float invn[32];
    __shared__ float pb_s[KTXT];
    int tid = threadIdx.x, lane = tid & 31, warp = tid >> 5;
    int t0 = blockIdx.x * 32;
    int b  = t0 >> 12;

    if (tid < 32) {
        float qn2 = g_qn2[t0 + tid] + g_nb2[0];
        float n = sqrtf(fmaxf(qn2, 0.f));
        invn[tid] = 1.0f / fmaxf(n, 1e-12f);
    }
    if (tid < KTXT) pb_s[tid] = g_pb[b * KTXT + tid];
    __syncthreads();

    for (int rr = 0; rr < 4; rr++) {
        int row = warp * 4 + rr;
        float sc = invn[row];
        const float* sp = g_sim + (size_t)(t0 + row) * KTXT;
        float tv[4];
        #pragma unroll
        for (int j = 0; j < 4; j++) {
            int col = lane + 32 * j;
            tv[j] = (sp[col] + pb_s[col]) * sc;
        }

        float mval[TOPM]; int midx[TOPM];
        #pragma unroll
        for (int it = 0; it < TOPM; it++) {
            float lm = tv[0]; int lj = 0;
            #pragma unroll
            for (int j = 1; j < 4; j++) if (tv[j] > lm) { lm = tv[j]; lj = j; }
            int li = lane + 32 * lj;
            #pragma unroll
            for (int o = 16; o; o >>= 1) {
                float ov = __shfl_xor_sync(0xffffffffu, lm, o);
                int   oi = __shfl_xor_sync(0xffffffffu, li, o);
                if (ov > lm || (ov == lm && oi < li)) { lm = ov; li = oi; }
            }
            mval[it] = lm; midx[it] = li;
            if ((li & 31) == lane) tv[li >> 5] = -INFINITY;
        }

        float p[TOPM], psum = 0.f;
        #pragma unroll
        for (int it = 0; it < TOPM; it++) {
            p[it] = expf((mval[it] - mval[0]) * TEMP_INV);
            psum += p[it];
        }
        float rnorm = 1.0f / psum;

        float f[16];
        #pragma unroll
        for (int i = 0; i < 16; i++) f[i] = 0.f;
        const float* Vb = g_value + (size_t)b * KTXT * CDIM;
        #pragma unroll
        for (int it = 0; it < TOPM; it++) {
            const float4* vr = (const float4*)(Vb + (size_t)midx[it] * CDIM + lane * 16);
            float a_ = p[it] * rnorm;
            #pragma unroll
            for (int j = 0; j < 4; j++) {
                float4 v = vr[j];
                f[4 * j + 0] += a_ * v.x;
                f[4 * j + 1] += a_ * v.y;
                f[4 * j + 2] += a_ * v.z;
                f[4 * j + 3] += a_ * v.w;
            }
        }

        const float4* rp = (const float4*)(resid + (size_t)(t0 + row) * CDIM + lane * 16);
        float s = 0.f, s2 = 0.f;
        #pragma unroll
        for (int j = 0; j < 4; j++) {
            float4 v = rp[j];
            f[4 * j + 0] += v.x;  f[4 * j + 1] += v.y;
            f[4 * j + 2] += v.z;  f[4 * j + 3] += v.w;
        }
        #pragma unroll
        for (int i = 0; i < 16; i++) { s += f[i]; s2 += f[i] * f[i]; }
        #pragma unroll
        for (int o = 16; o; o >>= 1) {
            s  += __shfl_xor_sync(0xffffffffu, s, o);
            s2 += __shfl_xor_sync(0xffffffffu, s2, o);
        }
        float mu  = s * (1.0f / CDIM);
        float var = s2 * (1.0f / CDIM) - mu * mu;
        float rstd = rsqrtf(var + LN_EPS);

        size_t rbase = (size_t)(t0 + row);
        float*    xp = g_X  + rbase * CDIM + lane * 16;
        uint32_t* xh = g_Xh + rbase * (CDIM / 2) + lane * 8;
        #pragma unroll
        for (int j = 0; j < 4; j++) {
            int c = lane * 16 + 4 * j;
            float4 o;
            o.x = (f[4 * j + 0] - mu) * rstd * g2[c + 0] + be2[c + 0];
            o.y = (f[4 * j + 1] - mu) * rstd * g2[c + 1] + be2[c + 1];
            o.z = (f[4 * j + 2] - mu) * rstd * g2[c + 2] + be2[c + 2];
            o.w = (f[4 * j + 3] - mu) * rstd * g2[c + 3] + be2[c + 3];
            *(float4*)(xp + 4 * j) = o;
            uint2 h;
            h.x = packh2(o.x, o.y);
            h.y = packh2(o.z, o.w);
            *(uint2*)(xh + 2 * j) = h;
        }
    }
}

// ---------------------------------------------------------------------------
// Launch
// ---------------------------------------------------------------------------
extern "C" void kernel_launch(void* const* d_in, const int* in_sizes, int n_in,
                              void* d_out, int out_size)
{
    const float* vis  = (const float*)d_in[0];
    const float* text = (const float*)d_in[1];
    const float* Wq   = (const float*)d_in[2];
    const float* bq   = (const float*)d_in[3];
    const float* Wv   = (const float*)d_in[4];
    const float* bv   = (const float*)d_in[5];
    const float* W1   = (const float*)d_in[6];
    const float* b1   = (const float*)d_in[7];
    const float* W2   = (const float*)d_in[8];
    const float* b2   = (const float*)d_in[9];
    const float* g1   = (const float*)d_in[10];
    const float* be1  = (const float*)d_in[11];
    const float* g2   = (const float*)d_in[12];
    const float* be2  = (const float*)d_in[13];
    float* out = (float*)d_out;

    float *p_X, *p_wb2, *p_qn2, *p_sim;
    uint32_t *p_vh, *p_vl, *p_Xh, *p_Hh;
    uint32_t *p_Gh, *p_Ph, *p_Pl, *p_W1h, *p_W1l, *p_W2h, *p_W2l;
    cudaGetSymbolAddress((void**)&p_X,     g_X);
    cudaGetSymbolAddress((void**)&p_wb2,   g_wb2);
    cudaGetSymbolAddress((void**)&p_qn2,   g_qn2);
    cudaGetSymbolAddress((void**)&p_sim,   g_sim);
    cudaGetSymbolAddress((void**)&p_vh,    g_vh);
    cudaGetSymbolAddress((void**)&p_vl,    g_vl);
    cudaGetSymbolAddress((void**)&p_Xh,    g_Xh);
    cudaGetSymbolAddress((void**)&p_Hh,    g_Hh);
    cudaGetSymbolAddress((void**)&p_Gh,    g_Gh);
    cudaGetSymbolAddress((void**)&p_Ph,    g_Ph);
    cudaGetSymbolAddress((void**)&p_Pl,    g_Pl);
    cudaGetSymbolAddress((void**)&p_W1h,   g_W1h);
    cudaGetSymbolAddress((void**)&p_W1l,   g_W1l);
    cudaGetSymbolAddress((void**)&p_W2h,   g_W2h);
    cudaGetSymbolAddress((void**)&p_W2l,   g_W2l);

    const int SMEM_1P  = 2 * (1 * A_PLANE + 1 * B_PLANE) * 4;   // 61440
    const int SMEM_SIM = 2 * (2 * A_PLANE + 2 * B_PLANE) * 4;   // 122880
    cudaFuncSetAttribute((const void*)tgemm4_kernel<0, 2, 2>,
                         cudaFuncAttributeMaxDynamicSharedMemorySize, SMEM_SIM);
    cudaFuncSetAttribute((const void*)tgemm4_kernel<1, 1, 1>,
                         cudaFuncAttributeMaxDynamicSharedMemorySize, SMEM_1P);
    cudaFuncSetAttribute((const void*)tgemm4_kernel<2, 1, 1>,
                         cudaFuncAttributeMaxDynamicSharedMemorySize, SMEM_1P);
    cudaFuncSetAttribute((const void*)tgemm4_kernel<3, 1, 1>,
                         cudaFuncAttributeMaxDynamicSharedMemorySize, SMEM_1P);

    // A) LN1 + text prep + W1/W2 converts + wb2/nb2  (independent work, 1 launch)
    fused_prepA_kernel<<<4801, 256>>>(vis, g1, be1, text, Wv, bv, W1, W2, Wq, bq);
    // B) G gemm + P gemms + pb  (depend on keyt from A)
    fused_prepB_kernel<<<176, 256>>>(Wq, bq);
    // C) convert G + convert P  (depend on B)
    fused_prepC_kernel<<<192, 256>>>();
    // D) qn2
    cudaMemsetAsync(p_qn2, 0, MTOT * sizeof(float));
    tgemm4_kernel<3, 1, 1><<<dim3(CDIM / 128, MTOT / 256), 512, SMEM_1P>>>(
        p_vh, p_vl, p_Gh, nullptr, p_wb2, nullptr, nullptr, nullptr,
        MTOT, CDIM, CDIM);
    // E) sim (3 products) -> g_sim fp32
    tgemm4_kernel<0, 2, 2><<<dim3(1, MTOT / 256), 512, SMEM_SIM>>>(
        p_vh, p_vl, p_Ph, p_Pl, nullptr, nullptr, p_sim, nullptr,
        MTOT, KTXT, CDIM);
    // F) attention epilogue + residual + LN2 -> X fp32 + Xh fp16
    attn_kernel<<<MTOT / 32, 256>>>(vis, g2, be2);
    // G) H = gelu(X @ W1 + b1) -> fp16 plane Hh
    tgemm4_kernel<1, 1, 1><<<dim3(HID / 128, MTOT / 256), 512, SMEM_1P>>>(
        p_Xh, nullptr, p_W1h, p_W1l, b1, nullptr, nullptr, p_Hh,
        MTOT, HID, CDIM);
    // H) out = X + H @ W2 + b2
    tgemm4_kernel<2, 1, 1><<<dim3(CDIM / 128, MTOT / 256), 512, SMEM_1P>>>(
        p_Hh, nullptr, p_W2h, p_W2l, b2, p_X, out, nullptr,
        MTOT, CDIM, HID);
}